// round 1
// baseline (speedup 1.0000x reference)
#include <cuda_runtime.h>
#include <math.h>

#define N_NODES 100000
#define MEM_DIM 128
#define MSG_DIM 128
#define TIME_DIM 32
#define EDGE_DIM 32
#define NODE_DIM 64
#define EMB_DIM 64
#define XDIM 320   // 2*MEM + EDGE + TIME
#define TE 64
#define TN 64

// ---------------- scratch (static device globals; no allocation) ----------------
__device__ float g_aggr[(size_t)N_NODES * MSG_DIM];   // 51.2 MB
__device__ float g_cnt[N_NODES];
__device__ float g_newmem[(size_t)N_NODES * MEM_DIM]; // 51.2 MB

// ---------------- K0: zero aggregation buffers ----------------
__global__ void k_zero() {
    size_t stride = (size_t)gridDim.x * blockDim.x;
    size_t tid0 = (size_t)blockIdx.x * blockDim.x + threadIdx.x;
    size_t tot = (size_t)N_NODES * MSG_DIM;
    for (size_t i = tid0; i < tot; i += stride) g_aggr[i] = 0.f;
    for (size_t i = tid0; i < N_NODES; i += stride) g_cnt[i] = 0.f;
}

// ---------------- K1: per-edge message MLP + scatter-add ----------------
// x = [mem[src](128) | mem[dst](128) | edge_feat(32) | cos(ts*tw+tb)(32)]  (320)
// h = relu(x @ W1 + b1)  (128);  msg = h @ W2 + b2  (128)
// atomicAdd into g_aggr[src], g_aggr[dst]; g_cnt[src]++, g_cnt[dst]++
extern __shared__ float smem[];

__global__ __launch_bounds__(256, 1) void k_msg(
    const int* __restrict__ src, const int* __restrict__ dst,
    const float* __restrict__ ef, const float* __restrict__ ts,
    const float* __restrict__ memory,
    const float* __restrict__ tw, const float* __restrict__ tb,
    const float* __restrict__ W1, const float* __restrict__ b1,
    const float* __restrict__ W2, const float* __restrict__ b2,
    int E)
{
    float* sX = smem;                 // TE*XDIM
    float* sW = sX + TE * XDIM;       // 32*128
    float* sH = sW + 32 * 128;        // TE*128
    int*   sN = (int*)(sH + TE * 128);// 2*TE

    const int tid = threadIdx.x;
    const int e0 = blockIdx.x * TE;
    const int nE = min(TE, E - e0);

    if (tid < TE) {
        int e = e0 + tid;
        sN[tid]      = (tid < nE) ? src[e] : 0;
        sN[TE + tid] = (tid < nE) ? dst[e] : 0;
    }
    __syncthreads();

    // build X tile
    for (int idx = tid; idx < TE * MEM_DIM; idx += 256) {
        int e = idx >> 7, c = idx & 127;
        float vs = 0.f, vd = 0.f;
        if (e < nE) {
            vs = memory[(size_t)sN[e] * MEM_DIM + c];
            vd = memory[(size_t)sN[TE + e] * MEM_DIM + c];
        }
        sX[e * XDIM + c]       = vs;
        sX[e * XDIM + 128 + c] = vd;
    }
    for (int idx = tid; idx < TE * EDGE_DIM; idx += 256) {
        int e = idx >> 5, c = idx & 31;
        float v = 0.f, t = 0.f;
        if (e < nE) {
            v = ef[(size_t)(e0 + e) * EDGE_DIM + c];
            t = cosf(ts[e0 + e] * tw[c] + tb[c]);
        }
        sX[e * XDIM + 256 + c] = v;
        sX[e * XDIM + 288 + c] = t;
    }
    __syncthreads();

    const int tx = tid & 31, ty = tid >> 5;

    // GEMM1: 64x128, K=320
    float acc[8][4];
    #pragma unroll
    for (int i = 0; i < 8; i++)
        #pragma unroll
        for (int j = 0; j < 4; j++) acc[i][j] = 0.f;

    for (int k0 = 0; k0 < XDIM; k0 += 32) {
        for (int idx = tid; idx < 32 * 128; idx += 256)
            sW[idx] = W1[(size_t)k0 * 128 + idx];
        __syncthreads();
        #pragma unroll
        for (int kk = 0; kk < 32; kk++) {
            float wv[4];
            #pragma unroll
            for (int j = 0; j < 4; j++) wv[j] = sW[kk * 128 + tx + 32 * j];
            #pragma unroll
            for (int i = 0; i < 8; i++) {
                float xv = sX[(i * 8 + ty) * XDIM + k0 + kk];
                #pragma unroll
                for (int j = 0; j < 4; j++) acc[i][j] = fmaf(xv, wv[j], acc[i][j]);
            }
        }
        __syncthreads();
    }
    #pragma unroll
    for (int i = 0; i < 8; i++) {
        int e = i * 8 + ty;
        #pragma unroll
        for (int j = 0; j < 4; j++) {
            int c = tx + 32 * j;
            sH[e * 128 + c] = fmaxf(acc[i][j] + b1[c], 0.f);
        }
    }
    __syncthreads();

    // GEMM2: 64x128, K=128
    #pragma unroll
    for (int i = 0; i < 8; i++)
        #pragma unroll
        for (int j = 0; j < 4; j++) acc[i][j] = 0.f;

    for (int k0 = 0; k0 < 128; k0 += 32) {
        for (int idx = tid; idx < 32 * 128; idx += 256)
            sW[idx] = W2[(size_t)k0 * 128 + idx];
        __syncthreads();
        #pragma unroll
        for (int kk = 0; kk < 32; kk++) {
            float wv[4];
            #pragma unroll
            for (int j = 0; j < 4; j++) wv[j] = sW[kk * 128 + tx + 32 * j];
            #pragma unroll
            for (int i = 0; i < 8; i++) {
                float xv = sH[(i * 8 + ty) * 128 + k0 + kk];
                #pragma unroll
                for (int j = 0; j < 4; j++) acc[i][j] = fmaf(xv, wv[j], acc[i][j]);
            }
        }
        __syncthreads();
    }

    // scatter msg
    #pragma unroll
    for (int i = 0; i < 8; i++) {
        int e = i * 8 + ty;
        if (e < nE) {
            int ns = sN[e], nd = sN[TE + e];
            #pragma unroll
            for (int j = 0; j < 4; j++) {
                int c = tx + 32 * j;
                float v = acc[i][j] + b2[c];
                atomicAdd(&g_aggr[(size_t)ns * MSG_DIM + c], v);
                atomicAdd(&g_aggr[(size_t)nd * MSG_DIM + c], v);
            }
        }
    }
    if (tid < nE) {
        atomicAdd(&g_cnt[sN[tid]], 1.f);
        atomicAdd(&g_cnt[sN[TE + tid]], 1.f);
    }
}

// ---------------- K2: GRU memory update ----------------
__device__ __forceinline__ void gru_gate_fused(
    const float* __restrict__ Wih, const float* __restrict__ Whh,
    const float* sIn, float* sWa,
    int tid, int tx, int ty, int jr, float acc[8][4])
{
    for (int k0 = 0; k0 < 256; k0 += 32) {
        for (int idx = tid; idx < 32 * 128; idx += 256) {
            int kk = idx & 31, j = idx >> 5;
            int kg = k0 + kk;
            float w = (kg < 128) ? Wih[(size_t)(jr + j) * 128 + kg]
                                 : Whh[(size_t)(jr + j) * 128 + (kg - 128)];
            sWa[kk * 129 + j] = w;
        }
        __syncthreads();
        #pragma unroll
        for (int kk = 0; kk < 32; kk++) {
            float wv[4];
            #pragma unroll
            for (int j = 0; j < 4; j++) wv[j] = sWa[kk * 129 + tx + 32 * j];
            #pragma unroll
            for (int i = 0; i < 8; i++) {
                float xv = sIn[(i * 8 + ty) * 256 + k0 + kk];
                #pragma unroll
                for (int j = 0; j < 4; j++) acc[i][j] = fmaf(xv, wv[j], acc[i][j]);
            }
        }
        __syncthreads();
    }
}

__global__ __launch_bounds__(256, 1) void k_gru(
    const float* __restrict__ memory,
    const float* __restrict__ Wih, const float* __restrict__ Whh,
    const float* __restrict__ bih, const float* __restrict__ bhh)
{
    float* sIn  = smem;                 // TN*256
    float* sWa  = sIn + TN * 256;       // 32*129
    float* sWb  = sWa + 32 * 129;       // 32*129
    float* sCnt = sWb + 32 * 129;       // TN

    const int tid = threadIdx.x;
    const int n0 = blockIdx.x * TN;
    const int nN = min(TN, N_NODES - n0);

    if (tid < TN) sCnt[tid] = (tid < nN) ? g_cnt[n0 + tid] : 0.f;
    __syncthreads();

    for (int idx = tid; idx < TN * 128; idx += 256) {
        int n = idx >> 7, c = idx & 127;
        float mm = 0.f, mv = 0.f;
        if (n < nN) {
            float cnt = sCnt[n];
            mm = (cnt > 0.f) ? g_aggr[(size_t)(n0 + n) * 128 + c] / cnt : 0.f;
            mv = memory[(size_t)(n0 + n) * 128 + c];
        }
        sIn[n * 256 + c]       = mm;
        sIn[n * 256 + 128 + c] = mv;
    }
    __syncthreads();

    const int tx = tid & 31, ty = tid >> 5;

    float rg[8][4], zg[8][4];
    #pragma unroll
    for (int i = 0; i < 8; i++)
        #pragma unroll
        for (int j = 0; j < 4; j++) { rg[i][j] = 0.f; zg[i][j] = 0.f; }

    gru_gate_fused(Wih, Whh, sIn, sWa, tid, tx, ty, 0, rg);
    gru_gate_fused(Wih, Whh, sIn, sWa, tid, tx, ty, 128, zg);

    #pragma unroll
    for (int i = 0; i < 8; i++)
        #pragma unroll
        for (int j = 0; j < 4; j++) {
            int jc = tx + 32 * j;
            rg[i][j] = 1.f / (1.f + expf(-(rg[i][j] + bih[jc] + bhh[jc])));
            zg[i][j] = 1.f / (1.f + expf(-(zg[i][j] + bih[128 + jc] + bhh[128 + jc])));
        }

    // n gate: i_n and h_n separately
    float acci[8][4], acch[8][4];
    #pragma unroll
    for (int i = 0; i < 8; i++)
        #pragma unroll
        for (int j = 0; j < 4; j++) { acci[i][j] = 0.f; acch[i][j] = 0.f; }

    for (int k0 = 0; k0 < 128; k0 += 32) {
        for (int idx = tid; idx < 32 * 128; idx += 256) {
            int kk = idx & 31, j = idx >> 5;
            sWa[kk * 129 + j] = Wih[(size_t)(256 + j) * 128 + k0 + kk];
            sWb[kk * 129 + j] = Whh[(size_t)(256 + j) * 128 + k0 + kk];
        }
        __syncthreads();
        #pragma unroll
        for (int kk = 0; kk < 32; kk++) {
            float wa[4], wb[4];
            #pragma unroll
            for (int j = 0; j < 4; j++) {
                wa[j] = sWa[kk * 129 + tx + 32 * j];
                wb[j] = sWb[kk * 129 + tx + 32 * j];
            }
            #pragma unroll
            for (int i = 0; i < 8; i++) {
                float xm = sIn[(i * 8 + ty) * 256 + k0 + kk];
                float xh = sIn[(i * 8 + ty) * 256 + 128 + k0 + kk];
                #pragma unroll
                for (int j = 0; j < 4; j++) {
                    acci[i][j] = fmaf(xm, wa[j], acci[i][j]);
                    acch[i][j] = fmaf(xh, wb[j], acch[i][j]);
                }
            }
        }
        __syncthreads();
    }

    #pragma unroll
    for (int i = 0; i < 8; i++) {
        int n = i * 8 + ty;
        if (n < nN) {
            float cnt = sCnt[n];
            #pragma unroll
            for (int j = 0; j < 4; j++) {
                int jc = tx + 32 * j;
                float i_n = acci[i][j] + bih[256 + jc];
                float h_n = acch[i][j] + bhh[256 + jc];
                float nn = tanhf(i_n + rg[i][j] * h_n);
                float mv = sIn[n * 256 + 128 + jc];
                float hnew = (1.f - zg[i][j]) * nn + zg[i][j] * mv;
                g_newmem[(size_t)(n0 + n) * 128 + jc] = (cnt > 0.f) ? hnew : mv;
            }
        }
    }
}

// ---------------- K3: embeddings + dot ----------------
__global__ __launch_bounds__(256, 1) void k_emb(
    const int* __restrict__ src, const int* __restrict__ dst,
    const float* __restrict__ sf, const float* __restrict__ df,
    const float* __restrict__ W1, const float* __restrict__ b1,
    const float* __restrict__ W2, const float* __restrict__ b2,
    float* __restrict__ out, int E)
{
    float* sW1 = smem;                  // 192*64
    float* sW2 = sW1 + 192 * 64;        // 64*64
    float* sC  = sW2 + 64 * 64;         // TE*192
    float* sH1 = sC + TE * 192;         // TE*65 (padded)
    float* sEs = sH1 + TE * 65;         // TE*65
    float* sEd = sEs + TE * 65;         // TE*65

    const int tid = threadIdx.x;
    const int e0 = blockIdx.x * TE;
    const int nE = min(TE, E - e0);

    for (int idx = tid; idx < 192 * 64; idx += 256) sW1[idx] = W1[idx];
    for (int idx = tid; idx < 64 * 64; idx += 256)  sW2[idx] = W2[idx];

    const int tx = tid & 15, ty = tid >> 4;  // 16x16 thread grid

    for (int ep = 0; ep < 2; ep++) {
        const int* nodes = ep ? dst : src;
        const float* feats = ep ? df : sf;
        __syncthreads();

        // build sC = [new_mem (128) | feats (64)]
        for (int idx = tid; idx < TE * MEM_DIM; idx += 256) {
            int e = idx >> 7, c = idx & 127;
            float v = 0.f;
            if (e < nE) v = g_newmem[(size_t)nodes[e0 + e] * 128 + c];
            sC[e * 192 + c] = v;
        }
        for (int idx = tid; idx < TE * NODE_DIM; idx += 256) {
            int e = idx >> 6, c = idx & 63;
            float v = 0.f;
            if (e < nE) v = feats[(size_t)(e0 + e) * 64 + c];
            sC[e * 192 + 128 + c] = v;
        }
        __syncthreads();

        // GEMM1: 64x64, K=192
        float acc[4][4];
        #pragma unroll
        for (int i = 0; i < 4; i++)
            #pragma unroll
            for (int j = 0; j < 4; j++) acc[i][j] = 0.f;

        for (int k = 0; k < 192; k++) {
            float wv[4];
            #pragma unroll
            for (int j = 0; j < 4; j++) wv[j] = sW1[k * 64 + tx + 16 * j];
            #pragma unroll
            for (int i = 0; i < 4; i++) {
                float xv = sC[(i * 16 + ty) * 192 + k];
                #pragma unroll
                for (int j = 0; j < 4; j++) acc[i][j] = fmaf(xv, wv[j], acc[i][j]);
            }
        }
        #pragma unroll
        for (int i = 0; i < 4; i++) {
            int e = i * 16 + ty;
            #pragma unroll
            for (int j = 0; j < 4; j++) {
                int c = tx + 16 * j;
                sH1[e * 65 + c] = fmaxf(acc[i][j] + b1[c], 0.f);
            }
        }
        __syncthreads();

        // GEMM2: 64x64, K=64
        float acc2[4][4];
        #pragma unroll
        for (int i = 0; i < 4; i++)
            #pragma unroll
            for (int j = 0; j < 4; j++) acc2[i][j] = 0.f;

        for (int k = 0; k < 64; k++) {
            float wv[4];
            #pragma unroll
            for (int j = 0; j < 4; j++) wv[j] = sW2[k * 64 + tx + 16 * j];
            #pragma unroll
            for (int i = 0; i < 4; i++) {
                float xv = sH1[(i * 16 + ty) * 65 + k];
                #pragma unroll
                for (int j = 0; j < 4; j++) acc2[i][j] = fmaf(xv, wv[j], acc2[i][j]);
            }
        }
        __syncthreads();  // everyone done reading sH1 before next pass rewrites it

        float* sE = ep ? sEd : sEs;
        #pragma unroll
        for (int i = 0; i < 4; i++) {
            int e = i * 16 + ty;
            #pragma unroll
            for (int j = 0; j < 4; j++) {
                int c = tx + 16 * j;
                sE[e * 65 + c] = acc2[i][j] + b2[c];
            }
        }
    }
    __syncthreads();

    if (tid < TE && tid < nE) {
        float s = 0.f;
        #pragma unroll
        for (int c = 0; c < 64; c++)
            s = fmaf(sEs[tid * 65 + c], sEd[tid * 65 + c], s);
        out[e0 + tid] = s;
    }
}

// ---------------- host launch ----------------
extern "C" void kernel_launch(void* const* d_in, const int* in_sizes, int n_in,
                              void* d_out, int out_size)
{
    const int*   src   = (const int*)d_in[0];
    const int*   dst   = (const int*)d_in[1];
    const float* ef    = (const float*)d_in[2];
    const float* ts    = (const float*)d_in[3];
    const float* sf    = (const float*)d_in[4];
    const float* df    = (const float*)d_in[5];
    const float* mem   = (const float*)d_in[6];
    const float* tw    = (const float*)d_in[7];
    const float* tb    = (const float*)d_in[8];
    const float* mw1   = (const float*)d_in[9];
    const float* mb1   = (const float*)d_in[10];
    const float* mw2   = (const float*)d_in[11];
    const float* mb2   = (const float*)d_in[12];
    const float* gwih  = (const float*)d_in[13];
    const float* gwhh  = (const float*)d_in[14];
    const float* gbih  = (const float*)d_in[15];
    const float* gbhh  = (const float*)d_in[16];
    const float* ew1   = (const float*)d_in[17];
    const float* eb1   = (const float*)d_in[18];
    const float* ew2   = (const float*)d_in[19];
    const float* eb2   = (const float*)d_in[20];
    float* out = (float*)d_out;

    const int E = in_sizes[0];

    const int SMEM1 = (TE * XDIM + 32 * 128 + TE * 128) * 4 + 2 * TE * 4;
    const int SMEM2 = (TN * 256 + 2 * 32 * 129 + TN) * 4;
    const int SMEM3 = (192 * 64 + 64 * 64 + TE * 192 + 3 * TE * 65) * 4;

    cudaFuncSetAttribute(k_msg, cudaFuncAttributeMaxDynamicSharedMemorySize, SMEM1);
    cudaFuncSetAttribute(k_gru, cudaFuncAttributeMaxDynamicSharedMemorySize, SMEM2);
    cudaFuncSetAttribute(k_emb, cudaFuncAttributeMaxDynamicSharedMemorySize, SMEM3);

    k_zero<<<2048, 256>>>();
    k_msg<<<(E + TE - 1) / TE, 256, SMEM1>>>(src, dst, ef, ts, mem, tw, tb,
                                             mw1, mb1, mw2, mb2, E);
    k_gru<<<(N_NODES + TN - 1) / TN, 256, SMEM2>>>(mem, gwih, gwhh, gbih, gbhh);
    k_emb<<<(E + TE - 1) / TE, 256, SMEM3>>>(src, dst, sf, df,
                                             ew1, eb1, ew2, eb2, out, E);
}

// round 2
// speedup vs baseline: 1.7846x; 1.7846x over previous
#include <cuda_runtime.h>
#include <math.h>

#define N_NODES 100000
#define MEM_DIM 128
#define MSG_DIM 128
#define TIME_DIM 32
#define EDGE_DIM 32
#define NODE_DIM 64
#define EMB_DIM 64
#define TE 64
#define TN 32

// ---------------- scratch (static device globals; no allocation) ----------------
__device__ float g_aggr[(size_t)N_NODES * MSG_DIM];   // 51.2 MB
__device__ float g_cnt[N_NODES];
__device__ float g_newmem[(size_t)N_NODES * MEM_DIM]; // 51.2 MB

extern __shared__ float smem[];

// ---------------- K0: zero aggregation buffers ----------------
__global__ void k_zero() {
    size_t stride = (size_t)gridDim.x * blockDim.x;
    size_t tid0 = (size_t)blockIdx.x * blockDim.x + threadIdx.x;
    size_t tot = (size_t)N_NODES * MSG_DIM;
    for (size_t i = tid0; i < tot; i += stride) g_aggr[i] = 0.f;
    for (size_t i = tid0; i < N_NODES; i += stride) g_cnt[i] = 0.f;
}

// ======================= K1: message MLP + scatter =======================
// GEMM helper: C[64 x 128] += A[64 x KLEN] * W[KLEN x 128], W chunked through smem.
// Thread (tx,ty): rows i*8+ty (i<8), cols 4*tx..4*tx+3.
__device__ __forceinline__ void gemm64x128(
    const float* __restrict__ Wg, int wrow, int klen, int astride,
    const float* sA_, float* sW_, int tid, int tx, int ty, float acc[8][4])
{
    for (int k0 = 0; k0 < klen; k0 += 32) {
        const float4* wsrc = (const float4*)(Wg + (size_t)(wrow + k0) * 128);
        #pragma unroll
        for (int it = 0; it < 4; it++)
            ((float4*)sW_)[tid + 256 * it] = __ldg(wsrc + tid + 256 * it);
        __syncthreads();
        #pragma unroll
        for (int kk = 0; kk < 32; kk++) {
            float4 w = ((const float4*)sW_)[kk * 32 + tx];
            #pragma unroll
            for (int i = 0; i < 8; i++) {
                float xv = sA_[(i * 8 + ty) * astride + k0 + kk];
                acc[i][0] = fmaf(xv, w.x, acc[i][0]);
                acc[i][1] = fmaf(xv, w.y, acc[i][1]);
                acc[i][2] = fmaf(xv, w.z, acc[i][2]);
                acc[i][3] = fmaf(xv, w.w, acc[i][3]);
            }
        }
        __syncthreads();
    }
}

__global__ __launch_bounds__(256, 2) void k_msg(
    const int* __restrict__ src, const int* __restrict__ dst,
    const float* __restrict__ ef, const float* __restrict__ ts,
    const float* __restrict__ memory,
    const float* __restrict__ tw, const float* __restrict__ tb,
    const float* __restrict__ W1, const float* __restrict__ b1,
    const float* __restrict__ W2, const float* __restrict__ b2,
    int E)
{
    float* sA = smem;                 // 64*128
    float* sW = sA + 64 * 128;        // 32*128
    float* sH = sW + 32 * 128;        // 64*128
    int*   sN = (int*)(sH + 64 * 128);// 2*64

    const int tid = threadIdx.x;
    const int e0 = blockIdx.x * TE;
    const int nE = min(TE, E - e0);
    const int tx = tid & 31, ty = tid >> 5;

    if (tid < 2 * TE) {
        int e = tid & 63;
        const int* p = (tid < TE) ? src : dst;
        sN[tid] = (e < nE) ? p[e0 + e] : 0;
    }
    __syncthreads();

    float acc[8][4];
    #pragma unroll
    for (int i = 0; i < 8; i++)
        #pragma unroll
        for (int j = 0; j < 4; j++) acc[i][j] = 0.f;

    // Phase 0: A = memory[src]  (K rows 0..127 of W1)
    for (int idx = tid; idx < TE * 32; idx += 256) {
        int e = idx >> 5, c4 = idx & 31;
        float4 v = make_float4(0.f, 0.f, 0.f, 0.f);
        if (e < nE) v = __ldg((const float4*)(memory + (size_t)sN[e] * 128) + c4);
        ((float4*)(sA + e * 128))[c4] = v;
    }
    gemm64x128(W1, 0, 128, 128, sA, sW, tid, tx, ty, acc);

    // Phase 1: A = memory[dst]  (K rows 128..255)
    for (int idx = tid; idx < TE * 32; idx += 256) {
        int e = idx >> 5, c4 = idx & 31;
        float4 v = make_float4(0.f, 0.f, 0.f, 0.f);
        if (e < nE) v = __ldg((const float4*)(memory + (size_t)sN[TE + e] * 128) + c4);
        ((float4*)(sA + e * 128))[c4] = v;
    }
    gemm64x128(W1, 128, 128, 128, sA, sW, tid, tx, ty, acc);

    // Phase 2: A = [edge_feat | time_enc]  64x64  (K rows 256..319)
    for (int idx = tid; idx < TE * EDGE_DIM; idx += 256) {
        int e = idx >> 5, c = idx & 31;
        float v = 0.f, t = 0.f;
        if (e < nE) {
            v = __ldg(ef + (size_t)(e0 + e) * EDGE_DIM + c);
            t = cosf(ts[e0 + e] * __ldg(tw + c) + __ldg(tb + c));
        }
        sA[e * 64 + c]      = v;
        sA[e * 64 + 32 + c] = t;
    }
    gemm64x128(W1, 256, 64, 64, sA, sW, tid, tx, ty, acc);

    // bias + relu -> sH
    {
        float4 b1v = __ldg((const float4*)b1 + tx);
        #pragma unroll
        for (int i = 0; i < 8; i++) {
            float4 h;
            h.x = fmaxf(acc[i][0] + b1v.x, 0.f);
            h.y = fmaxf(acc[i][1] + b1v.y, 0.f);
            h.z = fmaxf(acc[i][2] + b1v.z, 0.f);
            h.w = fmaxf(acc[i][3] + b1v.w, 0.f);
            ((float4*)(sH + (i * 8 + ty) * 128))[tx] = h;
        }
    }
    #pragma unroll
    for (int i = 0; i < 8; i++)
        #pragma unroll
        for (int j = 0; j < 4; j++) acc[i][j] = 0.f;

    gemm64x128(W2, 0, 128, 128, sH, sW, tid, tx, ty, acc);

    // scatter (vector float4 atomics)
    {
        float4 b2v = __ldg((const float4*)b2 + tx);
        #pragma unroll
        for (int i = 0; i < 8; i++) {
            int e = i * 8 + ty;
            if (e < nE) {
                float4 v;
                v.x = acc[i][0] + b2v.x;
                v.y = acc[i][1] + b2v.y;
                v.z = acc[i][2] + b2v.z;
                v.w = acc[i][3] + b2v.w;
                atomicAdd((float4*)(g_aggr + (size_t)sN[e] * 128) + tx, v);
                atomicAdd((float4*)(g_aggr + (size_t)sN[TE + e] * 128) + tx, v);
            }
        }
    }
    if (tid < nE) {
        atomicAdd(&g_cnt[sN[tid]], 1.f);
        atomicAdd(&g_cnt[sN[TE + tid]], 1.f);
    }
}

// ======================= K2: GRU memory update =======================
// 32 nodes per block, 256 threads. Thread (tx,ty): rows i*8+ty (i<4), cols tx+32j.
__device__ __forceinline__ void gru_gate(
    const float* __restrict__ Wih, const float* __restrict__ Whh,
    const float* sIn, float* sWa,
    int tid, int tx, int ty, int jr, float acc[4][4])
{
    for (int k0 = 0; k0 < 256; k0 += 32) {
        for (int idx = tid; idx < 32 * 128; idx += 256) {
            int kk = idx & 31, j = idx >> 5;
            int kg = k0 + kk;
            float w = (kg < 128) ? __ldg(Wih + (size_t)(jr + j) * 128 + kg)
                                 : __ldg(Whh + (size_t)(jr + j) * 128 + (kg - 128));
            sWa[kk * 129 + j] = w;
        }
        __syncthreads();
        #pragma unroll
        for (int kk = 0; kk < 32; kk++) {
            float wv[4];
            #pragma unroll
            for (int j = 0; j < 4; j++) wv[j] = sWa[kk * 129 + tx + 32 * j];
            #pragma unroll
            for (int i = 0; i < 4; i++) {
                float xv = sIn[(i * 8 + ty) * 256 + k0 + kk];
                #pragma unroll
                for (int j = 0; j < 4; j++) acc[i][j] = fmaf(xv, wv[j], acc[i][j]);
            }
        }
        __syncthreads();
    }
}

__global__ __launch_bounds__(256, 2) void k_gru(
    const float* __restrict__ memory,
    const float* __restrict__ Wih, const float* __restrict__ Whh,
    const float* __restrict__ bih, const float* __restrict__ bhh)
{
    float* sIn  = smem;                 // 32*256
    float* sWa  = sIn + TN * 256;       // 32*129
    float* sWb  = sWa + 32 * 129;       // 32*129
    float* sCnt = sWb + 32 * 129;       // 32

    const int tid = threadIdx.x;
    const int n0 = blockIdx.x * TN;
    const int nN = min(TN, N_NODES - n0);

    if (tid < TN) sCnt[tid] = (tid < nN) ? g_cnt[n0 + tid] : 0.f;
    __syncthreads();

    for (int idx = tid; idx < TN * 128; idx += 256) {
        int n = idx >> 7, c = idx & 127;
        float mm = 0.f, mv = 0.f;
        if (n < nN) {
            float cnt = sCnt[n];
            mm = (cnt > 0.f) ? g_aggr[(size_t)(n0 + n) * 128 + c] / cnt : 0.f;
            mv = memory[(size_t)(n0 + n) * 128 + c];
        }
        sIn[n * 256 + c]       = mm;
        sIn[n * 256 + 128 + c] = mv;
    }
    __syncthreads();

    const int tx = tid & 31, ty = tid >> 5;

    float rg[4][4], zg[4][4];
    #pragma unroll
    for (int i = 0; i < 4; i++)
        #pragma unroll
        for (int j = 0; j < 4; j++) { rg[i][j] = 0.f; zg[i][j] = 0.f; }

    gru_gate(Wih, Whh, sIn, sWa, tid, tx, ty, 0, rg);
    gru_gate(Wih, Whh, sIn, sWa, tid, tx, ty, 128, zg);

    #pragma unroll
    for (int i = 0; i < 4; i++)
        #pragma unroll
        for (int j = 0; j < 4; j++) {
            int jc = tx + 32 * j;
            rg[i][j] = 1.f / (1.f + expf(-(rg[i][j] + __ldg(bih + jc) + __ldg(bhh + jc))));
            zg[i][j] = 1.f / (1.f + expf(-(zg[i][j] + __ldg(bih + 128 + jc) + __ldg(bhh + 128 + jc))));
        }

    float acci[4][4], acch[4][4];
    #pragma unroll
    for (int i = 0; i < 4; i++)
        #pragma unroll
        for (int j = 0; j < 4; j++) { acci[i][j] = 0.f; acch[i][j] = 0.f; }

    for (int k0 = 0; k0 < 128; k0 += 32) {
        for (int idx = tid; idx < 32 * 128; idx += 256) {
            int kk = idx & 31, j = idx >> 5;
            sWa[kk * 129 + j] = __ldg(Wih + (size_t)(256 + j) * 128 + k0 + kk);
            sWb[kk * 129 + j] = __ldg(Whh + (size_t)(256 + j) * 128 + k0 + kk);
        }
        __syncthreads();
        #pragma unroll
        for (int kk = 0; kk < 32; kk++) {
            float wa[4], wb[4];
            #pragma unroll
            for (int j = 0; j < 4; j++) {
                wa[j] = sWa[kk * 129 + tx + 32 * j];
                wb[j] = sWb[kk * 129 + tx + 32 * j];
            }
            #pragma unroll
            for (int i = 0; i < 4; i++) {
                float xm = sIn[(i * 8 + ty) * 256 + k0 + kk];
                float xh = sIn[(i * 8 + ty) * 256 + 128 + k0 + kk];
                #pragma unroll
                for (int j = 0; j < 4; j++) {
                    acci[i][j] = fmaf(xm, wa[j], acci[i][j]);
                    acch[i][j] = fmaf(xh, wb[j], acch[i][j]);
                }
            }
        }
        __syncthreads();
    }

    #pragma unroll
    for (int i = 0; i < 4; i++) {
        int n = i * 8 + ty;
        if (n < nN) {
            float cnt = sCnt[n];
            #pragma unroll
            for (int j = 0; j < 4; j++) {
                int jc = tx + 32 * j;
                float i_n = acci[i][j] + __ldg(bih + 256 + jc);
                float h_n = acch[i][j] + __ldg(bhh + 256 + jc);
                float nn = tanhf(i_n + rg[i][j] * h_n);
                float mv = sIn[n * 256 + 128 + jc];
                float hnew = (1.f - zg[i][j]) * nn + zg[i][j] * mv;
                g_newmem[(size_t)(n0 + n) * 128 + jc] = (cnt > 0.f) ? hnew : mv;
            }
        }
    }
}

// ======================= K3: embeddings + dot =======================
// 64 edges/block, 256 threads. Thread (tx,ty), tx<16, ty<16:
// rows i*16+ty (i<4), cols 4*tx..4*tx+3.
__global__ __launch_bounds__(256, 2) void k_emb(
    const int* __restrict__ src, const int* __restrict__ dst,
    const float* __restrict__ sf, const float* __restrict__ df,
    const float* __restrict__ W1, const float* __restrict__ b1,
    const float* __restrict__ W2, const float* __restrict__ b2,
    float* __restrict__ out, int E)
{
    float* sA  = smem;              // 64*128
    float* sW  = sA + 64 * 128;     // 32*64
    float* sW2 = sW + 32 * 64;      // 64*64
    float* sH1 = sW2 + 64 * 64;     // 64*68 (padded)
    float* sEs = sH1 + 64 * 68;     // 64*68
    int* sNode = (int*)(sEs + 64 * 68); // 64

    const int tid = threadIdx.x;
    const int e0 = blockIdx.x * TE;
    const int nE = min(TE, E - e0);
    const int tx = tid & 15, ty = tid >> 4;

    // resident W2
    #pragma unroll
    for (int it = 0; it < 4; it++)
        ((float4*)sW2)[tid + 256 * it] = __ldg((const float4*)W2 + tid + 256 * it);

    const float4 b1v = __ldg((const float4*)b1 + tx);
    const float4 b2v = __ldg((const float4*)b2 + tx);

    for (int ep = 0; ep < 2; ep++) {
        const int* nodes = ep ? dst : src;
        const float* feats = ep ? df : sf;
        __syncthreads();

        if (tid < TE) sNode[tid] = (tid < nE) ? nodes[e0 + tid] : 0;
        __syncthreads();

        // Phase 0: A = new_memory[node]  (K rows 0..127)
        for (int idx = tid; idx < TE * 32; idx += 256) {
            int e = idx >> 5, c4 = idx & 31;
            float4 v = make_float4(0.f, 0.f, 0.f, 0.f);
            if (e < nE) v = *((const float4*)(g_newmem + (size_t)sNode[e] * 128) + c4);
            ((float4*)(sA + e * 128))[c4] = v;
        }

        float acc[4][4];
        #pragma unroll
        for (int i = 0; i < 4; i++)
            #pragma unroll
            for (int j = 0; j < 4; j++) acc[i][j] = 0.f;

        for (int k0 = 0; k0 < 128; k0 += 32) {
            const float4* wsrc = (const float4*)(W1 + (size_t)k0 * 64);
            #pragma unroll
            for (int it = 0; it < 2; it++)
                ((float4*)sW)[tid + 256 * it] = __ldg(wsrc + tid + 256 * it);
            __syncthreads();
            #pragma unroll
            for (int kk = 0; kk < 32; kk++) {
                float4 w = ((const float4*)sW)[kk * 16 + tx];
                #pragma unroll
                for (int i = 0; i < 4; i++) {
                    float xv = sA[(i * 16 + ty) * 128 + k0 + kk];
                    acc[i][0] = fmaf(xv, w.x, acc[i][0]);
                    acc[i][1] = fmaf(xv, w.y, acc[i][1]);
                    acc[i][2] = fmaf(xv, w.z, acc[i][2]);
                    acc[i][3] = fmaf(xv, w.w, acc[i][3]);
                }
            }
            __syncthreads();
        }

        // Phase 1: A = feats 64x64  (K rows 128..191)
        for (int idx = tid; idx < TE * 16; idx += 256) {
            int e = idx >> 4, c4 = idx & 15;
            float4 v = make_float4(0.f, 0.f, 0.f, 0.f);
            if (e < nE) v = __ldg((const float4*)(feats + (size_t)(e0 + e) * 64) + c4);
            ((float4*)(sA + e * 64))[c4] = v;
        }
        for (int k0 = 0; k0 < 64; k0 += 32) {
            const float4* wsrc = (const float4*)(W1 + (size_t)(128 + k0) * 64);
            #pragma unroll
            for (int it = 0; it < 2; it++)
                ((float4*)sW)[tid + 256 * it] = __ldg(wsrc + tid + 256 * it);
            __syncthreads();
            #pragma unroll
            for (int kk = 0; kk < 32; kk++) {
                float4 w = ((const float4*)sW)[kk * 16 + tx];
                #pragma unroll
                for (int i = 0; i < 4; i++) {
                    float xv = sA[(i * 16 + ty) * 64 + k0 + kk];
                    acc[i][0] = fmaf(xv, w.x, acc[i][0]);
                    acc[i][1] = fmaf(xv, w.y, acc[i][1]);
                    acc[i][2] = fmaf(xv, w.z, acc[i][2]);
                    acc[i][3] = fmaf(xv, w.w, acc[i][3]);
                }
            }
            __syncthreads();
        }

        // bias + relu -> sH1 (stride 68)
        #pragma unroll
        for (int i = 0; i < 4; i++) {
            float4 h;
            h.x = fmaxf(acc[i][0] + b1v.x, 0.f);
            h.y = fmaxf(acc[i][1] + b1v.y, 0.f);
            h.z = fmaxf(acc[i][2] + b1v.z, 0.f);
            h.w = fmaxf(acc[i][3] + b1v.w, 0.f);
            ((float4*)(sH1 + (i * 16 + ty) * 68))[tx] = h;
        }
        __syncthreads();

        // GEMM2: K=64, resident W2
        float acc2[4][4];
        #pragma unroll
        for (int i = 0; i < 4; i++)
            #pragma unroll
            for (int j = 0; j < 4; j++) acc2[i][j] = 0.f;

        #pragma unroll
        for (int k = 0; k < 64; k++) {
            float4 w = ((const float4*)sW2)[k * 16 + tx];
            #pragma unroll
            for (int i = 0; i < 4; i++) {
                float xv = sH1[(i * 16 + ty) * 68 + k];
                acc2[i][0] = fmaf(xv, w.x, acc2[i][0]);
                acc2[i][1] = fmaf(xv, w.y, acc2[i][1]);
                acc2[i][2] = fmaf(xv, w.z, acc2[i][2]);
                acc2[i][3] = fmaf(xv, w.w, acc2[i][3]);
            }
        }

        if (ep == 0) {
            #pragma unroll
            for (int i = 0; i < 4; i++) {
                float4 v;
                v.x = acc2[i][0] + b2v.x;
                v.y = acc2[i][1] + b2v.y;
                v.z = acc2[i][2] + b2v.z;
                v.w = acc2[i][3] + b2v.w;
                ((float4*)(sEs + (i * 16 + ty) * 68))[tx] = v;
            }
        } else {
            float p[4];
            #pragma unroll
            for (int i = 0; i < 4; i++) {
                float4 s = ((const float4*)(sEs + (i * 16 + ty) * 68))[tx];
                p[i] = (acc2[i][0] + b2v.x) * s.x
                     + (acc2[i][1] + b2v.y) * s.y
                     + (acc2[i][2] + b2v.z) * s.z
                     + (acc2[i][3] + b2v.w) * s.w;
            }
            #pragma unroll
            for (int m = 1; m < 16; m <<= 1) {
                #pragma unroll
                for (int i = 0; i < 4; i++)
                    p[i] += __shfl_xor_sync(0xffffffffu, p[i], m);
            }
            if (tx == 0) {
                #pragma unroll
                for (int i = 0; i < 4; i++) {
                    int e = i * 16 + ty;
                    if (e < nE) out[e0 + e] = p[i];
                }
            }
        }
    }
}

// ---------------- host launch ----------------
extern "C" void kernel_launch(void* const* d_in, const int* in_sizes, int n_in,
                              void* d_out, int out_size)
{
    const int*   src   = (const int*)d_in[0];
    const int*   dst   = (const int*)d_in[1];
    const float* ef    = (const float*)d_in[2];
    const float* ts    = (const float*)d_in[3];
    const float* sf    = (const float*)d_in[4];
    const float* df    = (const float*)d_in[5];
    const float* mem   = (const float*)d_in[6];
    const float* tw    = (const float*)d_in[7];
    const float* tb    = (const float*)d_in[8];
    const float* mw1   = (const float*)d_in[9];
    const float* mb1   = (const float*)d_in[10];
    const float* mw2   = (const float*)d_in[11];
    const float* mb2   = (const float*)d_in[12];
    const float* gwih  = (const float*)d_in[13];
    const float* gwhh  = (const float*)d_in[14];
    const float* gbih  = (const float*)d_in[15];
    const float* gbhh  = (const float*)d_in[16];
    const float* ew1   = (const float*)d_in[17];
    const float* eb1   = (const float*)d_in[18];
    const float* ew2   = (const float*)d_in[19];
    const float* eb2   = (const float*)d_in[20];
    float* out = (float*)d_out;

    const int E = in_sizes[0];

    const int SMEM1 = (64 * 128 + 32 * 128 + 64 * 128) * 4 + 2 * 64 * 4;
    const int SMEM2 = (TN * 256 + 2 * 32 * 129 + TN) * 4;
    const int SMEM3 = (64 * 128 + 32 * 64 + 64 * 64 + 2 * 64 * 68) * 4 + 64 * 4;

    cudaFuncSetAttribute(k_msg, cudaFuncAttributeMaxDynamicSharedMemorySize, SMEM1);
    cudaFuncSetAttribute(k_gru, cudaFuncAttributeMaxDynamicSharedMemorySize, SMEM2);
    cudaFuncSetAttribute(k_emb, cudaFuncAttributeMaxDynamicSharedMemorySize, SMEM3);

    k_zero<<<2048, 256>>>();
    k_msg<<<(E + TE - 1) / TE, 256, SMEM1>>>(src, dst, ef, ts, mem, tw, tb,
                                             mw1, mb1, mw2, mb2, E);
    k_gru<<<(N_NODES + TN - 1) / TN, 256, SMEM2>>>(mem, gwih, gwhh, gbih, gbhh);
    k_emb<<<(E + TE - 1) / TE, 256, SMEM3>>>(src, dst, sf, df,
                                             ew1, eb1, ew2, eb2, out, E);
}

// round 3
// speedup vs baseline: 1.8587x; 1.0415x over previous
#include <cuda_runtime.h>
#include <math.h>

#define N_NODES 100000
#define MEM_DIM 128
#define MSG_DIM 128
#define TN 32

// ---------------- scratch (static device globals; no allocation) ----------------
__device__ float g_aggr[(size_t)N_NODES * MSG_DIM];
__device__ float g_cnt[N_NODES];
__device__ float g_newmem[(size_t)N_NODES * MEM_DIM];
__device__ float g_M[64 * 64];   // W2 @ W2^T (symmetric)
__device__ float g_v[64];        // W2 @ b2
__device__ float g_c0;           // b2.b2

extern __shared__ float smem[];

// ---------------- K0: zero aggregation buffers ----------------
__global__ void k_zero() {
    size_t stride = (size_t)gridDim.x * blockDim.x;
    size_t tid0 = (size_t)blockIdx.x * blockDim.x + threadIdx.x;
    size_t tot = (size_t)N_NODES * MSG_DIM;
    for (size_t i = tid0; i < tot; i += stride) g_aggr[i] = 0.f;
    for (size_t i = tid0; i < N_NODES; i += stride) g_cnt[i] = 0.f;
}

// ---------------- K-pre: M = W2 W2^T, v = W2 b2, c0 = b2.b2 ----------------
__global__ void k_pre(const float* __restrict__ W2, const float* __restrict__ b2) {
    __shared__ float sW2[64 * 64];
    __shared__ float sb2[64];
    int tid = threadIdx.x;
    for (int i = tid; i < 64 * 64; i += 256) sW2[i] = W2[i];
    if (tid < 64) sb2[tid] = b2[tid];
    __syncthreads();
    for (int p = tid; p < 64 * 64; p += 256) {
        int j = p >> 6, k = p & 63;
        float s = 0.f;
        #pragma unroll 16
        for (int c = 0; c < 64; c++) s = fmaf(sW2[j * 64 + c], sW2[k * 64 + c], s);
        g_M[p] = s;
    }
    if (tid < 64) {
        float s = 0.f;
        #pragma unroll 16
        for (int c = 0; c < 64; c++) s = fmaf(sW2[tid * 64 + c], sb2[c], s);
        g_v[tid] = s;
    }
    if (tid == 0) {
        float s = 0.f;
        for (int c = 0; c < 64; c++) s = fmaf(sb2[c], sb2[c], s);
        g_c0 = s;
    }
}

// ---------------- shared helpers ----------------
// stage 32 K-rows x 128 cols of W into sW
__device__ __forceinline__ void stage_w128(const float* __restrict__ Wg, int row0,
                                           float* sW, int tid) {
    const float4* wsrc = (const float4*)(Wg + (size_t)row0 * 128);
    #pragma unroll
    for (int it = 0; it < 4; it++)
        ((float4*)sW)[tid + 256 * it] = __ldg(wsrc + tid + 256 * it);
}
// stage 32 K-rows x 64 cols of W into sW
__device__ __forceinline__ void stage_w64(const float* __restrict__ Wg, int row0,
                                          float* sW, int tid) {
    const float4* wsrc = (const float4*)(Wg + (size_t)row0 * 64);
    #pragma unroll
    for (int it = 0; it < 2; it++)
        ((float4*)sW)[tid + 256 * it] = __ldg(wsrc + tid + 256 * it);
}
// stage A chunk: 128 rows x 32 cols gathered from 128-wide rows of base, f4 offset q0
__device__ __forceinline__ void stage_a_gather(const float* __restrict__ base,
                                               const int* sN, int nE, int q0,
                                               float* sA, int tid) {
    #pragma unroll
    for (int it = 0; it < 4; it++) {
        int idx = tid + 256 * it;
        int e = idx >> 3, q = idx & 7;
        float4 v = make_float4(0.f, 0.f, 0.f, 0.f);
        if (e < nE) v = __ldg((const float4*)(base + (size_t)sN[e] * 128) + q0 + q);
        ((float4*)sA)[idx] = v;
    }
}
// C[128x128] += A[128x32chunk] * W[32x128]; thread(tx<16,ty<16): rows i*16+ty, cols 4tx & 64+4tx
__device__ __forceinline__ void mm128(const float* sA_, int astride, int kbase,
                                      const float* sW_, int tx, int ty,
                                      float4 acc0[8], float4 acc1[8]) {
    #pragma unroll
    for (int kk = 0; kk < 32; kk++) {
        float4 w0 = ((const float4*)sW_)[kk * 32 + tx];
        float4 w1 = ((const float4*)sW_)[kk * 32 + 16 + tx];
        #pragma unroll
        for (int i = 0; i < 8; i++) {
            float a = sA_[(i * 16 + ty) * astride + kbase + kk];
            acc0[i].x = fmaf(a, w0.x, acc0[i].x);
            acc0[i].y = fmaf(a, w0.y, acc0[i].y);
            acc0[i].z = fmaf(a, w0.z, acc0[i].z);
            acc0[i].w = fmaf(a, w0.w, acc0[i].w);
            acc1[i].x = fmaf(a, w1.x, acc1[i].x);
            acc1[i].y = fmaf(a, w1.y, acc1[i].y);
            acc1[i].z = fmaf(a, w1.z, acc1[i].z);
            acc1[i].w = fmaf(a, w1.w, acc1[i].w);
        }
    }
}
// C[128x64] += A[128x32chunk] * W[32x64]
__device__ __forceinline__ void mm64(const float* sA_, const float* sW_,
                                     int tx, int ty, float4 acc[8]) {
    #pragma unroll
    for (int kk = 0; kk < 32; kk++) {
        float4 w = ((const float4*)sW_)[kk * 16 + tx];
        #pragma unroll
        for (int i = 0; i < 8; i++) {
            float a = sA_[(i * 16 + ty) * 32 + kk];
            acc[i].x = fmaf(a, w.x, acc[i].x);
            acc[i].y = fmaf(a, w.y, acc[i].y);
            acc[i].z = fmaf(a, w.z, acc[i].z);
            acc[i].w = fmaf(a, w.w, acc[i].w);
        }
    }
}

// ======================= K1: message MLP + scatter (128 edges/block) ==============
__global__ __launch_bounds__(256, 2) void k_msg(
    const int* __restrict__ src, const int* __restrict__ dst,
    const float* __restrict__ ef, const float* __restrict__ ts,
    const float* __restrict__ memory,
    const float* __restrict__ tw, const float* __restrict__ tb,
    const float* __restrict__ W1, const float* __restrict__ b1,
    const float* __restrict__ W2, const float* __restrict__ b2,
    int E)
{
    float* sA = smem;                   // 128*32
    float* sW = sA + 128 * 32;          // 32*128
    float* sH = sW + 32 * 128;          // 128*128
    int*   sN = (int*)(sH + 128 * 128); // 256

    const int tid = threadIdx.x;
    const int e0 = blockIdx.x * 128;
    const int nE = min(128, E - e0);
    const int tx = tid & 15, ty = tid >> 4;

    if (tid < 128)       sN[tid] = (tid < nE) ? src[e0 + tid] : 0;
    else                 sN[tid] = (tid - 128 < nE) ? dst[e0 + tid - 128] : 0;

    float4 acc0[8], acc1[8];
    #pragma unroll
    for (int i = 0; i < 8; i++) {
        acc0[i] = make_float4(0.f, 0.f, 0.f, 0.f);
        acc1[i] = make_float4(0.f, 0.f, 0.f, 0.f);
    }
    __syncthreads();

    // GEMM1: K rows 0..127 (src memory)
    #pragma unroll 1
    for (int kc = 0; kc < 4; kc++) {
        stage_a_gather(memory, sN, nE, kc * 8, sA, tid);
        stage_w128(W1, kc * 32, sW, tid);
        __syncthreads();
        mm128(sA, 32, 0, sW, tx, ty, acc0, acc1);
        __syncthreads();
    }
    // K rows 128..255 (dst memory)
    #pragma unroll 1
    for (int kc = 0; kc < 4; kc++) {
        stage_a_gather(memory, sN + 128, nE, kc * 8, sA, tid);
        stage_w128(W1, 128 + kc * 32, sW, tid);
        __syncthreads();
        mm128(sA, 32, 0, sW, tx, ty, acc0, acc1);
        __syncthreads();
    }
    // K rows 256..287 (edge features)
    {
        #pragma unroll
        for (int it = 0; it < 4; it++) {
            int idx = tid + 256 * it;
            int e = idx >> 3, q = idx & 7;
            float4 v = make_float4(0.f, 0.f, 0.f, 0.f);
            if (e < nE) v = __ldg((const float4*)(ef + (size_t)(e0 + e) * 32) + q);
            ((float4*)sA)[idx] = v;
        }
        stage_w128(W1, 256, sW, tid);
        __syncthreads();
        mm128(sA, 32, 0, sW, tx, ty, acc0, acc1);
        __syncthreads();
    }
    // K rows 288..319 (time encoding)
    {
        for (int it = 0; it < 16; it++) {
            int idx = tid + 256 * it;
            int e = idx >> 5, c = idx & 31;
            float t = 0.f;
            if (e < nE) t = cosf(ts[e0 + e] * __ldg(tw + c) + __ldg(tb + c));
            sA[idx] = t;
        }
        stage_w128(W1, 288, sW, tid);
        __syncthreads();
        mm128(sA, 32, 0, sW, tx, ty, acc0, acc1);
    }

    // bias + relu -> sH
    {
        float4 b1a = __ldg((const float4*)b1 + tx);
        float4 b1b = __ldg((const float4*)b1 + 16 + tx);
        #pragma unroll
        for (int i = 0; i < 8; i++) {
            int row = i * 16 + ty;
            float4 h0, h1;
            h0.x = fmaxf(acc0[i].x + b1a.x, 0.f); h0.y = fmaxf(acc0[i].y + b1a.y, 0.f);
            h0.z = fmaxf(acc0[i].z + b1a.z, 0.f); h0.w = fmaxf(acc0[i].w + b1a.w, 0.f);
            h1.x = fmaxf(acc1[i].x + b1b.x, 0.f); h1.y = fmaxf(acc1[i].y + b1b.y, 0.f);
            h1.z = fmaxf(acc1[i].z + b1b.z, 0.f); h1.w = fmaxf(acc1[i].w + b1b.w, 0.f);
            ((float4*)(sH + row * 128))[tx] = h0;
            ((float4*)(sH + row * 128))[16 + tx] = h1;
        }
        #pragma unroll
        for (int i = 0; i < 8; i++) {
            acc0[i] = make_float4(0.f, 0.f, 0.f, 0.f);
            acc1[i] = make_float4(0.f, 0.f, 0.f, 0.f);
        }
    }

    // GEMM2: K=128 over sH
    #pragma unroll 1
    for (int kc = 0; kc < 4; kc++) {
        __syncthreads();
        stage_w128(W2, kc * 32, sW, tid);
        __syncthreads();
        mm128(sH, 128, kc * 32, sW, tx, ty, acc0, acc1);
    }

    // scatter (float4 vector atomics)
    {
        float4 b2a = __ldg((const float4*)b2 + tx);
        float4 b2b = __ldg((const float4*)b2 + 16 + tx);
        #pragma unroll
        for (int i = 0; i < 8; i++) {
            int e = i * 16 + ty;
            if (e < nE) {
                float4 v0, v1;
                v0.x = acc0[i].x + b2a.x; v0.y = acc0[i].y + b2a.y;
                v0.z = acc0[i].z + b2a.z; v0.w = acc0[i].w + b2a.w;
                v1.x = acc1[i].x + b2b.x; v1.y = acc1[i].y + b2b.y;
                v1.z = acc1[i].z + b2b.z; v1.w = acc1[i].w + b2b.w;
                int ns = sN[e], nd = sN[128 + e];
                atomicAdd((float4*)(g_aggr + (size_t)ns * 128) + tx, v0);
                atomicAdd((float4*)(g_aggr + (size_t)ns * 128) + 16 + tx, v1);
                atomicAdd((float4*)(g_aggr + (size_t)nd * 128) + tx, v0);
                atomicAdd((float4*)(g_aggr + (size_t)nd * 128) + 16 + tx, v1);
            }
        }
    }
    if (tid < nE) {
        atomicAdd(&g_cnt[sN[tid]], 1.f);
        atomicAdd(&g_cnt[sN[128 + tid]], 1.f);
    }
}

// ======================= K2: GRU memory update =======================
__device__ __forceinline__ void gru_gate(
    const float* __restrict__ Wih, const float* __restrict__ Whh,
    const float* sIn, float* sWa,
    int tid, int tx, int ty, int jr, float acc[4][4])
{
    for (int k0 = 0; k0 < 256; k0 += 32) {
        for (int idx = tid; idx < 32 * 128; idx += 256) {
            int kk = idx & 31, j = idx >> 5;
            int kg = k0 + kk;
            float w = (kg < 128) ? __ldg(Wih + (size_t)(jr + j) * 128 + kg)
                                 : __ldg(Whh + (size_t)(jr + j) * 128 + (kg - 128));
            sWa[kk * 129 + j] = w;
        }
        __syncthreads();
        #pragma unroll
        for (int kk = 0; kk < 32; kk++) {
            float wv[4];
            #pragma unroll
            for (int j = 0; j < 4; j++) wv[j] = sWa[kk * 129 + tx + 32 * j];
            #pragma unroll
            for (int i = 0; i < 4; i++) {
                float xv = sIn[(i * 8 + ty) * 256 + k0 + kk];
                #pragma unroll
                for (int j = 0; j < 4; j++) acc[i][j] = fmaf(xv, wv[j], acc[i][j]);
            }
        }
        __syncthreads();
    }
}

__global__ __launch_bounds__(256, 2) void k_gru(
    const float* __restrict__ memory,
    const float* __restrict__ Wih, const float* __restrict__ Whh,
    const float* __restrict__ bih, const float* __restrict__ bhh)
{
    float* sIn  = smem;
    float* sWa  = sIn + TN * 256;
    float* sWb  = sWa + 32 * 129;
    float* sCnt = sWb + 32 * 129;

    const int tid = threadIdx.x;
    const int n0 = blockIdx.x * TN;
    const int nN = min(TN, N_NODES - n0);

    if (tid < TN) sCnt[tid] = (tid < nN) ? g_cnt[n0 + tid] : 0.f;
    __syncthreads();

    for (int idx = tid; idx < TN * 128; idx += 256) {
        int n = idx >> 7, c = idx & 127;
        float mm = 0.f, mv = 0.f;
        if (n < nN) {
            float cnt = sCnt[n];
            mm = (cnt > 0.f) ? g_aggr[(size_t)(n0 + n) * 128 + c] / cnt : 0.f;
            mv = memory[(size_t)(n0 + n) * 128 + c];
        }
        sIn[n * 256 + c]       = mm;
        sIn[n * 256 + 128 + c] = mv;
    }
    __syncthreads();

    const int tx = tid & 31, ty = tid >> 5;

    float rg[4][4], zg[4][4];
    #pragma unroll
    for (int i = 0; i < 4; i++)
        #pragma unroll
        for (int j = 0; j < 4; j++) { rg[i][j] = 0.f; zg[i][j] = 0.f; }

    gru_gate(Wih, Whh, sIn, sWa, tid, tx, ty, 0, rg);
    gru_gate(Wih, Whh, sIn, sWa, tid, tx, ty, 128, zg);

    #pragma unroll
    for (int i = 0; i < 4; i++)
        #pragma unroll
        for (int j = 0; j < 4; j++) {
            int jc = tx + 32 * j;
            rg[i][j] = 1.f / (1.f + expf(-(rg[i][j] + __ldg(bih + jc) + __ldg(bhh + jc))));
            zg[i][j] = 1.f / (1.f + expf(-(zg[i][j] + __ldg(bih + 128 + jc) + __ldg(bhh + 128 + jc))));
        }

    float acci[4][4], acch[4][4];
    #pragma unroll
    for (int i = 0; i < 4; i++)
        #pragma unroll
        for (int j = 0; j < 4; j++) { acci[i][j] = 0.f; acch[i][j] = 0.f; }

    for (int k0 = 0; k0 < 128; k0 += 32) {
        for (int idx = tid; idx < 32 * 128; idx += 256) {
            int kk = idx & 31, j = idx >> 5;
            sWa[kk * 129 + j] = __ldg(Wih + (size_t)(256 + j) * 128 + k0 + kk);
            sWb[kk * 129 + j] = __ldg(Whh + (size_t)(256 + j) * 128 + k0 + kk);
        }
        __syncthreads();
        #pragma unroll
        for (int kk = 0; kk < 32; kk++) {
            float wa[4], wb[4];
            #pragma unroll
            for (int j = 0; j < 4; j++) {
                wa[j] = sWa[kk * 129 + tx + 32 * j];
                wb[j] = sWb[kk * 129 + tx + 32 * j];
            }
            #pragma unroll
            for (int i = 0; i < 4; i++) {
                float xm = sIn[(i * 8 + ty) * 256 + k0 + kk];
                float xh = sIn[(i * 8 + ty) * 256 + 128 + k0 + kk];
                #pragma unroll
                for (int j = 0; j < 4; j++) {
                    acci[i][j] = fmaf(xm, wa[j], acci[i][j]);
                    acch[i][j] = fmaf(xh, wb[j], acch[i][j]);
                }
            }
        }
        __syncthreads();
    }

    #pragma unroll
    for (int i = 0; i < 4; i++) {
        int n = i * 8 + ty;
        if (n < nN) {
            float cnt = sCnt[n];
            #pragma unroll
            for (int j = 0; j < 4; j++) {
                int jc = tx + 32 * j;
                float i_n = acci[i][j] + __ldg(bih + 256 + jc);
                float h_n = acch[i][j] + __ldg(bhh + 256 + jc);
                float nn = tanhf(i_n + rg[i][j] * h_n);
                float mv = sIn[n * 256 + 128 + jc];
                float hnew = (1.f - zg[i][j]) * nn + zg[i][j] * mv;
                g_newmem[(size_t)(n0 + n) * 128 + jc] = (cnt > 0.f) ? hnew : mv;
            }
        }
    }
}

// ======================= K3: embeddings + bilinear dot (128 edges/block) ==========
__global__ __launch_bounds__(256, 2) void k_emb(
    const int* __restrict__ src, const int* __restrict__ dst,
    const float* __restrict__ sf, const float* __restrict__ df,
    const float* __restrict__ W1, const float* __restrict__ b1,
    float* __restrict__ out, int E)
{
    float* sA  = smem;                  // 128*32
    float* sW  = sA + 128 * 32;         // 32*64
    float* sHs = sW + 32 * 64;          // 128*64
    float* sHd = sHs + 128 * 64;        // 128*64
    float* sM  = sHd + 128 * 64;        // 64*64
    float* sv  = sM + 64 * 64;          // 64
    int*   sN  = (int*)(sv + 64);       // 128

    const int tid = threadIdx.x;
    const int e0 = blockIdx.x * 128;
    const int nE = min(128, E - e0);
    const int tx = tid & 15, ty = tid >> 4;

    #pragma unroll
    for (int it = 0; it < 4; it++)
        ((float4*)sM)[tid + 256 * it] = ((const float4*)g_M)[tid + 256 * it];
    if (tid < 16) ((float4*)sv)[tid] = ((const float4*)g_v)[tid];

    const float4 b1v = __ldg((const float4*)b1 + tx);

    #pragma unroll 1
    for (int side = 0; side < 2; side++) {
        const int* nodes = side ? dst : src;
        const float* feats = side ? df : sf;
        float* sH = side ? sHd : sHs;
        __syncthreads();
        if (tid < 128) sN[tid] = (tid < nE) ? nodes[e0 + tid] : 0;
        __syncthreads();

        float4 acc[8];
        #pragma unroll
        for (int i = 0; i < 8; i++) acc[i] = make_float4(0.f, 0.f, 0.f, 0.f);

        // K rows 0..127: new_memory[node]
        #pragma unroll 1
        for (int kc = 0; kc < 4; kc++) {
            stage_a_gather(g_newmem, sN, nE, kc * 8, sA, tid);
            stage_w64(W1, kc * 32, sW, tid);
            __syncthreads();
            mm64(sA, sW, tx, ty, acc);
            __syncthreads();
        }
        // K rows 128..191: node features (row = 64 floats = 16 f4)
        #pragma unroll 1
        for (int fc = 0; fc < 2; fc++) {
            #pragma unroll
            for (int it = 0; it < 4; it++) {
                int idx = tid + 256 * it;
                int e = idx >> 3, q = idx & 7;
                float4 v = make_float4(0.f, 0.f, 0.f, 0.f);
                if (e < nE) v = __ldg((const float4*)(feats + (size_t)(e0 + e) * 64) + fc * 8 + q);
                ((float4*)sA)[idx] = v;
            }
            stage_w64(W1, 128 + fc * 32, sW, tid);
            __syncthreads();
            mm64(sA, sW, tx, ty, acc);
            if (fc == 0) __syncthreads();
        }

        // bias + relu -> sH
        #pragma unroll
        for (int i = 0; i < 8; i++) {
            int row = i * 16 + ty;
            float4 h;
            h.x = fmaxf(acc[i].x + b1v.x, 0.f);
            h.y = fmaxf(acc[i].y + b1v.y, 0.f);
            h.z = fmaxf(acc[i].z + b1v.z, 0.f);
            h.w = fmaxf(acc[i].w + b1v.w, 0.f);
            ((float4*)(sH + row * 64))[tx] = h;
        }
    }
    __syncthreads();

    // t = hd @ M  (M symmetric, resident)
    float4 t[8];
    #pragma unroll
    for (int i = 0; i < 8; i++) t[i] = make_float4(0.f, 0.f, 0.f, 0.f);
    #pragma unroll 2
    for (int kk = 0; kk < 64; kk++) {
        float4 m = ((const float4*)sM)[kk * 16 + tx];
        #pragma unroll
        for (int i = 0; i < 8; i++) {
            float a = sHd[(i * 16 + ty) * 64 + kk];
            t[i].x = fmaf(a, m.x, t[i].x);
            t[i].y = fmaf(a, m.y, t[i].y);
            t[i].z = fmaf(a, m.z, t[i].z);
            t[i].w = fmaf(a, m.w, t[i].w);
        }
    }

    // dot = hs.t + (hs+hd).v  (+ c0)
    float c0 = g_c0;
    float4 vv = ((const float4*)sv)[tx];
    float p[8];
    #pragma unroll
    for (int i = 0; i < 8; i++) {
        int row = i * 16 + ty;
        float4 hs = ((const float4*)(sHs + row * 64))[tx];
        float4 hd = ((const float4*)(sHd + row * 64))[tx];
        p[i] = hs.x * t[i].x + hs.y * t[i].y + hs.z * t[i].z + hs.w * t[i].w
             + (hs.x + hd.x) * vv.x + (hs.y + hd.y) * vv.y
             + (hs.z + hd.z) * vv.z + (hs.w + hd.w) * vv.w;
    }
    #pragma unroll
    for (int m = 1; m < 16; m <<= 1)
        #pragma unroll
        for (int i = 0; i < 8; i++)
            p[i] += __shfl_xor_sync(0xffffffffu, p[i], m);
    if (tx == 0) {
        #pragma unroll
        for (int i = 0; i < 8; i++) {
            int e = i * 16 + ty;
            if (e < nE) out[e0 + e] = p[i] + c0;
        }
    }
}

// ---------------- host launch ----------------
extern "C" void kernel_launch(void* const* d_in, const int* in_sizes, int n_in,
                              void* d_out, int out_size)
{
    const int*   src   = (const int*)d_in[0];
    const int*   dst   = (const int*)d_in[1];
    const float* ef    = (const float*)d_in[2];
    const float* ts    = (const float*)d_in[3];
    const float* sf    = (const float*)d_in[4];
    const float* df    = (const float*)d_in[5];
    const float* mem   = (const float*)d_in[6];
    const float* tw    = (const float*)d_in[7];
    const float* tb    = (const float*)d_in[8];
    const float* mw1   = (const float*)d_in[9];
    const float* mb1   = (const float*)d_in[10];
    const float* mw2   = (const float*)d_in[11];
    const float* mb2   = (const float*)d_in[12];
    const float* gwih  = (const float*)d_in[13];
    const float* gwhh  = (const float*)d_in[14];
    const float* gbih  = (const float*)d_in[15];
    const float* gbhh  = (const float*)d_in[16];
    const float* ew1   = (const float*)d_in[17];
    const float* eb1   = (const float*)d_in[18];
    const float* ew2   = (const float*)d_in[19];
    const float* eb2   = (const float*)d_in[20];
    float* out = (float*)d_out;

    const int E = in_sizes[0];

    const int SMEM1 = (128 * 32 + 32 * 128 + 128 * 128) * 4 + 256 * 4;
    const int SMEM2 = (TN * 256 + 2 * 32 * 129 + TN) * 4;
    const int SMEM3 = (128 * 32 + 32 * 64 + 2 * 128 * 64 + 64 * 64 + 64) * 4 + 128 * 4;

    cudaFuncSetAttribute(k_msg, cudaFuncAttributeMaxDynamicSharedMemorySize, SMEM1);
    cudaFuncSetAttribute(k_gru, cudaFuncAttributeMaxDynamicSharedMemorySize, SMEM2);
    cudaFuncSetAttribute(k_emb, cudaFuncAttributeMaxDynamicSharedMemorySize, SMEM3);

    k_zero<<<2048, 256>>>();
    k_pre<<<1, 256>>>(ew2, eb2);
    k_msg<<<(E + 127) / 128, 256, SMEM1>>>(src, dst, ef, ts, mem, tw, tb,
                                           mw1, mb1, mw2, mb2, E);
    k_gru<<<(N_NODES + TN - 1) / TN, 256, SMEM2>>>(mem, gwih, gwhh, gbih, gbhh);
    k_emb<<<(E + 127) / 128, 256, SMEM3>>>(src, dst, sf, df,
                                           ew1, eb1, out, E);
}

// round 4
// speedup vs baseline: 2.0025x; 1.0773x over previous
#include <cuda_runtime.h>
#include <math.h>

#define N_NODES 100000
#define MEM_DIM 128
#define MSG_DIM 128

// ---------------- scratch (static device globals; no allocation) ----------------
__device__ float g_aggr[(size_t)N_NODES * MSG_DIM];
__device__ float g_cnt[N_NODES];
__device__ float g_newmem[(size_t)N_NODES * MEM_DIM];
__device__ float g_M[64 * 64];     // W2 @ W2^T (symmetric)
__device__ float g_v[64];          // W2 @ b2
__device__ float g_c0;             // b2.b2
__device__ float g_Wrz[256 * 256]; // transposed GRU weights: r,z gates over [mm|mem]
__device__ float g_Win[128 * 128]; // Wih n-gate transposed
__device__ float g_Whn[128 * 128]; // Whh n-gate transposed

extern __shared__ float smem[];

// ---------------- K0: zero aggregation buffers ----------------
__global__ void k_zero() {
    size_t stride = (size_t)gridDim.x * blockDim.x;
    size_t tid0 = (size_t)blockIdx.x * blockDim.x + threadIdx.x;
    size_t tot4 = (size_t)N_NODES * MSG_DIM / 4;
    float4 z = make_float4(0.f, 0.f, 0.f, 0.f);
    for (size_t i = tid0; i < tot4; i += stride) ((float4*)g_aggr)[i] = z;
    for (size_t i = tid0; i < N_NODES; i += stride) g_cnt[i] = 0.f;
}

// ---------------- K-pre: bilinear precompute for emb ----------------
__global__ void k_pre(const float* __restrict__ W2, const float* __restrict__ b2) {
    __shared__ float sW2[64 * 64];
    __shared__ float sb2[64];
    int tid = threadIdx.x;
    for (int i = tid; i < 64 * 64; i += 256) sW2[i] = W2[i];
    if (tid < 64) sb2[tid] = b2[tid];
    __syncthreads();
    for (int p = tid; p < 64 * 64; p += 256) {
        int j = p >> 6, k = p & 63;
        float s = 0.f;
        #pragma unroll 16
        for (int c = 0; c < 64; c++) s = fmaf(sW2[j * 64 + c], sW2[k * 64 + c], s);
        g_M[p] = s;
    }
    if (tid < 64) {
        float s = 0.f;
        #pragma unroll 16
        for (int c = 0; c < 64; c++) s = fmaf(sW2[tid * 64 + c], sb2[c], s);
        g_v[tid] = s;
    }
    if (tid == 0) {
        float s = 0.f;
        for (int c = 0; c < 64; c++) s = fmaf(sb2[c], sb2[c], s);
        g_c0 = s;
    }
}

// ---------------- K-prew: transpose GRU weights ----------------
__global__ void k_prew(const float* __restrict__ Wih, const float* __restrict__ Whh) {
    int stride = gridDim.x * blockDim.x;
    int idx = blockIdx.x * blockDim.x + threadIdx.x;
    for (int p = idx; p < 256 * 256; p += stride) {
        int k = p >> 8, c = p & 255;
        int gate = c >> 7;          // 0 = r, 1 = z
        int j = c & 127;
        float w = (k < 128) ? Wih[(size_t)(gate * 128 + j) * 128 + k]
                            : Whh[(size_t)(gate * 128 + j) * 128 + (k - 128)];
        g_Wrz[p] = w;
    }
    for (int p = idx; p < 128 * 128; p += stride) {
        int k = p >> 7, j = p & 127;
        g_Win[p] = Wih[(size_t)(256 + j) * 128 + k];
        g_Whn[p] = Whh[(size_t)(256 + j) * 128 + k];
    }
}

// ---------------- shared helpers ----------------
__device__ __forceinline__ void stage_w128_rows(const float* __restrict__ Wg, int row0,
                                                int nrows, float* sW, int tid) {
    const float4* wsrc = (const float4*)(Wg + (size_t)row0 * 128);
    int tot = nrows * 32;
    for (int i = tid; i < tot; i += 256)
        ((float4*)sW)[i] = __ldg(wsrc + i);
}
__device__ __forceinline__ void stage_w64(const float* __restrict__ Wg, int row0,
                                          float* sW, int tid) {
    const float4* wsrc = (const float4*)(Wg + (size_t)row0 * 64);
    #pragma unroll
    for (int it = 0; it < 2; it++)
        ((float4*)sW)[tid + 256 * it] = __ldg(wsrc + tid + 256 * it);
}
// gather 128 rows x 64 cols (16 f4) from 128-wide rows of base, f4 offset q0
__device__ __forceinline__ void stage_a_gather64(const float* __restrict__ base,
                                                 const int* sN, int nE, int q0,
                                                 float* sA, int tid) {
    #pragma unroll
    for (int it = 0; it < 8; it++) {
        int idx = tid + 256 * it;
        int e = idx >> 4, q = idx & 15;
        float4 v = make_float4(0.f, 0.f, 0.f, 0.f);
        if (e < nE) v = __ldg((const float4*)(base + (size_t)sN[e] * 128) + q0 + q);
        ((float4*)sA)[idx] = v;
    }
}
// gather 128 rows x 32 cols (8 f4)
__device__ __forceinline__ void stage_a_gather32(const float* __restrict__ base,
                                                 const int* sN, int nE, int q0,
                                                 float* sA, int tid) {
    #pragma unroll
    for (int it = 0; it < 4; it++) {
        int idx = tid + 256 * it;
        int e = idx >> 3, q = idx & 7;
        float4 v = make_float4(0.f, 0.f, 0.f, 0.f);
        if (e < nE) v = __ldg((const float4*)(base + (size_t)sN[e] * 128) + q0 + q);
        ((float4*)sA)[idx] = v;
    }
}
// C[128x128] += A[128xk] * W[kx128]
__device__ __forceinline__ void mm128(const float* sA_, int astride, int kbase,
                                      const float* sW_, int kcount, int tx, int ty,
                                      float4 acc0[8], float4 acc1[8]) {
    #pragma unroll 16
    for (int kk = 0; kk < kcount; kk++) {
        float4 w0 = ((const float4*)sW_)[kk * 32 + tx];
        float4 w1 = ((const float4*)sW_)[kk * 32 + 16 + tx];
        #pragma unroll
        for (int i = 0; i < 8; i++) {
            float a = sA_[(i * 16 + ty) * astride + kbase + kk];
            acc0[i].x = fmaf(a, w0.x, acc0[i].x);
            acc0[i].y = fmaf(a, w0.y, acc0[i].y);
            acc0[i].z = fmaf(a, w0.z, acc0[i].z);
            acc0[i].w = fmaf(a, w0.w, acc0[i].w);
            acc1[i].x = fmaf(a, w1.x, acc1[i].x);
            acc1[i].y = fmaf(a, w1.y, acc1[i].y);
            acc1[i].z = fmaf(a, w1.z, acc1[i].z);
            acc1[i].w = fmaf(a, w1.w, acc1[i].w);
        }
    }
}
// C[128x64] += A[128x32chunk] * W[32x64]
__device__ __forceinline__ void mm64(const float* sA_, const float* sW_,
                                     int tx, int ty, float4 acc[8]) {
    #pragma unroll 16
    for (int kk = 0; kk < 32; kk++) {
        float4 w = ((const float4*)sW_)[kk * 16 + tx];
        #pragma unroll
        for (int i = 0; i < 8; i++) {
            float a = sA_[(i * 16 + ty) * 32 + kk];
            acc[i].x = fmaf(a, w.x, acc[i].x);
            acc[i].y = fmaf(a, w.y, acc[i].y);
            acc[i].z = fmaf(a, w.z, acc[i].z);
            acc[i].w = fmaf(a, w.w, acc[i].w);
        }
    }
}

// ======================= K1: message MLP + scatter (128 edges/block) ==============
// smem: U[0:16384) = (sA 128x64 | sW 64x128) during GEMM1, sH 128x128 during GEMM2
//       sW2[16384:20480) 32x128,  sN ints after.
__global__ __launch_bounds__(256, 2) void k_msg(
    const int* __restrict__ src, const int* __restrict__ dst,
    const float* __restrict__ ef, const float* __restrict__ ts,
    const float* __restrict__ memory,
    const float* __restrict__ tw, const float* __restrict__ tb,
    const float* __restrict__ W1, const float* __restrict__ b1,
    const float* __restrict__ W2, const float* __restrict__ b2,
    int E)
{
    float* sA  = smem;              // 128*64
    float* sW  = smem + 8192;       // 64*128
    float* sH  = smem;              // 128*128 (aliases sA+sW)
    float* sW2 = smem + 16384;      // 32*128
    int*   sN  = (int*)(smem + 20480);

    const int tid = threadIdx.x;
    const int e0 = blockIdx.x * 128;
    const int nE = min(128, E - e0);
    const int tx = tid & 15, ty = tid >> 4;

    if (tid < 128) sN[tid] = (tid < nE) ? src[e0 + tid] : 0;
    else           sN[tid] = (tid - 128 < nE) ? dst[e0 + tid - 128] : 0;

    float4 acc0[8], acc1[8];
    #pragma unroll
    for (int i = 0; i < 8; i++) {
        acc0[i] = make_float4(0.f, 0.f, 0.f, 0.f);
        acc1[i] = make_float4(0.f, 0.f, 0.f, 0.f);
    }
    __syncthreads();

    // GEMM1: 5 chunks of K=64
    #pragma unroll 1
    for (int kc = 0; kc < 5; kc++) {
        if (kc < 2) {
            stage_a_gather64(memory, sN, nE, kc * 16, sA, tid);
        } else if (kc < 4) {
            stage_a_gather64(memory, sN + 128, nE, (kc - 2) * 16, sA, tid);
        } else {
            // [ef(32) | te(32)] per edge
            #pragma unroll
            for (int it = 0; it < 4; it++) {
                int idx = tid + 256 * it;
                int e = idx >> 3, q = idx & 7;   // q<8: ef f4
                float4 v = make_float4(0.f, 0.f, 0.f, 0.f);
                if (e < nE) v = __ldg((const float4*)(ef + (size_t)(e0 + e) * 32) + q);
                ((float4*)sA)[e * 16 + q] = v;
            }
            for (int it = 0; it < 16; it++) {
                int idx = tid + 256 * it;
                int e = idx >> 5, c = idx & 31;
                float t = 0.f;
                if (e < nE) t = cosf(ts[e0 + e] * __ldg(tw + c) + __ldg(tb + c));
                sA[e * 64 + 32 + c] = t;
            }
        }
        stage_w128_rows(W1, kc * 64, 64, sW, tid);
        __syncthreads();
        mm128(sA, 64, 0, sW, 64, tx, ty, acc0, acc1);
        __syncthreads();
    }

    // bias + relu -> sH (overwrites sA/sW region; synced above)
    {
        float4 b1a = __ldg((const float4*)b1 + tx);
        float4 b1b = __ldg((const float4*)b1 + 16 + tx);
        #pragma unroll
        for (int i = 0; i < 8; i++) {
            int row = i * 16 + ty;
            float4 h0, h1;
            h0.x = fmaxf(acc0[i].x + b1a.x, 0.f); h0.y = fmaxf(acc0[i].y + b1a.y, 0.f);
            h0.z = fmaxf(acc0[i].z + b1a.z, 0.f); h0.w = fmaxf(acc0[i].w + b1a.w, 0.f);
            h1.x = fmaxf(acc1[i].x + b1b.x, 0.f); h1.y = fmaxf(acc1[i].y + b1b.y, 0.f);
            h1.z = fmaxf(acc1[i].z + b1b.z, 0.f); h1.w = fmaxf(acc1[i].w + b1b.w, 0.f);
            ((float4*)(sH + row * 128))[tx] = h0;
            ((float4*)(sH + row * 128))[16 + tx] = h1;
        }
        #pragma unroll
        for (int i = 0; i < 8; i++) {
            acc0[i] = make_float4(0.f, 0.f, 0.f, 0.f);
            acc1[i] = make_float4(0.f, 0.f, 0.f, 0.f);
        }
    }

    // GEMM2: K=128 over sH, W2 chunks of 32 into sW2
    #pragma unroll 1
    for (int kc = 0; kc < 4; kc++) {
        __syncthreads();
        {
            const float4* wsrc = (const float4*)(W2 + (size_t)kc * 32 * 128);
            #pragma unroll
            for (int it = 0; it < 4; it++)
                ((float4*)sW2)[tid + 256 * it] = __ldg(wsrc + tid + 256 * it);
        }
        __syncthreads();
        mm128(sH, 128, kc * 32, sW2, 32, tx, ty, acc0, acc1);
    }

    // scatter (float4 vector atomics)
    {
        float4 b2a = __ldg((const float4*)b2 + tx);
        float4 b2b = __ldg((const float4*)b2 + 16 + tx);
        #pragma unroll
        for (int i = 0; i < 8; i++) {
            int e = i * 16 + ty;
            if (e < nE) {
                float4 v0, v1;
                v0.x = acc0[i].x + b2a.x; v0.y = acc0[i].y + b2a.y;
                v0.z = acc0[i].z + b2a.z; v0.w = acc0[i].w + b2a.w;
                v1.x = acc1[i].x + b2b.x; v1.y = acc1[i].y + b2b.y;
                v1.z = acc1[i].z + b2b.z; v1.w = acc1[i].w + b2b.w;
                int ns = sN[e], nd = sN[128 + e];
                atomicAdd((float4*)(g_aggr + (size_t)ns * 128) + tx, v0);
                atomicAdd((float4*)(g_aggr + (size_t)ns * 128) + 16 + tx, v1);
                atomicAdd((float4*)(g_aggr + (size_t)nd * 128) + tx, v0);
                atomicAdd((float4*)(g_aggr + (size_t)nd * 128) + 16 + tx, v1);
            }
        }
    }
    if (tid < nE) {
        atomicAdd(&g_cnt[sN[tid]], 1.f);
        atomicAdd(&g_cnt[sN[128 + tid]], 1.f);
    }
}

// ======================= K2: GRU as GEMM over transposed weights ==================
// 32 nodes/block (100000/32 = 3125 exact). Threads (tx<16, ty<16).
// Rows handled: ty and 16+ty. Cols: accRZ m<4 -> c=m*64+4tx (r: m<2, z: m>=2);
// accIN/accHN m<2 -> n-gate col j=m*64+4tx.
__device__ __forceinline__ void gru_chunk(
    const float* sIn, const float* sWrz, const float* sWn, int k0,
    int tx, int ty, float4 accRZ[2][4], float4 accN[2][2])
{
    #pragma unroll 8
    for (int kk = 0; kk < 32; kk++) {
        float4 wrz[4], wn[2];
        #pragma unroll
        for (int m = 0; m < 4; m++) wrz[m] = ((const float4*)sWrz)[kk * 64 + m * 16 + tx];
        #pragma unroll
        for (int m = 0; m < 2; m++) wn[m] = ((const float4*)sWn)[kk * 32 + m * 16 + tx];
        #pragma unroll
        for (int i = 0; i < 2; i++) {
            float a = sIn[(i * 16 + ty) * 256 + k0 + kk];
            #pragma unroll
            for (int m = 0; m < 4; m++) {
                accRZ[i][m].x = fmaf(a, wrz[m].x, accRZ[i][m].x);
                accRZ[i][m].y = fmaf(a, wrz[m].y, accRZ[i][m].y);
                accRZ[i][m].z = fmaf(a, wrz[m].z, accRZ[i][m].z);
                accRZ[i][m].w = fmaf(a, wrz[m].w, accRZ[i][m].w);
            }
            #pragma unroll
            for (int m = 0; m < 2; m++) {
                accN[i][m].x = fmaf(a, wn[m].x, accN[i][m].x);
                accN[i][m].y = fmaf(a, wn[m].y, accN[i][m].y);
                accN[i][m].z = fmaf(a, wn[m].z, accN[i][m].z);
                accN[i][m].w = fmaf(a, wn[m].w, accN[i][m].w);
            }
        }
    }
}

__global__ __launch_bounds__(256, 2) void k_gru(
    const float* __restrict__ memory,
    const float* __restrict__ bih, const float* __restrict__ bhh)
{
    float* sIn  = smem;             // 32*256  (mm | mem)
    float* sWrz = sIn + 32 * 256;   // 32*256
    float* sWn  = sWrz + 32 * 256;  // 32*128
    float* sCnt = sWn + 32 * 128;   // 32

    const int tid = threadIdx.x;
    const int n0 = blockIdx.x * 32;
    const int tx = tid & 15, ty = tid >> 4;

    if (tid < 32) sCnt[tid] = g_cnt[n0 + tid];
    __syncthreads();

    // sIn: 32 nodes x 64 f4 ([mm/cnt | mem])
    #pragma unroll
    for (int it = 0; it < 8; it++) {
        int idx = tid + 256 * it;
        int n = idx >> 6, q = idx & 63;
        float4 v;
        if (q < 32) {
            float cnt = sCnt[n];
            v = *((const float4*)(g_aggr + (size_t)(n0 + n) * 128) + q);
            float inv = (cnt > 0.f) ? (1.f / cnt) : 0.f;
            v.x *= inv; v.y *= inv; v.z *= inv; v.w *= inv;
        } else {
            v = __ldg((const float4*)(memory + (size_t)(n0 + n) * 128) + (q - 32));
        }
        ((float4*)sIn)[idx] = v;
    }

    float4 accRZ[2][4], accIN[2][2], accHN[2][2];
    #pragma unroll
    for (int i = 0; i < 2; i++) {
        #pragma unroll
        for (int m = 0; m < 4; m++) accRZ[i][m] = make_float4(0.f, 0.f, 0.f, 0.f);
        #pragma unroll
        for (int m = 0; m < 2; m++) {
            accIN[i][m] = make_float4(0.f, 0.f, 0.f, 0.f);
            accHN[i][m] = make_float4(0.f, 0.f, 0.f, 0.f);
        }
    }

    // K chunks: kc<4 -> mm half (i_n), kc>=4 -> mem half (h_n)
    #pragma unroll 1
    for (int kc = 0; kc < 4; kc++) {
        __syncthreads();
        {
            const float4* wsrc = (const float4*)(g_Wrz + (size_t)kc * 32 * 256);
            #pragma unroll
            for (int it = 0; it < 8; it++)
                ((float4*)sWrz)[tid + 256 * it] = wsrc[tid + 256 * it];
            const float4* nsrc = (const float4*)(g_Win + (size_t)kc * 32 * 128);
            #pragma unroll
            for (int it = 0; it < 4; it++)
                ((float4*)sWn)[tid + 256 * it] = nsrc[tid + 256 * it];
        }
        __syncthreads();
        gru_chunk(sIn, sWrz, sWn, kc * 32, tx, ty, accRZ, accIN);
    }
    #pragma unroll 1
    for (int kc = 4; kc < 8; kc++) {
        __syncthreads();
        {
            const float4* wsrc = (const float4*)(g_Wrz + (size_t)kc * 32 * 256);
            #pragma unroll
            for (int it = 0; it < 8; it++)
                ((float4*)sWrz)[tid + 256 * it] = wsrc[tid + 256 * it];
            const float4* nsrc = (const float4*)(g_Whn + (size_t)(kc - 4) * 32 * 128);
            #pragma unroll
            for (int it = 0; it < 4; it++)
                ((float4*)sWn)[tid + 256 * it] = nsrc[tid + 256 * it];
        }
        __syncthreads();
        gru_chunk(sIn, sWrz, sWn, kc * 32, tx, ty, accRZ, accHN);
    }

    // epilogue
    #pragma unroll
    for (int i = 0; i < 2; i++) {
        int row = i * 16 + ty;
        float cnt = sCnt[row];
        #pragma unroll
        for (int m = 0; m < 2; m++) {
            int f4idx = m * 16 + tx;
            float4 bir = __ldg((const float4*)bih + f4idx);
            float4 bhr = __ldg((const float4*)bhh + f4idx);
            float4 biz = __ldg((const float4*)bih + 32 + f4idx);
            float4 bhz = __ldg((const float4*)bhh + 32 + f4idx);
            float4 bin = __ldg((const float4*)bih + 64 + f4idx);
            float4 bhn = __ldg((const float4*)bhh + 64 + f4idx);
            float4 mv = ((const float4*)sIn)[row * 64 + 32 + f4idx];

            float4 r, z, nn, res;
            r.x = 1.f / (1.f + expf(-(accRZ[i][m].x + bir.x + bhr.x)));
            r.y = 1.f / (1.f + expf(-(accRZ[i][m].y + bir.y + bhr.y)));
            r.z = 1.f / (1.f + expf(-(accRZ[i][m].z + bir.z + bhr.z)));
            r.w = 1.f / (1.f + expf(-(accRZ[i][m].w + bir.w + bhr.w)));
            z.x = 1.f / (1.f + expf(-(accRZ[i][m + 2].x + biz.x + bhz.x)));
            z.y = 1.f / (1.f + expf(-(accRZ[i][m + 2].y + biz.y + bhz.y)));
            z.z = 1.f / (1.f + expf(-(accRZ[i][m + 2].z + biz.z + bhz.z)));
            z.w = 1.f / (1.f + expf(-(accRZ[i][m + 2].w + biz.w + bhz.w)));
            nn.x = tanhf(accIN[i][m].x + bin.x + r.x * (accHN[i][m].x + bhn.x));
            nn.y = tanhf(accIN[i][m].y + bin.y + r.y * (accHN[i][m].y + bhn.y));
            nn.z = tanhf(accIN[i][m].z + bin.z + r.z * (accHN[i][m].z + bhn.z));
            nn.w = tanhf(accIN[i][m].w + bin.w + r.w * (accHN[i][m].w + bhn.w));
            res.x = (cnt > 0.f) ? ((1.f - z.x) * nn.x + z.x * mv.x) : mv.x;
            res.y = (cnt > 0.f) ? ((1.f - z.y) * nn.y + z.y * mv.y) : mv.y;
            res.z = (cnt > 0.f) ? ((1.f - z.z) * nn.z + z.z * mv.z) : mv.z;
            res.w = (cnt > 0.f) ? ((1.f - z.w) * nn.w + z.w * mv.w) : mv.w;
            ((float4*)(g_newmem + (size_t)(n0 + row) * 128))[f4idx] = res;
        }
    }
}

// ======================= K3: embeddings + bilinear dot (128 edges/block) ==========
__global__ __launch_bounds__(256, 2) void k_emb(
    const int* __restrict__ src, const int* __restrict__ dst,
    const float* __restrict__ sf, const float* __restrict__ df,
    const float* __restrict__ W1, const float* __restrict__ b1,
    float* __restrict__ out, int E)
{
    float* sA  = smem;                  // 128*32
    float* sW  = sA + 128 * 32;         // 32*64
    float* sHs = sW + 32 * 64;          // 128*64
    float* sHd = sHs + 128 * 64;        // 128*64
    float* sM  = sHd + 128 * 64;        // 64*64
    float* sv  = sM + 64 * 64;          // 64
    int*   sN  = (int*)(sv + 64);       // 128

    const int tid = threadIdx.x;
    const int e0 = blockIdx.x * 128;
    const int nE = min(128, E - e0);
    const int tx = tid & 15, ty = tid >> 4;

    #pragma unroll
    for (int it = 0; it < 4; it++)
        ((float4*)sM)[tid + 256 * it] = ((const float4*)g_M)[tid + 256 * it];
    if (tid < 16) ((float4*)sv)[tid] = ((const float4*)g_v)[tid];

    const float4 b1v = __ldg((const float4*)b1 + tx);

    #pragma unroll 1
    for (int side = 0; side < 2; side++) {
        const int* nodes = side ? dst : src;
        const float* feats = side ? df : sf;
        float* sH = side ? sHd : sHs;
        __syncthreads();
        if (tid < 128) sN[tid] = (tid < nE) ? nodes[e0 + tid] : 0;
        __syncthreads();

        float4 acc[8];
        #pragma unroll
        for (int i = 0; i < 8; i++) acc[i] = make_float4(0.f, 0.f, 0.f, 0.f);

        #pragma unroll 1
        for (int kc = 0; kc < 4; kc++) {
            stage_a_gather32(g_newmem, sN, nE, kc * 8, sA, tid);
            stage_w64(W1, kc * 32, sW, tid);
            __syncthreads();
            mm64(sA, sW, tx, ty, acc);
            __syncthreads();
        }
        #pragma unroll 1
        for (int fc = 0; fc < 2; fc++) {
            #pragma unroll
            for (int it = 0; it < 4; it++) {
                int idx = tid + 256 * it;
                int e = idx >> 3, q = idx & 7;
                float4 v = make_float4(0.f, 0.f, 0.f, 0.f);
                if (e < nE) v = __ldg((const float4*)(feats + (size_t)(e0 + e) * 64) + fc * 8 + q);
                ((float4*)sA)[idx] = v;
            }
            stage_w64(W1, 128 + fc * 32, sW, tid);
            __syncthreads();
            mm64(sA, sW, tx, ty, acc);
            if (fc == 0) __syncthreads();
        }

        #pragma unroll
        for (int i = 0; i < 8; i++) {
            int row = i * 16 + ty;
            float4 h;
            h.x = fmaxf(acc[i].x + b1v.x, 0.f);
            h.y = fmaxf(acc[i].y + b1v.y, 0.f);
            h.z = fmaxf(acc[i].z + b1v.z, 0.f);
            h.w = fmaxf(acc[i].w + b1v.w, 0.f);
            ((float4*)(sH + row * 64))[tx] = h;
        }
    }
    __syncthreads();

    float4 t[8];
    #pragma unroll
    for (int i = 0; i < 8; i++) t[i] = make_float4(0.f, 0.f, 0.f, 0.f);
    #pragma unroll 8
    for (int kk = 0; kk < 64; kk++) {
        float4 m = ((const float4*)sM)[kk * 16 + tx];
        #pragma unroll
        for (int i = 0; i < 8; i++) {
            float a = sHd[(i * 16 + ty) * 64 + kk];
            t[i].x = fmaf(a, m.x, t[i].x);
            t[i].y = fmaf(a, m.y, t[i].y);
            t[i].z = fmaf(a, m.z, t[i].z);
            t[i].w = fmaf(a, m.w, t[i].w);
        }
    }

    float c0 = g_c0;
    float4 vv = ((const float4*)sv)[tx];
    float p[8];
    #pragma unroll
    for (int i = 0; i < 8; i++) {
        int row = i * 16 + ty;
        float4 hs = ((const float4*)(sHs + row * 64))[tx];
        float4 hd = ((const float4*)(sHd + row * 64))[tx];
        p[i] = hs.x * t[i].x + hs.y * t[i].y + hs.z * t[i].z + hs.w * t[i].w
             + (hs.x + hd.x) * vv.x + (hs.y + hd.y) * vv.y
             + (hs.z + hd.z) * vv.z + (hs.w + hd.w) * vv.w;
    }
    #pragma unroll
    for (int m = 1; m < 16; m <<= 1)
        #pragma unroll
        for (int i = 0; i < 8; i++)
            p[i] += __shfl_xor_sync(0xffffffffu, p[i], m);
    if (tx == 0) {
        #pragma unroll
        for (int i = 0; i < 8; i++) {
            int e = i * 16 + ty;
            if (e < nE) out[e0 + e] = p[i] + c0;
        }
    }
}

// ---------------- host launch ----------------
extern "C" void kernel_launch(void* const* d_in, const int* in_sizes, int n_in,
                              void* d_out, int out_size)
{
    const int*   src   = (const int*)d_in[0];
    const int*   dst   = (const int*)d_in[1];
    const float* ef    = (const float*)d_in[2];
    const float* ts    = (const float*)d_in[3];
    const float* sf    = (const float*)d_in[4];
    const float* df    = (const float*)d_in[5];
    const float* mem   = (const float*)d_in[6];
    const float* tw    = (const float*)d_in[7];
    const float* tb    = (const float*)d_in[8];
    const float* mw1   = (const float*)d_in[9];
    const float* mb1   = (const float*)d_in[10];
    const float* mw2   = (const float*)d_in[11];
    const float* mb2   = (const float*)d_in[12];
    const float* gwih  = (const float*)d_in[13];
    const float* gwhh  = (const float*)d_in[14];
    const float* gbih  = (const float*)d_in[15];
    const float* gbhh  = (const float*)d_in[16];
    const float* ew1   = (const float*)d_in[17];
    const float* eb1   = (const float*)d_in[18];
    const float* ew2   = (const float*)d_in[19];
    const float* eb2   = (const float*)d_in[20];
    float* out = (float*)d_out;

    const int E = in_sizes[0];

    const int SMEM1 = (16384 + 4096) * 4 + 256 * 4;                          // ~83KB
    const int SMEM2 = (32 * 256 + 32 * 256 + 32 * 128 + 32) * 4;             // ~82KB
    const int SMEM3 = (128 * 32 + 32 * 64 + 2 * 128 * 64 + 64 * 64 + 64) * 4 + 128 * 4;

    cudaFuncSetAttribute(k_msg, cudaFuncAttributeMaxDynamicSharedMemorySize, SMEM1);
    cudaFuncSetAttribute(k_gru, cudaFuncAttributeMaxDynamicSharedMemorySize, SMEM2);
    cudaFuncSetAttribute(k_emb, cudaFuncAttributeMaxDynamicSharedMemorySize, SMEM3);

    k_zero<<<2048, 256>>>();
    k_pre<<<1, 256>>>(ew2, eb2);
    k_prew<<<128, 256>>>(gwih, gwhh);
    k_msg<<<(E + 127) / 128, 256, SMEM1>>>(src, dst, ef, ts, mem, tw, tb,
                                           mw1, mb1, mw2, mb2, E);
    k_gru<<<N_NODES / 32, 256, SMEM2>>>(mem, gbih, gbhh);
    k_emb<<<(E + 127) / 128, 256, SMEM3>>>(src, dst, sf, df,
                                           ew1, eb1, out, E);
}

// round 6
// speedup vs baseline: 2.6993x; 1.3480x over previous
#include <cuda_runtime.h>
#include <stdint.h>
#include <math.h>

#define N_NODES 100000
#define MEM_DIM 128
#define MSG_DIM 128

// ---------------- scratch (static device globals; no allocation) ----------------
__device__ float g_aggr[(size_t)N_NODES * MSG_DIM];
__device__ float g_cnt[N_NODES];
__device__ float g_newmem[(size_t)N_NODES * MEM_DIM];
__device__ float g_M[64 * 64];     // W2 @ W2^T (symmetric)
__device__ float g_v[64];          // W2 @ b2
__device__ float g_c0;             // b2.b2
__device__ float g_Wrz[256 * 256]; // transposed GRU weights: r,z gates over [mm|mem]
__device__ float g_Win[128 * 128]; // Wih n-gate transposed
__device__ float g_Whn[128 * 128]; // Whh n-gate transposed

extern __shared__ float smem[];

// ---------------- tf32 helpers ----------------
__device__ __forceinline__ float to_tf32(float x) {
    unsigned int u;
    asm("cvt.rna.tf32.f32 %0, %1;" : "=r"(u) : "f"(x));
    return __uint_as_float(u);
}
__device__ __forceinline__ float4 to_tf32_4(float4 v) {
    v.x = to_tf32(v.x); v.y = to_tf32(v.y);
    v.z = to_tf32(v.z); v.w = to_tf32(v.w);
    return v;
}
__device__ __forceinline__ void mma_tf32(float4& c, const unsigned int a[4], const unsigned int b[2]) {
    asm volatile(
        "mma.sync.aligned.m16n8k8.row.col.f32.tf32.tf32.f32 "
        "{%0,%1,%2,%3},{%4,%5,%6,%7},{%8,%9},{%0,%1,%2,%3};\n"
        : "+f"(c.x), "+f"(c.y), "+f"(c.z), "+f"(c.w)
        : "r"(a[0]), "r"(a[1]), "r"(a[2]), "r"(a[3]), "r"(b[0]), "r"(b[1]));
}

// ---------------- K0: zero aggregation buffers ----------------
__global__ void k_zero() {
    size_t stride = (size_t)gridDim.x * blockDim.x;
    size_t tid0 = (size_t)blockIdx.x * blockDim.x + threadIdx.x;
    size_t tot4 = (size_t)N_NODES * MSG_DIM / 4;
    float4 z = make_float4(0.f, 0.f, 0.f, 0.f);
    for (size_t i = tid0; i < tot4; i += stride) ((float4*)g_aggr)[i] = z;
    for (size_t i = tid0; i < N_NODES; i += stride) g_cnt[i] = 0.f;
}

// ---------------- K-pre: bilinear precompute for emb ----------------
__global__ void k_pre(const float* __restrict__ W2, const float* __restrict__ b2) {
    __shared__ float sW2[64 * 64];
    __shared__ float sb2[64];
    int tid = threadIdx.x;
    for (int i = tid; i < 64 * 64; i += 256) sW2[i] = W2[i];
    if (tid < 64) sb2[tid] = b2[tid];
    __syncthreads();
    for (int p = tid; p < 64 * 64; p += 256) {
        int j = p >> 6, k = p & 63;
        float s = 0.f;
        #pragma unroll 16
        for (int c = 0; c < 64; c++) s = fmaf(sW2[j * 64 + c], sW2[k * 64 + c], s);
        g_M[p] = s;
    }
    if (tid < 64) {
        float s = 0.f;
        #pragma unroll 16
        for (int c = 0; c < 64; c++) s = fmaf(sW2[tid * 64 + c], sb2[c], s);
        g_v[tid] = s;
    }
    if (tid == 0) {
        float s = 0.f;
        for (int c = 0; c < 64; c++) s = fmaf(sb2[c], sb2[c], s);
        g_c0 = s;
    }
}

// ---------------- K-prew: transpose GRU weights ----------------
__global__ void k_prew(const float* __restrict__ Wih, const float* __restrict__ Whh) {
    int stride = gridDim.x * blockDim.x;
    int idx = blockIdx.x * blockDim.x + threadIdx.x;
    for (int p = idx; p < 256 * 256; p += stride) {
        int k = p >> 8, c = p & 255;
        int gate = c >> 7;
        int j = c & 127;
        float w = (k < 128) ? Wih[(size_t)(gate * 128 + j) * 128 + k]
                            : Whh[(size_t)(gate * 128 + j) * 128 + (k - 128)];
        g_Wrz[p] = w;
    }
    for (int p = idx; p < 128 * 128; p += stride) {
        int k = p >> 7, j = p & 127;
        g_Win[p] = Wih[(size_t)(256 + j) * 128 + k];
        g_Whn[p] = Whh[(size_t)(256 + j) * 128 + k];
    }
}

// ---------------- helpers for k_emb (fp32 path) ----------------
__device__ __forceinline__ void stage_w64(const float* __restrict__ Wg, int row0,
                                          float* sW, int tid) {
    const float4* wsrc = (const float4*)(Wg + (size_t)row0 * 64);
    #pragma unroll
    for (int it = 0; it < 2; it++)
        ((float4*)sW)[tid + 256 * it] = __ldg(wsrc + tid + 256 * it);
}
__device__ __forceinline__ void stage_a_gather32(const float* __restrict__ base,
                                                 const int* sN, int nE, int q0,
                                                 float* sA, int tid) {
    #pragma unroll
    for (int it = 0; it < 4; it++) {
        int idx = tid + 256 * it;
        int e = idx >> 3, q = idx & 7;
        float4 v = make_float4(0.f, 0.f, 0.f, 0.f);
        if (e < nE) v = __ldg((const float4*)(base + (size_t)sN[e] * 128) + q0 + q);
        ((float4*)sA)[idx] = v;
    }
}
__device__ __forceinline__ void mm64(const float* sA_, const float* sW_,
                                     int tx, int ty, float4 acc[8]) {
    #pragma unroll 16
    for (int kk = 0; kk < 32; kk++) {
        float4 w = ((const float4*)sW_)[kk * 16 + tx];
        #pragma unroll
        for (int i = 0; i < 8; i++) {
            float a = sA_[(i * 16 + ty) * 32 + kk];
            acc[i].x = fmaf(a, w.x, acc[i].x);
            acc[i].y = fmaf(a, w.y, acc[i].y);
            acc[i].z = fmaf(a, w.z, acc[i].z);
            acc[i].w = fmaf(a, w.w, acc[i].w);
        }
    }
}

// ======================= K1: message MLP via tf32 MMA (128 edges/block) ===========
// smem: sU[128*132] (H / msg buffer; sA[128*36]+sW[32*136] alias inside during GEMM1)
//       sW2[32*136], sN[256]
// Warps: 2x4 grid, warp tile 64(M) x 32(N); mma m16n8k8 tf32.
__global__ __launch_bounds__(256, 2) void k_msg(
    const int* __restrict__ src, const int* __restrict__ dst,
    const float* __restrict__ ef, const float* __restrict__ ts,
    const float* __restrict__ memory,
    const float* __restrict__ tw, const float* __restrict__ tb,
    const float* __restrict__ W1, const float* __restrict__ b1,
    const float* __restrict__ W2, const float* __restrict__ b2,
    int E)
{
    float* sU  = smem;                 // 128*132
    float* sA  = sU;                   // 128*36  (GEMM1)
    float* sW  = sU + 128 * 36;        // 32*136  (GEMM1)
    float* sW2 = smem + 128 * 132;     // 32*136
    int*   sN  = (int*)(sW2 + 32 * 136);

    const int tid  = threadIdx.x;
    const int lane = tid & 31;
    const int wid  = tid >> 5;
    const int wm   = wid >> 2;         // 0..1
    const int wn   = wid & 3;          // 0..3
    const int grp  = lane >> 2;        // 0..7
    const int thr  = lane & 3;         // 0..3
    const int e0 = blockIdx.x * 128;
    const int nE = min(128, E - e0);

    if (tid < 128) sN[tid] = (tid < nE) ? src[e0 + tid] : 0;
    else           sN[tid] = (tid - 128 < nE) ? dst[e0 + tid - 128] : 0;
    __syncthreads();

    float4 acc[4][4];
    #pragma unroll
    for (int mt = 0; mt < 4; mt++)
        #pragma unroll
        for (int nt = 0; nt < 4; nt++) acc[mt][nt] = make_float4(0.f, 0.f, 0.f, 0.f);

    // -------- GEMM1: K=320 in 10 chunks of 32 --------
    #pragma unroll 1
    for (int kc = 0; kc < 10; kc++) {
        // stage A chunk (128 x 32, stride 36, tf32)
        if (kc < 8) {
            const int* nodes = (kc < 4) ? sN : sN + 128;
            int q0 = (kc & 3) * 8;
            #pragma unroll
            for (int it = 0; it < 4; it++) {
                int idx = tid + 256 * it;
                int e = idx >> 3, q = idx & 7;
                float4 v = make_float4(0.f, 0.f, 0.f, 0.f);
                if (e < nE) v = __ldg((const float4*)(memory + (size_t)nodes[e] * 128) + q0 + q);
                ((float4*)sA)[e * 9 + q] = to_tf32_4(v);
            }
        } else if (kc == 8) {
            #pragma unroll
            for (int it = 0; it < 4; it++) {
                int idx = tid + 256 * it;
                int e = idx >> 3, q = idx & 7;
                float4 v = make_float4(0.f, 0.f, 0.f, 0.f);
                if (e < nE) v = __ldg((const float4*)(ef + (size_t)(e0 + e) * 32) + q);
                ((float4*)sA)[e * 9 + q] = to_tf32_4(v);
            }
        } else {
            for (int it = 0; it < 16; it++) {
                int idx = tid + 256 * it;
                int e = idx >> 5, c = idx & 31;
                float t = 0.f;
                if (e < nE) t = cosf(ts[e0 + e] * __ldg(tw + c) + __ldg(tb + c));
                sA[e * 36 + c] = to_tf32(t);
            }
        }
        // stage W chunk (32 x 128, stride 136, tf32)
        {
            const float4* wsrc = (const float4*)(W1 + (size_t)kc * 32 * 128);
            #pragma unroll
            for (int it = 0; it < 4; it++) {
                int idx = tid + 256 * it;
                int r = idx >> 5, c = idx & 31;
                ((float4*)sW)[r * 34 + c] = to_tf32_4(__ldg(wsrc + idx));
            }
        }
        __syncthreads();
        // compute: 4 k-steps of 8
        #pragma unroll
        for (int ks = 0; ks < 4; ks++) {
            unsigned int a[4][4], b[4][2];
            #pragma unroll
            for (int mt = 0; mt < 4; mt++) {
                int r0 = (wm * 64 + mt * 16 + grp) * 36 + ks * 8 + thr;
                int r1 = r0 + 8 * 36;
                a[mt][0] = __float_as_uint(sA[r0]);
                a[mt][1] = __float_as_uint(sA[r1]);
                a[mt][2] = __float_as_uint(sA[r0 + 4]);
                a[mt][3] = __float_as_uint(sA[r1 + 4]);
            }
            #pragma unroll
            for (int nt = 0; nt < 4; nt++) {
                int col = wn * 32 + nt * 8 + grp;
                b[nt][0] = __float_as_uint(sW[(ks * 8 + thr) * 136 + col]);
                b[nt][1] = __float_as_uint(sW[(ks * 8 + thr + 4) * 136 + col]);
            }
            #pragma unroll
            for (int mt = 0; mt < 4; mt++)
                #pragma unroll
                for (int nt = 0; nt < 4; nt++)
                    mma_tf32(acc[mt][nt], a[mt], b[nt]);
        }
        __syncthreads();
    }

    // -------- bias + relu -> H in sU (stride 132, tf32) --------
    {
        float bc0[4], bc1[4];
        #pragma unroll
        for (int nt = 0; nt < 4; nt++) {
            int col = wn * 32 + nt * 8 + 2 * thr;
            bc0[nt] = __ldg(b1 + col);
            bc1[nt] = __ldg(b1 + col + 1);
        }
        #pragma unroll
        for (int mt = 0; mt < 4; mt++) {
            int r0 = wm * 64 + mt * 16 + grp;
            #pragma unroll
            for (int nt = 0; nt < 4; nt++) {
                int col = wn * 32 + nt * 8 + 2 * thr;
                sU[r0 * 132 + col]           = to_tf32(fmaxf(acc[mt][nt].x + bc0[nt], 0.f));
                sU[r0 * 132 + col + 1]       = to_tf32(fmaxf(acc[mt][nt].y + bc1[nt], 0.f));
                sU[(r0 + 8) * 132 + col]     = to_tf32(fmaxf(acc[mt][nt].z + bc0[nt], 0.f));
                sU[(r0 + 8) * 132 + col + 1] = to_tf32(fmaxf(acc[mt][nt].w + bc1[nt], 0.f));
                acc[mt][nt] = make_float4(0.f, 0.f, 0.f, 0.f);
            }
        }
    }

    // -------- GEMM2: K=128 in 4 chunks --------
    #pragma unroll 1
    for (int kc = 0; kc < 4; kc++) {
        __syncthreads();
        {
            const float4* wsrc = (const float4*)(W2 + (size_t)kc * 32 * 128);
            #pragma unroll
            for (int it = 0; it < 4; it++) {
                int idx = tid + 256 * it;
                int r = idx >> 5, c = idx & 31;
                ((float4*)sW2)[r * 34 + c] = to_tf32_4(__ldg(wsrc + idx));
            }
        }
        __syncthreads();
        #pragma unroll
        for (int ks = 0; ks < 4; ks++) {
            unsigned int a[4][4], b[4][2];
            int kbase = kc * 32 + ks * 8;
            #pragma unroll
            for (int mt = 0; mt < 4; mt++) {
                int r0 = (wm * 64 + mt * 16 + grp) * 132 + kbase + thr;
                int r1 = r0 + 8 * 132;
                a[mt][0] = __float_as_uint(sU[r0]);
                a[mt][1] = __float_as_uint(sU[r1]);
                a[mt][2] = __float_as_uint(sU[r0 + 4]);
                a[mt][3] = __float_as_uint(sU[r1 + 4]);
            }
            #pragma unroll
            for (int nt = 0; nt < 4; nt++) {
                int col = wn * 32 + nt * 8 + grp;
                b[nt][0] = __float_as_uint(sW2[(ks * 8 + thr) * 136 + col]);
                b[nt][1] = __float_as_uint(sW2[(ks * 8 + thr + 4) * 136 + col]);
            }
            #pragma unroll
            for (int mt = 0; mt < 4; mt++)
                #pragma unroll
                for (int nt = 0; nt < 4; nt++)
                    mma_tf32(acc[mt][nt], a[mt], b[nt]);
        }
    }
    __syncthreads();

    // -------- msg (+b2) -> sU, then float4 scatter --------
    {
        float bc0[4], bc1[4];
        #pragma unroll
        for (int nt = 0; nt < 4; nt++) {
            int col = wn * 32 + nt * 8 + 2 * thr;
            bc0[nt] = __ldg(b2 + col);
            bc1[nt] = __ldg(b2 + col + 1);
        }
        #pragma unroll
        for (int mt = 0; mt < 4; mt++) {
            int r0 = wm * 64 + mt * 16 + grp;
            #pragma unroll
            for (int nt = 0; nt < 4; nt++) {
                int col = wn * 32 + nt * 8 + 2 * thr;
                sU[r0 * 132 + col]           = acc[mt][nt].x + bc0[nt];
                sU[r0 * 132 + col + 1]       = acc[mt][nt].y + bc1[nt];
                sU[(r0 + 8) * 132 + col]     = acc[mt][nt].z + bc0[nt];
                sU[(r0 + 8) * 132 + col + 1] = acc[mt][nt].w + bc1[nt];
            }
        }
    }
    __syncthreads();

    {
        const int tx = tid & 15, ty = tid >> 4;
        #pragma unroll
        for (int i = 0; i < 8; i++) {
            int e = i * 16 + ty;
            if (e < nE) {
                float4 v0 = ((const float4*)(sU + e * 132))[tx];
                float4 v1 = ((const float4*)(sU + e * 132))[16 + tx];
                int ns = sN[e], nd = sN[128 + e];
                atomicAdd((float4*)(g_aggr + (size_t)ns * 128) + tx, v0);
                atomicAdd((float4*)(g_aggr + (size_t)ns * 128) + 16 + tx, v1);
                atomicAdd((float4*)(g_aggr + (size_t)nd * 128) + tx, v0);
                atomicAdd((float4*)(g_aggr + (size_t)nd * 128) + 16 + tx, v1);
            }
        }
    }
    if (tid < nE) {
        atomicAdd(&g_cnt[sN[tid]], 1.f);
        atomicAdd(&g_cnt[sN[128 + tid]], 1.f);
    }
}

// ======================= K2: GRU as GEMM over transposed weights ==================
__device__ __forceinline__ void gru_chunk(
    const float* sIn, const float* sWrz, const float* sWn, int k0,
    int tx, int ty, float4 accRZ[2][4], float4 accN[2][2])
{
    #pragma unroll 8
    for (int kk = 0; kk < 32; kk++) {
        float4 wrz[4], wn[2];
        #pragma unroll
        for (int m = 0; m < 4; m++) wrz[m] = ((const float4*)sWrz)[kk * 64 + m * 16 + tx];
        #pragma unroll
        for (int m = 0; m < 2; m++) wn[m] = ((const float4*)sWn)[kk * 32 + m * 16 + tx];
        #pragma unroll
        for (int i = 0; i < 2; i++) {
            float a = sIn[(i * 16 + ty) * 256 + k0 + kk];
            #pragma unroll
            for (int m = 0; m < 4; m++) {
                accRZ[i][m].x = fmaf(a, wrz[m].x, accRZ[i][m].x);
                accRZ[i][m].y = fmaf(a, wrz[m].y, accRZ[i][m].y);
                accRZ[i][m].z = fmaf(a, wrz[m].z, accRZ[i][m].z);
                accRZ[i][m].w = fmaf(a, wrz[m].w, accRZ[i][m].w);
            }
            #pragma unroll
            for (int m = 0; m < 2; m++) {
                accN[i][m].x = fmaf(a, wn[m].x, accN[i][m].x);
                accN[i][m].y = fmaf(a, wn[m].y, accN[i][m].y);
                accN[i][m].z = fmaf(a, wn[m].z, accN[i][m].z);
                accN[i][m].w = fmaf(a, wn[m].w, accN[i][m].w);
            }
        }
    }
}

__global__ __launch_bounds__(256, 2) void k_gru(
    const float* __restrict__ memory,
    const float* __restrict__ bih, const float* __restrict__ bhh)
{
    float* sIn  = smem;
    float* sWrz = sIn + 32 * 256;
    float* sWn  = sWrz + 32 * 256;
    float* sCnt = sWn + 32 * 128;

    const int tid = threadIdx.x;
    const int n0 = blockIdx.x * 32;
    const int tx = tid & 15, ty = tid >> 4;

    if (tid < 32) sCnt[tid] = g_cnt[n0 + tid];
    __syncthreads();

    #pragma unroll
    for (int it = 0; it < 8; it++) {
        int idx = tid + 256 * it;
        int n = idx >> 6, q = idx & 63;
        float4 v;
        if (q < 32) {
            float cnt = sCnt[n];
            v = *((const float4*)(g_aggr + (size_t)(n0 + n) * 128) + q);
            float inv = (cnt > 0.f) ? (1.f / cnt) : 0.f;
            v.x *= inv; v.y *= inv; v.z *= inv; v.w *= inv;
        } else {
            v = __ldg((const float4*)(memory + (size_t)(n0 + n) * 128) + (q - 32));
        }
        ((float4*)sIn)[idx] = v;
    }

    float4 accRZ[2][4], accIN[2][2], accHN[2][2];
    #pragma unroll
    for (int i = 0; i < 2; i++) {
        #pragma unroll
        for (int m = 0; m < 4; m++) accRZ[i][m] = make_float4(0.f, 0.f, 0.f, 0.f);
        #pragma unroll
        for (int m = 0; m < 2; m++) {
            accIN[i][m] = make_float4(0.f, 0.f, 0.f, 0.f);
            accHN[i][m] = make_float4(0.f, 0.f, 0.f, 0.f);
        }
    }

    #pragma unroll 1
    for (int kc = 0; kc < 4; kc++) {
        __syncthreads();
        {
            const float4* wsrc = (const float4*)(g_Wrz + (size_t)kc * 32 * 256);
            #pragma unroll
            for (int it = 0; it < 8; it++)
                ((float4*)sWrz)[tid + 256 * it] = wsrc[tid + 256 * it];
            const float4* nsrc = (const float4*)(g_Win + (size_t)kc * 32 * 128);
            #pragma unroll
            for (int it = 0; it < 4; it++)
                ((float4*)sWn)[tid + 256 * it] = nsrc[tid + 256 * it];
        }
        __syncthreads();
        gru_chunk(sIn, sWrz, sWn, kc * 32, tx, ty, accRZ, accIN);
    }
    #pragma unroll 1
    for (int kc = 4; kc < 8; kc++) {
        __syncthreads();
        {
            const float4* wsrc = (const float4*)(g_Wrz + (size_t)kc * 32 * 256);
            #pragma unroll
            for (int it = 0; it < 8; it++)
                ((float4*)sWrz)[tid + 256 * it] = wsrc[tid + 256 * it];
            const float4* nsrc = (const float4*)(g_Whn + (size_t)(kc - 4) * 32 * 128);
            #pragma unroll
            for (int it = 0; it < 4; it++)
                ((float4*)sWn)[tid + 256 * it] = nsrc[tid + 256 * it];
        }
        __syncthreads();
        gru_chunk(sIn, sWrz, sWn, kc * 32, tx, ty, accRZ, accHN);
    }

    #pragma unroll
    for (int i = 0; i < 2; i++) {
        int row = i * 16 + ty;
        float cnt = sCnt[row];
        #pragma unroll
        for (int m = 0; m < 2; m++) {
            int f4idx = m * 16 + tx;
            float4 bir = __ldg((const float4*)bih + f4idx);
            float4 bhr = __ldg((const float4*)bhh + f4idx);
            float4 biz = __ldg((const float4*)bih + 32 + f4idx);
            float4 bhz = __ldg((const float4*)bhh + 32 + f4idx);
            float4 bin = __ldg((const float4*)bih + 64 + f4idx);
            float4 bhn = __ldg((const float4*)bhh + 64 + f4idx);
            float4 mv = ((const float4*)sIn)[row * 64 + 32 + f4idx];

            float4 r, z, nn, res;
            r.x = 1.f / (1.f + expf(-(accRZ[i][m].x + bir.x + bhr.x)));
            r.y = 1.f / (1.f + expf(-(accRZ[i][m].y + bir.y + bhr.y)));
            r.z = 1.f / (1.f + expf(-(accRZ[i][m].z + bir.z + bhr.z)));
            r.w = 1.f / (1.f + expf(-(accRZ[i][m].w + bir.w + bhr.w)));
            z.x = 1.f / (1.f + expf(-(accRZ[i][m + 2].x + biz.x + bhz.x)));
            z.y = 1.f / (1.f + expf(-(accRZ[i][m + 2].y + biz.y + bhz.y)));
            z.z = 1.f / (1.f + expf(-(accRZ[i][m + 2].z + biz.z + bhz.z)));
            z.w = 1.f / (1.f + expf(-(accRZ[i][m + 2].w + biz.w + bhz.w)));
            nn.x = tanhf(accIN[i][m].x + bin.x + r.x * (accHN[i][m].x + bhn.x));
            nn.y = tanhf(accIN[i][m].y + bin.y + r.y * (accHN[i][m].y + bhn.y));
            nn.z = tanhf(accIN[i][m].z + bin.z + r.z * (accHN[i][m].z + bhn.z));
            nn.w = tanhf(accIN[i][m].w + bin.w + r.w * (accHN[i][m].w + bhn.w));
            res.x = (cnt > 0.f) ? ((1.f - z.x) * nn.x + z.x * mv.x) : mv.x;
            res.y = (cnt > 0.f) ? ((1.f - z.y) * nn.y + z.y * mv.y) : mv.y;
            res.z = (cnt > 0.f) ? ((1.f - z.z) * nn.z + z.z * mv.z) : mv.z;
            res.w = (cnt > 0.f) ? ((1.f - z.w) * nn.w + z.w * mv.w) : mv.w;
            ((float4*)(g_newmem + (size_t)(n0 + row) * 128))[f4idx] = res;
        }
    }
}

// ======================= K3: embeddings + bilinear dot (128 edges/block) ==========
__global__ __launch_bounds__(256, 2) void k_emb(
    const int* __restrict__ src, const int* __restrict__ dst,
    const float* __restrict__ sf, const float* __restrict__ df,
    const float* __restrict__ W1, const float* __restrict__ b1,
    float* __restrict__ out, int E)
{
    float* sA  = smem;                  // 128*32
    float* sW  = sA + 128 * 32;         // 32*64
    float* sHs = sW + 32 * 64;          // 128*64
    float* sHd = sHs + 128 * 64;        // 128*64
    float* sM  = sHd + 128 * 64;        // 64*64
    float* sv  = sM + 64 * 64;          // 64
    int*   sN  = (int*)(sv + 64);       // 128

    const int tid = threadIdx.x;
    const int e0 = blockIdx.x * 128;
    const int nE = min(128, E - e0);
    const int tx = tid & 15, ty = tid >> 4;

    #pragma unroll
    for (int it = 0; it < 4; it++)
        ((float4*)sM)[tid + 256 * it] = ((const float4*)g_M)[tid + 256 * it];
    if (tid < 16) ((float4*)sv)[tid] = ((const float4*)g_v)[tid];

    const float4 b1v = __ldg((const float4*)b1 + tx);

    #pragma unroll 1
    for (int side = 0; side < 2; side++) {
        const int* nodes = side ? dst : src;
        const float* feats = side ? df : sf;
        float* sH = side ? sHd : sHs;
        __syncthreads();
        if (tid < 128) sN[tid] = (tid < nE) ? nodes[e0 + tid] : 0;
        __syncthreads();

        float4 acc[8];
        #pragma unroll
        for (int i = 0; i < 8; i++) acc[i] = make_float4(0.f, 0.f, 0.f, 0.f);

        #pragma unroll 1
        for (int kc = 0; kc < 4; kc++) {
            stage_a_gather32(g_newmem, sN, nE, kc * 8, sA, tid);
            stage_w64(W1, kc * 32, sW, tid);
            __syncthreads();
            mm64(sA, sW, tx, ty, acc);
            __syncthreads();
        }
        #pragma unroll 1
        for (int fc = 0; fc < 2; fc++) {
            #pragma unroll
            for (int it = 0; it < 4; it++) {
                int idx = tid + 256 * it;
                int e = idx >> 3, q = idx & 7;
                float4 v = make_float4(0.f, 0.f, 0.f, 0.f);
                if (e < nE) v = __ldg((const float4*)(feats + (size_t)(e0 + e) * 64) + fc * 8 + q);
                ((float4*)sA)[idx] = v;
            }
            stage_w64(W1, 128 + fc * 32, sW, tid);
            __syncthreads();
            mm64(sA, sW, tx, ty, acc);
            if (fc == 0) __syncthreads();
        }

        #pragma unroll
        for (int i = 0; i < 8; i++) {
            int row = i * 16 + ty;
            float4 h;
            h.x = fmaxf(acc[i].x + b1v.x, 0.f);
            h.y = fmaxf(acc[i].y + b1v.y, 0.f);
            h.z = fmaxf(acc[i].z + b1v.z, 0.f);
            h.w = fmaxf(acc[i].w + b1v.w, 0.f);
            ((float4*)(sH + row * 64))[tx] = h;
        }
    }
    __syncthreads();

    float4 t[8];
    #pragma unroll
    for (int i = 0; i < 8; i++) t[i] = make_float4(0.f, 0.f, 0.f, 0.f);
    #pragma unroll 8
    for (int kk = 0; kk < 64; kk++) {
        float4 m = ((const float4*)sM)[kk * 16 + tx];
        #pragma unroll
        for (int i = 0; i < 8; i++) {
            float a = sHd[(i * 16 + ty) * 64 + kk];
            t[i].x = fmaf(a, m.x, t[i].x);
            t[i].y = fmaf(a, m.y, t[i].y);
            t[i].z = fmaf(a, m.z, t[i].z);
            t[i].w = fmaf(a, m.w, t[i].w);
        }
    }

    float c0 = g_c0;
    float4 vv = ((const float4*)sv)[tx];
    float p[8];
    #pragma unroll
    for (int i = 0; i < 8; i++) {
        int row = i * 16 + ty;
        float4 hs = ((const float4*)(sHs + row * 64))[tx];
        float4 hd = ((const float4*)(sHd + row * 64))[tx];
        p[i] = hs.x * t[i].x + hs.y * t[i].y + hs.z * t[i].z + hs.w * t[i].w
             + (hs.x + hd.x) * vv.x + (hs.y + hd.y) * vv.y
             + (hs.z + hd.z) * vv.z + (hs.w + hd.w) * vv.w;
    }
    #pragma unroll
    for (int m = 1; m < 16; m <<= 1)
        #pragma unroll
        for (int i = 0; i < 8; i++)
            p[i] += __shfl_xor_sync(0xffffffffu, p[i], m);
    if (tx == 0) {
        #pragma unroll
        for (int i = 0; i < 8; i++) {
            int e = i * 16 + ty;
            if (e < nE) out[e0 + e] = p[i] + c0;
        }
    }
}

// ---------------- host launch ----------------
extern "C" void kernel_launch(void* const* d_in, const int* in_sizes, int n_in,
                              void* d_out, int out_size)
{
    const int*   src   = (const int*)d_in[0];
    const int*   dst   = (const int*)d_in[1];
    const float* ef    = (const float*)d_in[2];
    const float* ts    = (const float*)d_in[3];
    const float* sf    = (const float*)d_in[4];
    const float* df    = (const float*)d_in[5];
    const float* mem   = (const float*)d_in[6];
    const float* tw    = (const float*)d_in[7];
    const float* tb    = (const float*)d_in[8];
    const float* mw1   = (const float*)d_in[9];
    const float* mb1   = (const float*)d_in[10];
    const float* mw2   = (const float*)d_in[11];
    const float* mb2   = (const float*)d_in[12];
    const float* gwih  = (const float*)d_in[13];
    const float* gwhh  = (const float*)d_in[14];
    const float* gbih  = (const float*)d_in[15];
    const float* gbhh  = (const float*)d_in[16];
    const float* ew1   = (const float*)d_in[17];
    const float* eb1   = (const float*)d_in[18];
    const float* ew2   = (const float*)d_in[19];
    const float* eb2   = (const float*)d_in[20];
    float* out = (float*)d_out;

    const int E = in_sizes[0];

    const int SMEM1 = (128 * 132 + 32 * 136) * 4 + 256 * 4;                  // ~86KB
    const int SMEM2 = (32 * 256 + 32 * 256 + 32 * 128 + 32) * 4;             // ~82KB
    const int SMEM3 = (128 * 32 + 32 * 64 + 2 * 128 * 64 + 64 * 64 + 64) * 4 + 128 * 4;

    cudaFuncSetAttribute(k_msg, cudaFuncAttributeMaxDynamicSharedMemorySize, SMEM1);
    cudaFuncSetAttribute(k_gru, cudaFuncAttributeMaxDynamicSharedMemorySize, SMEM2);
    cudaFuncSetAttribute(k_emb, cudaFuncAttributeMaxDynamicSharedMemorySize, SMEM3);

    k_zero<<<2048, 256>>>();
    k_pre<<<1, 256>>>(ew2, eb2);
    k_prew<<<128, 256>>>(gwih, gwhh);
    k_msg<<<(E + 127) / 128, 256, SMEM1>>>(src, dst, ef, ts, mem, tw, tb,
                                           mw1, mb1, mw2, mb2, E);
    k_gru<<<N_NODES / 32, 256, SMEM2>>>(mem, gbih, gbhh);
    k_emb<<<(E + 127) / 128, 256, SMEM3>>>(src, dst, sf, df,
                                           ew1, eb1, out, E);
}

// round 7
// speedup vs baseline: 3.1030x; 1.1495x over previous
#include <cuda_runtime.h>
#include <stdint.h>
#include <math.h>

#define N_NODES 100000
#define MEM_DIM 128
#define MSG_DIM 128

// ---------------- scratch (static device globals; no allocation) ----------------
__device__ float g_aggr[(size_t)N_NODES * MSG_DIM];
__device__ float g_cnt[N_NODES];
__device__ float g_newmem[(size_t)N_NODES * MEM_DIM];
__device__ float g_M[64 * 64];     // W2 @ W2^T (symmetric)
__device__ float g_v[64];          // W2 @ b2
__device__ float g_c0;             // b2.b2
__device__ float g_Wrz[256 * 256]; // transposed GRU weights: r,z gates over [mm|mem]
__device__ float g_Win[128 * 128]; // Wih n-gate transposed
__device__ float g_Whn[128 * 128]; // Whh n-gate transposed

extern __shared__ float smem[];

// ---------------- tf32 helpers ----------------
__device__ __forceinline__ float to_tf32(float x) {
    unsigned int u;
    asm("cvt.rna.tf32.f32 %0, %1;" : "=r"(u) : "f"(x));
    return __uint_as_float(u);
}
__device__ __forceinline__ float4 to_tf32_4(float4 v) {
    v.x = to_tf32(v.x); v.y = to_tf32(v.y);
    v.z = to_tf32(v.z); v.w = to_tf32(v.w);
    return v;
}
__device__ __forceinline__ void mma_tf32(float4& c, const unsigned int a[4], const unsigned int b[2]) {
    asm volatile(
        "mma.sync.aligned.m16n8k8.row.col.f32.tf32.tf32.f32 "
        "{%0,%1,%2,%3},{%4,%5,%6,%7},{%8,%9},{%0,%1,%2,%3};\n"
        : "+f"(c.x), "+f"(c.y), "+f"(c.z), "+f"(c.w)
        : "r"(a[0]), "r"(a[1]), "r"(a[2]), "r"(a[3]), "r"(b[0]), "r"(b[1]));
}

// ---------------- K0: zero aggregation buffers ----------------
__global__ void k_zero() {
    size_t stride = (size_t)gridDim.x * blockDim.x;
    size_t tid0 = (size_t)blockIdx.x * blockDim.x + threadIdx.x;
    size_t tot4 = (size_t)N_NODES * MSG_DIM / 4;
    float4 z = make_float4(0.f, 0.f, 0.f, 0.f);
    for (size_t i = tid0; i < tot4; i += stride) ((float4*)g_aggr)[i] = z;
    for (size_t i = tid0; i < N_NODES; i += stride) g_cnt[i] = 0.f;
}

// ---------------- K-pre: bilinear precompute for emb ----------------
__global__ void k_pre(const float* __restrict__ W2, const float* __restrict__ b2) {
    __shared__ float sW2[64 * 64];
    __shared__ float sb2[64];
    int tid = threadIdx.x;
    for (int i = tid; i < 64 * 64; i += 256) sW2[i] = W2[i];
    if (tid < 64) sb2[tid] = b2[tid];
    __syncthreads();
    for (int p = tid; p < 64 * 64; p += 256) {
        int j = p >> 6, k = p & 63;
        float s = 0.f;
        #pragma unroll 16
        for (int c = 0; c < 64; c++) s = fmaf(sW2[j * 64 + c], sW2[k * 64 + c], s);
        g_M[p] = s;
    }
    if (tid < 64) {
        float s = 0.f;
        #pragma unroll 16
        for (int c = 0; c < 64; c++) s = fmaf(sW2[tid * 64 + c], sb2[c], s);
        g_v[tid] = s;
    }
    if (tid == 0) {
        float s = 0.f;
        for (int c = 0; c < 64; c++) s = fmaf(sb2[c], sb2[c], s);
        g_c0 = s;
    }
}

// ---------------- K-prew: transpose GRU weights ----------------
__global__ void k_prew(const float* __restrict__ Wih, const float* __restrict__ Whh) {
    int stride = gridDim.x * blockDim.x;
    int idx = blockIdx.x * blockDim.x + threadIdx.x;
    for (int p = idx; p < 256 * 256; p += stride) {
        int k = p >> 8, c = p & 255;
        int gate = c >> 7;
        int j = c & 127;
        float w = (k < 128) ? Wih[(size_t)(gate * 128 + j) * 128 + k]
                            : Whh[(size_t)(gate * 128 + j) * 128 + (k - 128)];
        g_Wrz[p] = w;
    }
    for (int p = idx; p < 128 * 128; p += stride) {
        int k = p >> 7, j = p & 127;
        g_Win[p] = Wih[(size_t)(256 + j) * 128 + k];
        g_Whn[p] = Whh[(size_t)(256 + j) * 128 + k];
    }
}

// ======================= K1: message MLP via tf32 MMA (128 edges/block) ===========
__global__ __launch_bounds__(256, 2) void k_msg(
    const int* __restrict__ src, const int* __restrict__ dst,
    const float* __restrict__ ef, const float* __restrict__ ts,
    const float* __restrict__ memory,
    const float* __restrict__ tw, const float* __restrict__ tb,
    const float* __restrict__ W1, const float* __restrict__ b1,
    const float* __restrict__ W2, const float* __restrict__ b2,
    int E)
{
    float* sU  = smem;                 // 128*132
    float* sA  = sU;                   // 128*36  (GEMM1)
    float* sW  = sU + 128 * 36;        // 32*136  (GEMM1)
    float* sW2 = smem + 128 * 132;     // 32*136
    int*   sN  = (int*)(sW2 + 32 * 136);

    const int tid  = threadIdx.x;
    const int lane = tid & 31;
    const int wid  = tid >> 5;
    const int wm   = wid >> 2;         // 0..1
    const int wn   = wid & 3;          // 0..3
    const int grp  = lane >> 2;        // 0..7
    const int thr  = lane & 3;         // 0..3
    const int e0 = blockIdx.x * 128;
    const int nE = min(128, E - e0);

    if (tid < 128) sN[tid] = (tid < nE) ? src[e0 + tid] : 0;
    else           sN[tid] = (tid - 128 < nE) ? dst[e0 + tid - 128] : 0;
    __syncthreads();

    float4 acc[4][4];
    #pragma unroll
    for (int mt = 0; mt < 4; mt++)
        #pragma unroll
        for (int nt = 0; nt < 4; nt++) acc[mt][nt] = make_float4(0.f, 0.f, 0.f, 0.f);

    // -------- GEMM1: K=320 in 10 chunks of 32 --------
    #pragma unroll 1
    for (int kc = 0; kc < 10; kc++) {
        if (kc < 8) {
            const int* nodes = (kc < 4) ? sN : sN + 128;
            int q0 = (kc & 3) * 8;
            #pragma unroll
            for (int it = 0; it < 4; it++) {
                int idx = tid + 256 * it;
                int e = idx >> 3, q = idx & 7;
                float4 v = make_float4(0.f, 0.f, 0.f, 0.f);
                if (e < nE) v = __ldg((const float4*)(memory + (size_t)nodes[e] * 128) + q0 + q);
                ((float4*)sA)[e * 9 + q] = to_tf32_4(v);
            }
        } else if (kc == 8) {
            #pragma unroll
            for (int it = 0; it < 4; it++) {
                int idx = tid + 256 * it;
                int e = idx >> 3, q = idx & 7;
                float4 v = make_float4(0.f, 0.f, 0.f, 0.f);
                if (e < nE) v = __ldg((const float4*)(ef + (size_t)(e0 + e) * 32) + q);
                ((float4*)sA)[e * 9 + q] = to_tf32_4(v);
            }
        } else {
            for (int it = 0; it < 16; it++) {
                int idx = tid + 256 * it;
                int e = idx >> 5, c = idx & 31;
                float t = 0.f;
                if (e < nE) t = cosf(ts[e0 + e] * __ldg(tw + c) + __ldg(tb + c));
                sA[e * 36 + c] = to_tf32(t);
            }
        }
        {
            const float4* wsrc = (const float4*)(W1 + (size_t)kc * 32 * 128);
            #pragma unroll
            for (int it = 0; it < 4; it++) {
                int idx = tid + 256 * it;
                int r = idx >> 5, c = idx & 31;
                ((float4*)sW)[r * 34 + c] = to_tf32_4(__ldg(wsrc + idx));
            }
        }
        __syncthreads();
        #pragma unroll
        for (int ks = 0; ks < 4; ks++) {
            unsigned int a[4][4], b[4][2];
            #pragma unroll
            for (int mt = 0; mt < 4; mt++) {
                int r0 = (wm * 64 + mt * 16 + grp) * 36 + ks * 8 + thr;
                int r1 = r0 + 8 * 36;
                a[mt][0] = __float_as_uint(sA[r0]);
                a[mt][1] = __float_as_uint(sA[r1]);
                a[mt][2] = __float_as_uint(sA[r0 + 4]);
                a[mt][3] = __float_as_uint(sA[r1 + 4]);
            }
            #pragma unroll
            for (int nt = 0; nt < 4; nt++) {
                int col = wn * 32 + nt * 8 + grp;
                b[nt][0] = __float_as_uint(sW[(ks * 8 + thr) * 136 + col]);
                b[nt][1] = __float_as_uint(sW[(ks * 8 + thr + 4) * 136 + col]);
            }
            #pragma unroll
            for (int mt = 0; mt < 4; mt++)
                #pragma unroll
                for (int nt = 0; nt < 4; nt++)
                    mma_tf32(acc[mt][nt], a[mt], b[nt]);
        }
        __syncthreads();
    }

    // -------- bias + relu -> H in sU (stride 132, tf32) --------
    {
        float bc0[4], bc1[4];
        #pragma unroll
        for (int nt = 0; nt < 4; nt++) {
            int col = wn * 32 + nt * 8 + 2 * thr;
            bc0[nt] = __ldg(b1 + col);
            bc1[nt] = __ldg(b1 + col + 1);
        }
        #pragma unroll
        for (int mt = 0; mt < 4; mt++) {
            int r0 = wm * 64 + mt * 16 + grp;
            #pragma unroll
            for (int nt = 0; nt < 4; nt++) {
                int col = wn * 32 + nt * 8 + 2 * thr;
                sU[r0 * 132 + col]           = to_tf32(fmaxf(acc[mt][nt].x + bc0[nt], 0.f));
                sU[r0 * 132 + col + 1]       = to_tf32(fmaxf(acc[mt][nt].y + bc1[nt], 0.f));
                sU[(r0 + 8) * 132 + col]     = to_tf32(fmaxf(acc[mt][nt].z + bc0[nt], 0.f));
                sU[(r0 + 8) * 132 + col + 1] = to_tf32(fmaxf(acc[mt][nt].w + bc1[nt], 0.f));
                acc[mt][nt] = make_float4(0.f, 0.f, 0.f, 0.f);
            }
        }
    }

    // -------- GEMM2: K=128 in 4 chunks --------
    #pragma unroll 1
    for (int kc = 0; kc < 4; kc++) {
        __syncthreads();
        {
            const float4* wsrc = (const float4*)(W2 + (size_t)kc * 32 * 128);
            #pragma unroll
            for (int it = 0; it < 4; it++) {
                int idx = tid + 256 * it;
                int r = idx >> 5, c = idx & 31;
                ((float4*)sW2)[r * 34 + c] = to_tf32_4(__ldg(wsrc + idx));
            }
        }
        __syncthreads();
        #pragma unroll
        for (int ks = 0; ks < 4; ks++) {
            unsigned int a[4][4], b[4][2];
            int kbase = kc * 32 + ks * 8;
            #pragma unroll
            for (int mt = 0; mt < 4; mt++) {
                int r0 = (wm * 64 + mt * 16 + grp) * 132 + kbase + thr;
                int r1 = r0 + 8 * 132;
                a[mt][0] = __float_as_uint(sU[r0]);
                a[mt][1] = __float_as_uint(sU[r1]);
                a[mt][2] = __float_as_uint(sU[r0 + 4]);
                a[mt][3] = __float_as_uint(sU[r1 + 4]);
            }
            #pragma unroll
            for (int nt = 0; nt < 4; nt++) {
                int col = wn * 32 + nt * 8 + grp;
                b[nt][0] = __float_as_uint(sW2[(ks * 8 + thr) * 136 + col]);
                b[nt][1] = __float_as_uint(sW2[(ks * 8 + thr + 4) * 136 + col]);
            }
            #pragma unroll
            for (int mt = 0; mt < 4; mt++)
                #pragma unroll
                for (int nt = 0; nt < 4; nt++)
                    mma_tf32(acc[mt][nt], a[mt], b[nt]);
        }
    }
    __syncthreads();

    // -------- msg (+b2) -> sU, then float4 scatter --------
    {
        float bc0[4], bc1[4];
        #pragma unroll
        for (int nt = 0; nt < 4; nt++) {
            int col = wn * 32 + nt * 8 + 2 * thr;
            bc0[nt] = __ldg(b2 + col);
            bc1[nt] = __ldg(b2 + col + 1);
        }
        #pragma unroll
        for (int mt = 0; mt < 4; mt++) {
            int r0 = wm * 64 + mt * 16 + grp;
            #pragma unroll
            for (int nt = 0; nt < 4; nt++) {
                int col = wn * 32 + nt * 8 + 2 * thr;
                sU[r0 * 132 + col]           = acc[mt][nt].x + bc0[nt];
                sU[r0 * 132 + col + 1]       = acc[mt][nt].y + bc1[nt];
                sU[(r0 + 8) * 132 + col]     = acc[mt][nt].z + bc0[nt];
                sU[(r0 + 8) * 132 + col + 1] = acc[mt][nt].w + bc1[nt];
            }
        }
    }
    __syncthreads();

    {
        const int tx = tid & 15, ty = tid >> 4;
        #pragma unroll
        for (int i = 0; i < 8; i++) {
            int e = i * 16 + ty;
            if (e < nE) {
                float4 v0 = ((const float4*)(sU + e * 132))[tx];
                float4 v1 = ((const float4*)(sU + e * 132))[16 + tx];
                int ns = sN[e], nd = sN[128 + e];
                atomicAdd((float4*)(g_aggr + (size_t)ns * 128) + tx, v0);
                atomicAdd((float4*)(g_aggr + (size_t)ns * 128) + 16 + tx, v1);
                atomicAdd((float4*)(g_aggr + (size_t)nd * 128) + tx, v0);
                atomicAdd((float4*)(g_aggr + (size_t)nd * 128) + 16 + tx, v1);
            }
        }
    }
    if (tid < nE) {
        atomicAdd(&g_cnt[sN[tid]], 1.f);
        atomicAdd(&g_cnt[sN[128 + tid]], 1.f);
    }
}

// ======================= K2: GRU as GEMM over transposed weights ==================
__device__ __forceinline__ void gru_chunk(
    const float* sIn, const float* sWrz, const float* sWn, int k0,
    int tx, int ty, float4 accRZ[2][4], float4 accN[2][2])
{
    #pragma unroll 8
    for (int kk = 0; kk < 32; kk++) {
        float4 wrz[4], wn[2];
        #pragma unroll
        for (int m = 0; m < 4; m++) wrz[m] = ((const float4*)sWrz)[kk * 64 + m * 16 + tx];
        #pragma unroll
        for (int m = 0; m < 2; m++) wn[m] = ((const float4*)sWn)[kk * 32 + m * 16 + tx];
        #pragma unroll
        for (int i = 0; i < 2; i++) {
            float a = sIn[(i * 16 + ty) * 256 + k0 + kk];
            #pragma unroll
            for (int m = 0; m < 4; m++) {
                accRZ[i][m].x = fmaf(a, wrz[m].x, accRZ[i][m].x);
                accRZ[i][m].y = fmaf(a, wrz[m].y, accRZ[i][m].y);
                accRZ[i][m].z = fmaf(a, wrz[m].z, accRZ[i][m].z);
                accRZ[i][m].w = fmaf(a, wrz[m].w, accRZ[i][m].w);
            }
            #pragma unroll
            for (int m = 0; m < 2; m++) {
                accN[i][m].x = fmaf(a, wn[m].x, accN[i][m].x);
                accN[i][m].y = fmaf(a, wn[m].y, accN[i][m].y);
                accN[i][m].z = fmaf(a, wn[m].z, accN[i][m].z);
                accN[i][m].w = fmaf(a, wn[m].w, accN[i][m].w);
            }
        }
    }
}

__global__ __launch_bounds__(256, 2) void k_gru(
    const float* __restrict__ memory,
    const float* __restrict__ bih, const float* __restrict__ bhh)
{
    float* sIn  = smem;
    float* sWrz = sIn + 32 * 256;
    float* sWn  = sWrz + 32 * 256;
    float* sCnt = sWn + 32 * 128;

    const int tid = threadIdx.x;
    const int n0 = blockIdx.x * 32;
    const int tx = tid & 15, ty = tid >> 4;

    if (tid < 32) sCnt[tid] = g_cnt[n0 + tid];
    __syncthreads();

    #pragma unroll
    for (int it = 0; it < 8; it++) {
        int idx = tid + 256 * it;
        int n = idx >> 6, q = idx & 63;
        float4 v;
        if (q < 32) {
            float cnt = sCnt[n];
            v = *((const float4*)(g_aggr + (size_t)(n0 + n) * 128) + q);
            float inv = (cnt > 0.f) ? (1.f / cnt) : 0.f;
            v.x *= inv; v.y *= inv; v.z *= inv; v.w *= inv;
        } else {
            v = __ldg((const float4*)(memory + (size_t)(n0 + n) * 128) + (q - 32));
        }
        ((float4*)sIn)[idx] = v;
    }

    float4 accRZ[2][4], accIN[2][2], accHN[2][2];
    #pragma unroll
    for (int i = 0; i < 2; i++) {
        #pragma unroll
        for (int m = 0; m < 4; m++) accRZ[i][m] = make_float4(0.f, 0.f, 0.f, 0.f);
        #pragma unroll
        for (int m = 0; m < 2; m++) {
            accIN[i][m] = make_float4(0.f, 0.f, 0.f, 0.f);
            accHN[i][m] = make_float4(0.f, 0.f, 0.f, 0.f);
        }
    }

    #pragma unroll 1
    for (int kc = 0; kc < 4; kc++) {
        __syncthreads();
        {
            const float4* wsrc = (const float4*)(g_Wrz + (size_t)kc * 32 * 256);
            #pragma unroll
            for (int it = 0; it < 8; it++)
                ((float4*)sWrz)[tid + 256 * it] = wsrc[tid + 256 * it];
            const float4* nsrc = (const float4*)(g_Win + (size_t)kc * 32 * 128);
            #pragma unroll
            for (int it = 0; it < 4; it++)
                ((float4*)sWn)[tid + 256 * it] = nsrc[tid + 256 * it];
        }
        __syncthreads();
        gru_chunk(sIn, sWrz, sWn, kc * 32, tx, ty, accRZ, accIN);
    }
    #pragma unroll 1
    for (int kc = 4; kc < 8; kc++) {
        __syncthreads();
        {
            const float4* wsrc = (const float4*)(g_Wrz + (size_t)kc * 32 * 256);
            #pragma unroll
            for (int it = 0; it < 8; it++)
                ((float4*)sWrz)[tid + 256 * it] = wsrc[tid + 256 * it];
            const float4* nsrc = (const float4*)(g_Whn + (size_t)(kc - 4) * 32 * 128);
            #pragma unroll
            for (int it = 0; it < 4; it++)
                ((float4*)sWn)[tid + 256 * it] = nsrc[tid + 256 * it];
        }
        __syncthreads();
        gru_chunk(sIn, sWrz, sWn, kc * 32, tx, ty, accRZ, accHN);
    }

    #pragma unroll
    for (int i = 0; i < 2; i++) {
        int row = i * 16 + ty;
        float cnt = sCnt[row];
        #pragma unroll
        for (int m = 0; m < 2; m++) {
            int f4idx = m * 16 + tx;
            float4 bir = __ldg((const float4*)bih + f4idx);
            float4 bhr = __ldg((const float4*)bhh + f4idx);
            float4 biz = __ldg((const float4*)bih + 32 + f4idx);
            float4 bhz = __ldg((const float4*)bhh + 32 + f4idx);
            float4 bin = __ldg((const float4*)bih + 64 + f4idx);
            float4 bhn = __ldg((const float4*)bhh + 64 + f4idx);
            float4 mv = ((const float4*)sIn)[row * 64 + 32 + f4idx];

            float4 r, z, nn, res;
            r.x = 1.f / (1.f + expf(-(accRZ[i][m].x + bir.x + bhr.x)));
            r.y = 1.f / (1.f + expf(-(accRZ[i][m].y + bir.y + bhr.y)));
            r.z = 1.f / (1.f + expf(-(accRZ[i][m].z + bir.z + bhr.z)));
            r.w = 1.f / (1.f + expf(-(accRZ[i][m].w + bir.w + bhr.w)));
            z.x = 1.f / (1.f + expf(-(accRZ[i][m + 2].x + biz.x + bhz.x)));
            z.y = 1.f / (1.f + expf(-(accRZ[i][m + 2].y + biz.y + bhz.y)));
            z.z = 1.f / (1.f + expf(-(accRZ[i][m + 2].z + biz.z + bhz.z)));
            z.w = 1.f / (1.f + expf(-(accRZ[i][m + 2].w + biz.w + bhz.w)));
            nn.x = tanhf(accIN[i][m].x + bin.x + r.x * (accHN[i][m].x + bhn.x));
            nn.y = tanhf(accIN[i][m].y + bin.y + r.y * (accHN[i][m].y + bhn.y));
            nn.z = tanhf(accIN[i][m].z + bin.z + r.z * (accHN[i][m].z + bhn.z));
            nn.w = tanhf(accIN[i][m].w + bin.w + r.w * (accHN[i][m].w + bhn.w));
            res.x = (cnt > 0.f) ? ((1.f - z.x) * nn.x + z.x * mv.x) : mv.x;
            res.y = (cnt > 0.f) ? ((1.f - z.y) * nn.y + z.y * mv.y) : mv.y;
            res.z = (cnt > 0.f) ? ((1.f - z.z) * nn.z + z.z * mv.z) : mv.z;
            res.w = (cnt > 0.f) ? ((1.f - z.w) * nn.w + z.w * mv.w) : mv.w;
            ((float4*)(g_newmem + (size_t)(n0 + row) * 128))[f4idx] = res;
        }
    }
}

// ======================= K3: embeddings via tf32 MMA + bilinear dot ===============
// 128 edges/block. Warps: wm = wid>>1 (0..3), wn = wid&1 (0..1);
// warp tile 32(M) x 32(N); acc[2][4].
// smem: region0 [0,6912): sA 128*36 | sW 32*72 ; tail aliases sM 64*64 + sv 64.
//       sHs [6912, 15616), sHd [15616, 24320), sN ints at 24320.
__global__ __launch_bounds__(256, 2) void k_emb(
    const int* __restrict__ src, const int* __restrict__ dst,
    const float* __restrict__ sf, const float* __restrict__ df,
    const float* __restrict__ W1, const float* __restrict__ b1,
    float* __restrict__ out, int E)
{
    float* sA  = smem;                  // 128*36
    float* sW  = smem + 128 * 36;       // 32*72
    float* sM  = smem;                  // tail alias: 64*64
    float* sv  = smem + 64 * 64;        // tail alias: 64
    float* sHs = smem + 6912;           // 128*68
    float* sHd = smem + 6912 + 128 * 68;// 128*68
    int*   sN  = (int*)(smem + 6912 + 2 * 128 * 68);

    const int tid  = threadIdx.x;
    const int lane = tid & 31;
    const int wid  = tid >> 5;
    const int wm   = wid >> 1;          // 0..3
    const int wn   = wid & 1;           // 0..1
    const int grp  = lane >> 2;
    const int thr  = lane & 3;
    const int e0 = blockIdx.x * 128;
    const int nE = min(128, E - e0);

    #pragma unroll 1
    for (int side = 0; side < 2; side++) {
        const int* nodes = side ? dst : src;
        const float* feats = side ? df : sf;
        float* sH = side ? sHd : sHs;

        __syncthreads();
        if (tid < 128) sN[tid] = (tid < nE) ? nodes[e0 + tid] : 0;
        __syncthreads();

        float4 acc[2][4];
        #pragma unroll
        for (int mt = 0; mt < 2; mt++)
            #pragma unroll
            for (int nt = 0; nt < 4; nt++) acc[mt][nt] = make_float4(0.f, 0.f, 0.f, 0.f);

        // GEMM1: K=192 in 6 chunks of 32
        #pragma unroll 1
        for (int kc = 0; kc < 6; kc++) {
            if (kc < 4) {
                int q0 = kc * 8;
                #pragma unroll
                for (int it = 0; it < 4; it++) {
                    int idx = tid + 256 * it;
                    int e = idx >> 3, q = idx & 7;
                    float4 v = make_float4(0.f, 0.f, 0.f, 0.f);
                    if (e < nE) v = *((const float4*)(g_newmem + (size_t)sN[e] * 128) + q0 + q);
                    ((float4*)sA)[e * 9 + q] = to_tf32_4(v);
                }
            } else {
                int fc = kc - 4;
                #pragma unroll
                for (int it = 0; it < 4; it++) {
                    int idx = tid + 256 * it;
                    int e = idx >> 3, q = idx & 7;
                    float4 v = make_float4(0.f, 0.f, 0.f, 0.f);
                    if (e < nE) v = __ldg((const float4*)(feats + (size_t)(e0 + e) * 64) + fc * 8 + q);
                    ((float4*)sA)[e * 9 + q] = to_tf32_4(v);
                }
            }
            // stage W1 chunk: 32 rows x 64 cols, stride 72
            {
                const float4* wsrc = (const float4*)(W1 + (size_t)kc * 32 * 64);
                #pragma unroll
                for (int it = 0; it < 2; it++) {
                    int idx = tid + 256 * it;
                    int r = idx >> 4, c = idx & 15;
                    ((float4*)sW)[r * 18 + c] = to_tf32_4(__ldg(wsrc + idx));
                }
            }
            __syncthreads();
            #pragma unroll
            for (int ks = 0; ks < 4; ks++) {
                unsigned int a[2][4], b[4][2];
                #pragma unroll
                for (int mt = 0; mt < 2; mt++) {
                    int r0 = (wm * 32 + mt * 16 + grp) * 36 + ks * 8 + thr;
                    int r1 = r0 + 8 * 36;
                    a[mt][0] = __float_as_uint(sA[r0]);
                    a[mt][1] = __float_as_uint(sA[r1]);
                    a[mt][2] = __float_as_uint(sA[r0 + 4]);
                    a[mt][3] = __float_as_uint(sA[r1 + 4]);
                }
                #pragma unroll
                for (int nt = 0; nt < 4; nt++) {
                    int col = wn * 32 + nt * 8 + grp;
                    b[nt][0] = __float_as_uint(sW[(ks * 8 + thr) * 72 + col]);
                    b[nt][1] = __float_as_uint(sW[(ks * 8 + thr + 4) * 72 + col]);
                }
                #pragma unroll
                for (int mt = 0; mt < 2; mt++)
                    #pragma unroll
                    for (int nt = 0; nt < 4; nt++)
                        mma_tf32(acc[mt][nt], a[mt], b[nt]);
            }
            __syncthreads();
        }

        // bias + relu -> sH (stride 68)
        {
            float bc0[4], bc1[4];
            #pragma unroll
            for (int nt = 0; nt < 4; nt++) {
                int col = wn * 32 + nt * 8 + 2 * thr;
                bc0[nt] = __ldg(b1 + col);
                bc1[nt] = __ldg(b1 + col + 1);
            }
            #pragma unroll
            for (int mt = 0; mt < 2; mt++) {
                int r0 = wm * 32 + mt * 16 + grp;
                #pragma unroll
                for (int nt = 0; nt < 4; nt++) {
                    int col = wn * 32 + nt * 8 + 2 * thr;
                    sH[r0 * 68 + col]           = fmaxf(acc[mt][nt].x + bc0[nt], 0.f);
                    sH[r0 * 68 + col + 1]       = fmaxf(acc[mt][nt].y + bc1[nt], 0.f);
                    sH[(r0 + 8) * 68 + col]     = fmaxf(acc[mt][nt].z + bc0[nt], 0.f);
                    sH[(r0 + 8) * 68 + col + 1] = fmaxf(acc[mt][nt].w + bc1[nt], 0.f);
                }
            }
        }
    }
    __syncthreads();

    // stage M and v into region0 (sA/sW dead now)
    #pragma unroll
    for (int it = 0; it < 4; it++)
        ((float4*)sM)[tid + 256 * it] = ((const float4*)g_M)[tid + 256 * it];
    if (tid < 16) ((float4*)sv)[tid] = ((const float4*)g_v)[tid];
    __syncthreads();

    // t = hd @ M  (fp32 scalar tail)
    const int tx = tid & 15, ty = tid >> 4;
    float4 t[8];
    #pragma unroll
    for (int i = 0; i < 8; i++) t[i] = make_float4(0.f, 0.f, 0.f, 0.f);
    #pragma unroll 8
    for (int kk = 0; kk < 64; kk++) {
        float4 m = ((const float4*)sM)[kk * 16 + tx];
        #pragma unroll
        for (int i = 0; i < 8; i++) {
            float a = sHd[(i * 16 + ty) * 68 + kk];
            t[i].x = fmaf(a, m.x, t[i].x);
            t[i].y = fmaf(a, m.y, t[i].y);
            t[i].z = fmaf(a, m.z, t[i].z);
            t[i].w = fmaf(a, m.w, t[i].w);
        }
    }

    float c0 = g_c0;
    float4 vv = ((const float4*)sv)[tx];
    float p[8];
    #pragma unroll
    for (int i = 0; i < 8; i++) {
        int row = i * 16 + ty;
        float4 hs = ((const float4*)(sHs + row * 68))[tx];
        float4 hd = ((const float4*)(sHd + row * 68))[tx];
        p[i] = hs.x * t[i].x + hs.y * t[i].y + hs.z * t[i].z + hs.w * t[i].w
             + (hs.x + hd.x) * vv.x + (hs.y + hd.y) * vv.y
             + (hs.z + hd.z) * vv.z + (hs.w + hd.w) * vv.w;
    }
    #pragma unroll
    for (int m = 1; m < 16; m <<= 1)
        #pragma unroll
        for (int i = 0; i < 8; i++)
            p[i] += __shfl_xor_sync(0xffffffffu, p[i], m);
    if (tx == 0) {
        #pragma unroll
        for (int i = 0; i < 8; i++) {
            int e = i * 16 + ty;
            if (e < nE) out[e0 + e] = p[i] + c0;
        }
    }
}

// ---------------- host launch ----------------
extern "C" void kernel_launch(void* const* d_in, const int* in_sizes, int n_in,
                              void* d_out, int out_size)
{
    const int*   src   = (const int*)d_in[0];
    const int*   dst   = (const int*)d_in[1];
    const float* ef    = (const float*)d_in[2];
    const float* ts    = (const float*)d_in[3];
    const float* sf    = (const float*)d_in[4];
    const float* df    = (const float*)d_in[5];
    const float* mem   = (const float*)d_in[6];
    const float* tw    = (const float*)d_in[7];
    const float* tb    = (const float*)d_in[8];
    const float* mw1   = (const float*)d_in[9];
    const float* mb1   = (const float*)d_in[10];
    const float* mw2   = (const float*)d_in[11];
    const float* mb2   = (const float*)d_in[12];
    const float* gwih  = (const float*)d_in[13];
    const float* gwhh  = (const float*)d_in[14];
    const float* gbih  = (const float*)d_in[15];
    const float* gbhh  = (const float*)d_in[16];
    const float* ew1   = (const float*)d_in[17];
    const float* eb1   = (const float*)d_in[18];
    const float* ew2   = (const float*)d_in[19];
    const float* eb2   = (const float*)d_in[20];
    float* out = (float*)d_out;

    const int E = in_sizes[0];

    const int SMEM1 = (128 * 132 + 32 * 136) * 4 + 256 * 4;
    const int SMEM2 = (32 * 256 + 32 * 256 + 32 * 128 + 32) * 4;
    const int SMEM3 = (6912 + 2 * 128 * 68) * 4 + 128 * 4;

    cudaFuncSetAttribute(k_msg, cudaFuncAttributeMaxDynamicSharedMemorySize, SMEM1);
    cudaFuncSetAttribute(k_gru, cudaFuncAttributeMaxDynamicSharedMemorySize, SMEM2);
    cudaFuncSetAttribute(k_emb, cudaFuncAttributeMaxDynamicSharedMemorySize, SMEM3);

    k_zero<<<2048, 256>>>();
    k_pre<<<1, 256>>>(ew2, eb2);
    k_prew<<<128, 256>>>(gwih, gwhh);
    k_msg<<<(E + 127) / 128, 256, SMEM1>>>(src, dst, ef, ts, mem, tw, tb,
                                           mw1, mb1, mw2, mb2, E);
    k_gru<<<N_NODES / 32, 256, SMEM2>>>(mem, gbih, gbhh);
    k_emb<<<(E + 127) / 128, 256, SMEM3>>>(src, dst, sf, df,
                                           ew1, eb1, out, E);
}

// round 8
// speedup vs baseline: 3.8908x; 1.2539x over previous
#include <cuda_runtime.h>
#include <stdint.h>
#include <math.h>

#define N_NODES 100000
#define MEM_DIM 128
#define MSG_DIM 128

// ---------------- scratch (static device globals; no allocation) ----------------
__device__ float g_aggr[(size_t)N_NODES * MSG_DIM];
__device__ float g_cnt[N_NODES];
__device__ float g_newmem[(size_t)N_NODES * MEM_DIM];
__device__ float g_M[64 * 64];     // W2 @ W2^T (symmetric)
__device__ float g_v[64];          // W2 @ b2
__device__ float g_c0;             // b2.b2
__device__ float g_Wg[256 * 512];  // padded gate-interleaved GRU weights

extern __shared__ float smem[];

// ---------------- tf32 helpers ----------------
__device__ __forceinline__ float to_tf32(float x) {
    unsigned int u;
    asm("cvt.rna.tf32.f32 %0, %1;" : "=r"(u) : "f"(x));
    return __uint_as_float(u);
}
__device__ __forceinline__ float4 to_tf32_4(float4 v) {
    v.x = to_tf32(v.x); v.y = to_tf32(v.y);
    v.z = to_tf32(v.z); v.w = to_tf32(v.w);
    return v;
}
__device__ __forceinline__ void mma_tf32(float4& c, const unsigned int a[4], const unsigned int b[2]) {
    asm volatile(
        "mma.sync.aligned.m16n8k8.row.col.f32.tf32.tf32.f32 "
        "{%0,%1,%2,%3},{%4,%5,%6,%7},{%8,%9},{%0,%1,%2,%3};\n"
        : "+f"(c.x), "+f"(c.y), "+f"(c.z), "+f"(c.w)
        : "r"(a[0]), "r"(a[1]), "r"(a[2]), "r"(a[3]), "r"(b[0]), "r"(b[1]));
}
__device__ __forceinline__ float sigm(float x) { return 1.f / (1.f + expf(-x)); }

// ---------------- K0: zero aggregation buffers ----------------
__global__ void k_zero() {
    size_t stride = (size_t)gridDim.x * blockDim.x;
    size_t tid0 = (size_t)blockIdx.x * blockDim.x + threadIdx.x;
    size_t tot4 = (size_t)N_NODES * MSG_DIM / 4;
    float4 z = make_float4(0.f, 0.f, 0.f, 0.f);
    for (size_t i = tid0; i < tot4; i += stride) ((float4*)g_aggr)[i] = z;
    for (size_t i = tid0; i < N_NODES; i += stride) g_cnt[i] = 0.f;
}

// ---------------- K-pre: bilinear precompute for emb ----------------
__global__ void k_pre(const float* __restrict__ W2, const float* __restrict__ b2) {
    __shared__ float sW2[64 * 64];
    __shared__ float sb2[64];
    int tid = threadIdx.x;
    for (int i = tid; i < 64 * 64; i += 256) sW2[i] = W2[i];
    if (tid < 64) sb2[tid] = b2[tid];
    __syncthreads();
    for (int p = tid; p < 64 * 64; p += 256) {
        int j = p >> 6, k = p & 63;
        float s = 0.f;
        #pragma unroll 16
        for (int c = 0; c < 64; c++) s = fmaf(sW2[j * 64 + c], sW2[k * 64 + c], s);
        g_M[p] = s;
    }
    if (tid < 64) {
        float s = 0.f;
        #pragma unroll 16
        for (int c = 0; c < 64; c++) s = fmaf(sW2[tid * 64 + c], sb2[c], s);
        g_v[tid] = s;
    }
    if (tid == 0) {
        float s = 0.f;
        for (int c = 0; c < 64; c++) s = fmaf(sb2[c], sb2[c], s);
        g_c0 = s;
    }
}

// ---------------- K-prew: build gate-interleaved padded GRU weight matrix --------
// col c: jb = c>>5 (16 blocks), t = c&31, q = t>>3 (0:r 1:z 2:in 3:hn), j = jb*8 + (t&7)
// row k (0..255): k<128 -> input (mean msg) side, k>=128 -> hidden side
__global__ void k_prew(const float* __restrict__ Wih, const float* __restrict__ Whh) {
    int stride = gridDim.x * blockDim.x;
    int idx = blockIdx.x * blockDim.x + threadIdx.x;
    for (int p = idx; p < 256 * 512; p += stride) {
        int k = p >> 9, c = p & 511;
        int jb = c >> 5, t = c & 31, q = t >> 3;
        int j = jb * 8 + (t & 7);
        float w;
        if (q == 0)      w = (k < 128) ? Wih[(size_t)j * 128 + k]
                                       : Whh[(size_t)j * 128 + (k - 128)];
        else if (q == 1) w = (k < 128) ? Wih[(size_t)(128 + j) * 128 + k]
                                       : Whh[(size_t)(128 + j) * 128 + (k - 128)];
        else if (q == 2) w = (k < 128) ? Wih[(size_t)(256 + j) * 128 + k] : 0.f;
        else             w = (k < 128) ? 0.f : Whh[(size_t)(256 + j) * 128 + (k - 128)];
        g_Wg[p] = w;
    }
}

// ======================= K1: message MLP via tf32 MMA (128 edges/block) ===========
__global__ __launch_bounds__(256, 2) void k_msg(
    const int* __restrict__ src, const int* __restrict__ dst,
    const float* __restrict__ ef, const float* __restrict__ ts,
    const float* __restrict__ memory,
    const float* __restrict__ tw, const float* __restrict__ tb,
    const float* __restrict__ W1, const float* __restrict__ b1,
    const float* __restrict__ W2, const float* __restrict__ b2,
    int E)
{
    float* sU  = smem;                 // 128*132
    float* sA  = sU;                   // 128*36  (GEMM1)
    float* sW  = sU + 128 * 36;        // 32*136  (GEMM1)
    float* sW2 = smem + 128 * 132;     // 32*136
    int*   sN  = (int*)(sW2 + 32 * 136);

    const int tid  = threadIdx.x;
    const int lane = tid & 31;
    const int wid  = tid >> 5;
    const int wm   = wid >> 2;
    const int wn   = wid & 3;
    const int grp  = lane >> 2;
    const int thr  = lane & 3;
    const int e0 = blockIdx.x * 128;
    const int nE = min(128, E - e0);

    if (tid < 128) sN[tid] = (tid < nE) ? src[e0 + tid] : 0;
    else           sN[tid] = (tid - 128 < nE) ? dst[e0 + tid - 128] : 0;
    __syncthreads();

    float4 acc[4][4];
    #pragma unroll
    for (int mt = 0; mt < 4; mt++)
        #pragma unroll
        for (int nt = 0; nt < 4; nt++) acc[mt][nt] = make_float4(0.f, 0.f, 0.f, 0.f);

    #pragma unroll 1
    for (int kc = 0; kc < 10; kc++) {
        if (kc < 8) {
            const int* nodes = (kc < 4) ? sN : sN + 128;
            int q0 = (kc & 3) * 8;
            #pragma unroll
            for (int it = 0; it < 4; it++) {
                int idx = tid + 256 * it;
                int e = idx >> 3, q = idx & 7;
                float4 v = make_float4(0.f, 0.f, 0.f, 0.f);
                if (e < nE) v = __ldg((const float4*)(memory + (size_t)nodes[e] * 128) + q0 + q);
                ((float4*)sA)[e * 9 + q] = to_tf32_4(v);
            }
        } else if (kc == 8) {
            #pragma unroll
            for (int it = 0; it < 4; it++) {
                int idx = tid + 256 * it;
                int e = idx >> 3, q = idx & 7;
                float4 v = make_float4(0.f, 0.f, 0.f, 0.f);
                if (e < nE) v = __ldg((const float4*)(ef + (size_t)(e0 + e) * 32) + q);
                ((float4*)sA)[e * 9 + q] = to_tf32_4(v);
            }
        } else {
            for (int it = 0; it < 16; it++) {
                int idx = tid + 256 * it;
                int e = idx >> 5, c = idx & 31;
                float t = 0.f;
                if (e < nE) t = cosf(ts[e0 + e] * __ldg(tw + c) + __ldg(tb + c));
                sA[e * 36 + c] = to_tf32(t);
            }
        }
        {
            const float4* wsrc = (const float4*)(W1 + (size_t)kc * 32 * 128);
            #pragma unroll
            for (int it = 0; it < 4; it++) {
                int idx = tid + 256 * it;
                int r = idx >> 5, c = idx & 31;
                ((float4*)sW)[r * 34 + c] = to_tf32_4(__ldg(wsrc + idx));
            }
        }
        __syncthreads();
        #pragma unroll
        for (int ks = 0; ks < 4; ks++) {
            unsigned int a[4][4], b[4][2];
            #pragma unroll
            for (int mt = 0; mt < 4; mt++) {
                int r0 = (wm * 64 + mt * 16 + grp) * 36 + ks * 8 + thr;
                int r1 = r0 + 8 * 36;
                a[mt][0] = __float_as_uint(sA[r0]);
                a[mt][1] = __float_as_uint(sA[r1]);
                a[mt][2] = __float_as_uint(sA[r0 + 4]);
                a[mt][3] = __float_as_uint(sA[r1 + 4]);
            }
            #pragma unroll
            for (int nt = 0; nt < 4; nt++) {
                int col = wn * 32 + nt * 8 + grp;
                b[nt][0] = __float_as_uint(sW[(ks * 8 + thr) * 136 + col]);
                b[nt][1] = __float_as_uint(sW[(ks * 8 + thr + 4) * 136 + col]);
            }
            #pragma unroll
            for (int mt = 0; mt < 4; mt++)
                #pragma unroll
                for (int nt = 0; nt < 4; nt++)
                    mma_tf32(acc[mt][nt], a[mt], b[nt]);
        }
        __syncthreads();
    }

    {
        float bc0[4], bc1[4];
        #pragma unroll
        for (int nt = 0; nt < 4; nt++) {
            int col = wn * 32 + nt * 8 + 2 * thr;
            bc0[nt] = __ldg(b1 + col);
            bc1[nt] = __ldg(b1 + col + 1);
        }
        #pragma unroll
        for (int mt = 0; mt < 4; mt++) {
            int r0 = wm * 64 + mt * 16 + grp;
            #pragma unroll
            for (int nt = 0; nt < 4; nt++) {
                int col = wn * 32 + nt * 8 + 2 * thr;
                sU[r0 * 132 + col]           = to_tf32(fmaxf(acc[mt][nt].x + bc0[nt], 0.f));
                sU[r0 * 132 + col + 1]       = to_tf32(fmaxf(acc[mt][nt].y + bc1[nt], 0.f));
                sU[(r0 + 8) * 132 + col]     = to_tf32(fmaxf(acc[mt][nt].z + bc0[nt], 0.f));
                sU[(r0 + 8) * 132 + col + 1] = to_tf32(fmaxf(acc[mt][nt].w + bc1[nt], 0.f));
                acc[mt][nt] = make_float4(0.f, 0.f, 0.f, 0.f);
            }
        }
    }

    #pragma unroll 1
    for (int kc = 0; kc < 4; kc++) {
        __syncthreads();
        {
            const float4* wsrc = (const float4*)(W2 + (size_t)kc * 32 * 128);
            #pragma unroll
            for (int it = 0; it < 4; it++) {
                int idx = tid + 256 * it;
                int r = idx >> 5, c = idx & 31;
                ((float4*)sW2)[r * 34 + c] = to_tf32_4(__ldg(wsrc + idx));
            }
        }
        __syncthreads();
        #pragma unroll
        for (int ks = 0; ks < 4; ks++) {
            unsigned int a[4][4], b[4][2];
            int kbase = kc * 32 + ks * 8;
            #pragma unroll
            for (int mt = 0; mt < 4; mt++) {
                int r0 = (wm * 64 + mt * 16 + grp) * 132 + kbase + thr;
                int r1 = r0 + 8 * 132;
                a[mt][0] = __float_as_uint(sU[r0]);
                a[mt][1] = __float_as_uint(sU[r1]);
                a[mt][2] = __float_as_uint(sU[r0 + 4]);
                a[mt][3] = __float_as_uint(sU[r1 + 4]);
            }
            #pragma unroll
            for (int nt = 0; nt < 4; nt++) {
                int col = wn * 32 + nt * 8 + grp;
                b[nt][0] = __float_as_uint(sW2[(ks * 8 + thr) * 136 + col]);
                b[nt][1] = __float_as_uint(sW2[(ks * 8 + thr + 4) * 136 + col]);
            }
            #pragma unroll
            for (int mt = 0; mt < 4; mt++)
                #pragma unroll
                for (int nt = 0; nt < 4; nt++)
                    mma_tf32(acc[mt][nt], a[mt], b[nt]);
        }
    }
    __syncthreads();

    {
        float bc0[4], bc1[4];
        #pragma unroll
        for (int nt = 0; nt < 4; nt++) {
            int col = wn * 32 + nt * 8 + 2 * thr;
            bc0[nt] = __ldg(b2 + col);
            bc1[nt] = __ldg(b2 + col + 1);
        }
        #pragma unroll
        for (int mt = 0; mt < 4; mt++) {
            int r0 = wm * 64 + mt * 16 + grp;
            #pragma unroll
            for (int nt = 0; nt < 4; nt++) {
                int col = wn * 32 + nt * 8 + 2 * thr;
                sU[r0 * 132 + col]           = acc[mt][nt].x + bc0[nt];
                sU[r0 * 132 + col + 1]       = acc[mt][nt].y + bc1[nt];
                sU[(r0 + 8) * 132 + col]     = acc[mt][nt].z + bc0[nt];
                sU[(r0 + 8) * 132 + col + 1] = acc[mt][nt].w + bc1[nt];
            }
        }
    }
    __syncthreads();

    {
        const int tx = tid & 15, ty = tid >> 4;
        #pragma unroll
        for (int i = 0; i < 8; i++) {
            int e = i * 16 + ty;
            if (e < nE) {
                float4 v0 = ((const float4*)(sU + e * 132))[tx];
                float4 v1 = ((const float4*)(sU + e * 132))[16 + tx];
                int ns = sN[e], nd = sN[128 + e];
                atomicAdd((float4*)(g_aggr + (size_t)ns * 128) + tx, v0);
                atomicAdd((float4*)(g_aggr + (size_t)ns * 128) + 16 + tx, v1);
                atomicAdd((float4*)(g_aggr + (size_t)nd * 128) + tx, v0);
                atomicAdd((float4*)(g_aggr + (size_t)nd * 128) + 16 + tx, v1);
            }
        }
    }
    if (tid < nE) {
        atomicAdd(&g_cnt[sN[tid]], 1.f);
        atomicAdd(&g_cnt[sN[128 + tid]], 1.f);
    }
}

// ======================= K2: GRU via tf32 MMA, gate-interleaved ===================
// 64 nodes/block, 256 threads, warps 1x8 (warp tile 64M x 32N), 2 N-sweeps of 256.
// Within a warp's 32 cols: nt0 = r, nt1 = z, nt2 = i_n, nt3 = h_n for 8 j's.
__global__ __launch_bounds__(256, 2) void k_gru(
    const float* __restrict__ memory,
    const float* __restrict__ bih, const float* __restrict__ bhh)
{
    float* sA   = smem;                 // 64*36
    float* sW   = smem + 64 * 36;       // 32*264
    float* sCnt = sW + 32 * 264;        // 64

    const int tid  = threadIdx.x;
    const int lane = tid & 31;
    const int wid  = tid >> 5;          // 0..7
    const int grp  = lane >> 2;
    const int thr  = lane & 3;
    const int n0 = blockIdx.x * 64;
    const int nN = min(64, N_NODES - n0);

    if (tid < 64) sCnt[tid] = (tid < nN) ? g_cnt[n0 + tid] : 0.f;
    __syncthreads();

    #pragma unroll 1
    for (int sweep = 0; sweep < 2; sweep++) {
        float4 acc[4][4];
        #pragma unroll
        for (int mt = 0; mt < 4; mt++)
            #pragma unroll
            for (int nt = 0; nt < 4; nt++) acc[mt][nt] = make_float4(0.f, 0.f, 0.f, 0.f);

        #pragma unroll 1
        for (int kc = 0; kc < 8; kc++) {
            // stage A (64 x 32, stride 36, tf32); kc<4 -> mean msg, else memory
            #pragma unroll
            for (int it = 0; it < 2; it++) {
                int idx = tid + 256 * it;
                int e = idx >> 3, q = idx & 7;
                float4 v = make_float4(0.f, 0.f, 0.f, 0.f);
                if (e < nN) {
                    if (kc < 4) {
                        v = *((const float4*)(g_aggr + (size_t)(n0 + e) * 128) + kc * 8 + q);
                        float cnt = sCnt[e];
                        float inv = (cnt > 0.f) ? (1.f / cnt) : 0.f;
                        v.x *= inv; v.y *= inv; v.z *= inv; v.w *= inv;
                    } else {
                        v = __ldg((const float4*)(memory + (size_t)(n0 + e) * 128) + (kc - 4) * 8 + q);
                    }
                }
                ((float4*)sA)[e * 9 + q] = to_tf32_4(v);
            }
            // stage W (32 rows x 256 cols, stride 264, tf32) from g_Wg
            {
                const float* wsrc = g_Wg + (size_t)kc * 32 * 512 + sweep * 256;
                #pragma unroll
                for (int it = 0; it < 8; it++) {
                    int idx = tid + 256 * it;
                    int r = idx >> 6, c = idx & 63;
                    ((float4*)sW)[r * 66 + c] =
                        to_tf32_4(__ldg((const float4*)(wsrc + (size_t)r * 512) + c));
                }
            }
            __syncthreads();
            #pragma unroll
            for (int ks = 0; ks < 4; ks++) {
                unsigned int a[4][4], b[4][2];
                #pragma unroll
                for (int mt = 0; mt < 4; mt++) {
                    int r0 = (mt * 16 + grp) * 36 + ks * 8 + thr;
                    int r1 = r0 + 8 * 36;
                    a[mt][0] = __float_as_uint(sA[r0]);
                    a[mt][1] = __float_as_uint(sA[r1]);
                    a[mt][2] = __float_as_uint(sA[r0 + 4]);
                    a[mt][3] = __float_as_uint(sA[r1 + 4]);
                }
                #pragma unroll
                for (int nt = 0; nt < 4; nt++) {
                    int col = wid * 32 + nt * 8 + grp;
                    b[nt][0] = __float_as_uint(sW[(ks * 8 + thr) * 264 + col]);
                    b[nt][1] = __float_as_uint(sW[(ks * 8 + thr + 4) * 264 + col]);
                }
                #pragma unroll
                for (int mt = 0; mt < 4; mt++)
                    #pragma unroll
                    for (int nt = 0; nt < 4; nt++)
                        mma_tf32(acc[mt][nt], a[mt], b[nt]);
            }
            __syncthreads();
        }

        // ---- epilogue: this thread owns cols j0, j0+1 for rows mt*16+grp(+8) ----
        int j0 = sweep * 64 + wid * 8 + 2 * thr;
        float br0 = __ldg(bih + j0) + __ldg(bhh + j0);
        float br1 = __ldg(bih + j0 + 1) + __ldg(bhh + j0 + 1);
        float bz0 = __ldg(bih + 128 + j0) + __ldg(bhh + 128 + j0);
        float bz1 = __ldg(bih + 128 + j0 + 1) + __ldg(bhh + 128 + j0 + 1);
        float bi0 = __ldg(bih + 256 + j0),      bi1 = __ldg(bih + 256 + j0 + 1);
        float bh0 = __ldg(bhh + 256 + j0),      bh1 = __ldg(bhh + 256 + j0 + 1);

        #pragma unroll
        for (int mt = 0; mt < 4; mt++) {
            #pragma unroll
            for (int half = 0; half < 2; half++) {
                int row = mt * 16 + grp + half * 8;
                if (row < nN) {
                    float rp0 = half ? acc[mt][0].z : acc[mt][0].x;
                    float rp1 = half ? acc[mt][0].w : acc[mt][0].y;
                    float zp0 = half ? acc[mt][1].z : acc[mt][1].x;
                    float zp1 = half ? acc[mt][1].w : acc[mt][1].y;
                    float ip0 = half ? acc[mt][2].z : acc[mt][2].x;
                    float ip1 = half ? acc[mt][2].w : acc[mt][2].y;
                    float hp0 = half ? acc[mt][3].z : acc[mt][3].x;
                    float hp1 = half ? acc[mt][3].w : acc[mt][3].y;

                    float2 hv = *(const float2*)(memory + (size_t)(n0 + row) * 128 + j0);
                    float cnt = sCnt[row];

                    float r0g = sigm(rp0 + br0), r1g = sigm(rp1 + br1);
                    float z0g = sigm(zp0 + bz0), z1g = sigm(zp1 + bz1);
                    float n0g = tanhf(ip0 + bi0 + r0g * (hp0 + bh0));
                    float n1g = tanhf(ip1 + bi1 + r1g * (hp1 + bh1));
                    float2 res;
                    res.x = (cnt > 0.f) ? ((1.f - z0g) * n0g + z0g * hv.x) : hv.x;
                    res.y = (cnt > 0.f) ? ((1.f - z1g) * n1g + z1g * hv.y) : hv.y;
                    *(float2*)(g_newmem + (size_t)(n0 + row) * 128 + j0) = res;
                }
            }
        }
    }
}

// ======================= K3: embeddings via tf32 MMA + bilinear dot ===============
__global__ __launch_bounds__(256, 2) void k_emb(
    const int* __restrict__ src, const int* __restrict__ dst,
    const float* __restrict__ sf, const float* __restrict__ df,
    const float* __restrict__ W1, const float* __restrict__ b1,
    float* __restrict__ out, int E)
{
    float* sA  = smem;                  // 128*36
    float* sW  = smem + 128 * 36;       // 32*72
    float* sM  = smem;                  // tail alias
    float* sv  = smem + 64 * 64;        // tail alias
    float* sHs = smem + 6912;           // 128*68
    float* sHd = smem + 6912 + 128 * 68;// 128*68
    int*   sN  = (int*)(smem + 6912 + 2 * 128 * 68);

    const int tid  = threadIdx.x;
    const int lane = tid & 31;
    const int wid  = tid >> 5;
    const int wm   = wid >> 1;
    const int wn   = wid & 1;
    const int grp  = lane >> 2;
    const int thr  = lane & 3;
    const int e0 = blockIdx.x * 128;
    const int nE = min(128, E - e0);

    #pragma unroll 1
    for (int side = 0; side < 2; side++) {
        const int* nodes = side ? dst : src;
        const float* feats = side ? df : sf;
        float* sH = side ? sHd : sHs;

        __syncthreads();
        if (tid < 128) sN[tid] = (tid < nE) ? nodes[e0 + tid] : 0;
        __syncthreads();

        float4 acc[2][4];
        #pragma unroll
        for (int mt = 0; mt < 2; mt++)
            #pragma unroll
            for (int nt = 0; nt < 4; nt++) acc[mt][nt] = make_float4(0.f, 0.f, 0.f, 0.f);

        #pragma unroll 1
        for (int kc = 0; kc < 6; kc++) {
            if (kc < 4) {
                int q0 = kc * 8;
                #pragma unroll
                for (int it = 0; it < 4; it++) {
                    int idx = tid + 256 * it;
                    int e = idx >> 3, q = idx & 7;
                    float4 v = make_float4(0.f, 0.f, 0.f, 0.f);
                    if (e < nE) v = *((const float4*)(g_newmem + (size_t)sN[e] * 128) + q0 + q);
                    ((float4*)sA)[e * 9 + q] = to_tf32_4(v);
                }
            } else {
                int fc = kc - 4;
                #pragma unroll
                for (int it = 0; it < 4; it++) {
                    int idx = tid + 256 * it;
                    int e = idx >> 3, q = idx & 7;
                    float4 v = make_float4(0.f, 0.f, 0.f, 0.f);
                    if (e < nE) v = __ldg((const float4*)(feats + (size_t)(e0 + e) * 64) + fc * 8 + q);
                    ((float4*)sA)[e * 9 + q] = to_tf32_4(v);
                }
            }
            {
                const float4* wsrc = (const float4*)(W1 + (size_t)kc * 32 * 64);
                #pragma unroll
                for (int it = 0; it < 2; it++) {
                    int idx = tid + 256 * it;
                    int r = idx >> 4, c = idx & 15;
                    ((float4*)sW)[r * 18 + c] = to_tf32_4(__ldg(wsrc + idx));
                }
            }
            __syncthreads();
            #pragma unroll
            for (int ks = 0; ks < 4; ks++) {
                unsigned int a[2][4], b[4][2];
                #pragma unroll
                for (int mt = 0; mt < 2; mt++) {
                    int r0 = (wm * 32 + mt * 16 + grp) * 36 + ks * 8 + thr;
                    int r1 = r0 + 8 * 36;
                    a[mt][0] = __float_as_uint(sA[r0]);
                    a[mt][1] = __float_as_uint(sA[r1]);
                    a[mt][2] = __float_as_uint(sA[r0 + 4]);
                    a[mt][3] = __float_as_uint(sA[r1 + 4]);
                }
                #pragma unroll
                for (int nt = 0; nt < 4; nt++) {
                    int col = wn * 32 + nt * 8 + grp;
                    b[nt][0] = __float_as_uint(sW[(ks * 8 + thr) * 72 + col]);
                    b[nt][1] = __float_as_uint(sW[(ks * 8 + thr + 4) * 72 + col]);
                }
                #pragma unroll
                for (int mt = 0; mt < 2; mt++)
                    #pragma unroll
                    for (int nt = 0; nt < 4; nt++)
                        mma_tf32(acc[mt][nt], a[mt], b[nt]);
            }
            __syncthreads();
        }

        {
            float bc0[4], bc1[4];
            #pragma unroll
            for (int nt = 0; nt < 4; nt++) {
                int col = wn * 32 + nt * 8 + 2 * thr;
                bc0[nt] = __ldg(b1 + col);
                bc1[nt] = __ldg(b1 + col + 1);
            }
            #pragma unroll
            for (int mt = 0; mt < 2; mt++) {
                int r0 = wm * 32 + mt * 16 + grp;
                #pragma unroll
                for (int nt = 0; nt < 4; nt++) {
                    int col = wn * 32 + nt * 8 + 2 * thr;
                    sH[r0 * 68 + col]           = fmaxf(acc[mt][nt].x + bc0[nt], 0.f);
                    sH[r0 * 68 + col + 1]       = fmaxf(acc[mt][nt].y + bc1[nt], 0.f);
                    sH[(r0 + 8) * 68 + col]     = fmaxf(acc[mt][nt].z + bc0[nt], 0.f);
                    sH[(r0 + 8) * 68 + col + 1] = fmaxf(acc[mt][nt].w + bc1[nt], 0.f);
                }
            }
        }
    }
    __syncthreads();

    #pragma unroll
    for (int it = 0; it < 4; it++)
        ((float4*)sM)[tid + 256 * it] = ((const float4*)g_M)[tid + 256 * it];
    if (tid < 16) ((float4*)sv)[tid] = ((const float4*)g_v)[tid];
    __syncthreads();

    const int tx = tid & 15, ty = tid >> 4;
    float4 t[8];
    #pragma unroll
    for (int i = 0; i < 8; i++) t[i] = make_float4(0.f, 0.f, 0.f, 0.f);
    #pragma unroll 8
    for (int kk = 0; kk < 64; kk++) {
        float4 m = ((const float4*)sM)[kk * 16 + tx];
        #pragma unroll
        for (int i = 0; i < 8; i++) {
            float a = sHd[(i * 16 + ty) * 68 + kk];
            t[i].x = fmaf(a, m.x, t[i].x);
            t[i].y = fmaf(a, m.y, t[i].y);
            t[i].z = fmaf(a, m.z, t[i].z);
            t[i].w = fmaf(a, m.w, t[i].w);
        }
    }

    float c0 = g_c0;
    float4 vv = ((const float4*)sv)[tx];
    float p[8];
    #pragma unroll
    for (int i = 0; i < 8; i++) {
        int row = i * 16 + ty;
        float4 hs = ((const float4*)(sHs + row * 68))[tx];
        float4 hd = ((const float4*)(sHd + row * 68))[tx];
        p[i] = hs.x * t[i].x + hs.y * t[i].y + hs.z * t[i].z + hs.w * t[i].w
             + (hs.x + hd.x) * vv.x + (hs.y + hd.y) * vv.y
             + (hs.z + hd.z) * vv.z + (hs.w + hd.w) * vv.w;
    }
    #pragma unroll
    for (int m = 1; m < 16; m <<= 1)
        #pragma unroll
        for (int i = 0; i < 8; i++)
            p[i] += __shfl_xor_sync(0xffffffffu, p[i], m);
    if (tx == 0) {
        #pragma unroll
        for (int i = 0; i < 8; i++) {
            int e = i * 16 + ty;
            if (e < nE) out[e0 + e] = p[i] + c0;
        }
    }
}

// ---------------- host launch ----------------
extern "C" void kernel_launch(void* const* d_in, const int* in_sizes, int n_in,
                              void* d_out, int out_size)
{
    const int*   src   = (const int*)d_in[0];
    const int*   dst   = (const int*)d_in[1];
    const float* ef    = (const float*)d_in[2];
    const float* ts    = (const float*)d_in[3];
    const float* sf    = (const float*)d_in[4];
    const float* df    = (const float*)d_in[5];
    const float* mem   = (const float*)d_in[6];
    const float* tw    = (const float*)d_in[7];
    const float* tb    = (const float*)d_in[8];
    const float* mw1   = (const float*)d_in[9];
    const float* mb1   = (const float*)d_in[10];
    const float* mw2   = (const float*)d_in[11];
    const float* mb2   = (const float*)d_in[12];
    const float* gwih  = (const float*)d_in[13];
    const float* gwhh  = (const float*)d_in[14];
    const float* gbih  = (const float*)d_in[15];
    const float* gbhh  = (const float*)d_in[16];
    const float* ew1   = (const float*)d_in[17];
    const float* eb1   = (const float*)d_in[18];
    const float* ew2   = (const float*)d_in[19];
    const float* eb2   = (const float*)d_in[20];
    float* out = (float*)d_out;

    const int E = in_sizes[0];

    const int SMEM1 = (128 * 132 + 32 * 136) * 4 + 256 * 4;
    const int SMEM2 = (64 * 36 + 32 * 264 + 64) * 4;
    const int SMEM3 = (6912 + 2 * 128 * 68) * 4 + 128 * 4;

    cudaFuncSetAttribute(k_msg, cudaFuncAttributeMaxDynamicSharedMemorySize, SMEM1);
    cudaFuncSetAttribute(k_gru, cudaFuncAttributeMaxDynamicSharedMemorySize, SMEM2);
    cudaFuncSetAttribute(k_emb, cudaFuncAttributeMaxDynamicSharedMemorySize, SMEM3);

    k_zero<<<2048, 256>>>();
    k_pre<<<1, 256>>>(ew2, eb2);
    k_prew<<<256, 256>>>(gwih, gwhh);
    k_msg<<<(E + 127) / 128, 256, SMEM1>>>(src, dst, ef, ts, mem, tw, tb,
                                           mw1, mb1, mw2, mb2, E);
    k_gru<<<(N_NODES + 63) / 64, 256, SMEM2>>>(mem, gbih, gbhh);
    k_emb<<<(E + 127) / 128, 256, SMEM3>>>(src, dst, sf, df,
                                           ew1, eb1, out, E);
}

// round 9
// speedup vs baseline: 4.9869x; 1.2817x over previous
#include <cuda_runtime.h>
#include <stdint.h>
#include <math.h>

#define N_NODES 100000
#define MEM_DIM 128
#define MSG_DIM 128

// ---------------- scratch (static device globals; no allocation) ----------------
__device__ float g_aggr[(size_t)N_NODES * MSG_DIM];
__device__ float g_cnt[N_NODES];
__device__ float g_newmem[(size_t)N_NODES * MEM_DIM];
__device__ float g_M[64 * 64];     // W2 @ W2^T (symmetric)
__device__ float g_v[64];          // W2 @ b2
__device__ float g_c0;             // b2.b2
__device__ float g_Wg[256 * 512];  // padded gate-interleaved GRU weights

extern __shared__ float smem[];

// ---------------- helpers ----------------
__device__ __forceinline__ void mma_tf32(float4& c, const unsigned int a[4], const unsigned int b[2]) {
    asm volatile(
        "mma.sync.aligned.m16n8k8.row.col.f32.tf32.tf32.f32 "
        "{%0,%1,%2,%3},{%4,%5,%6,%7},{%8,%9},{%0,%1,%2,%3};\n"
        : "+f"(c.x), "+f"(c.y), "+f"(c.z), "+f"(c.w)
        : "r"(a[0]), "r"(a[1]), "r"(a[2]), "r"(a[3]), "r"(b[0]), "r"(b[1]));
}
__device__ __forceinline__ float sigm(float x) { return 1.f / (1.f + expf(-x)); }

// cp.async 16B with zero-fill predicate
__device__ __forceinline__ void cpa16(float* dst, const void* src, bool pred) {
    unsigned sa = (unsigned)__cvta_generic_to_shared(dst);
    asm volatile("cp.async.ca.shared.global [%0], [%1], 16, %2;\n"
                 :: "r"(sa), "l"(src), "r"(pred ? 16 : 0));
}
#define CP_COMMIT() asm volatile("cp.async.commit_group;\n" ::: "memory")
#define CP_WAIT(n)  asm volatile("cp.async.wait_group %0;\n" :: "n"(n) : "memory")

// ---------------- K0: zero aggregation buffers ----------------
__global__ void k_zero() {
    size_t stride = (size_t)gridDim.x * blockDim.x;
    size_t tid0 = (size_t)blockIdx.x * blockDim.x + threadIdx.x;
    size_t tot4 = (size_t)N_NODES * MSG_DIM / 4;
    float4 z = make_float4(0.f, 0.f, 0.f, 0.f);
    for (size_t i = tid0; i < tot4; i += stride) ((float4*)g_aggr)[i] = z;
    for (size_t i = tid0; i < N_NODES; i += stride) g_cnt[i] = 0.f;
}

// ---------------- K-pre: bilinear precompute for emb ----------------
__global__ void k_pre(const float* __restrict__ W2, const float* __restrict__ b2) {
    __shared__ float sW2[64 * 64];
    __shared__ float sb2[64];
    int tid = threadIdx.x;
    for (int i = tid; i < 64 * 64; i += 256) sW2[i] = W2[i];
    if (tid < 64) sb2[tid] = b2[tid];
    __syncthreads();
    for (int p = tid; p < 64 * 64; p += 256) {
        int j = p >> 6, k = p & 63;
        float s = 0.f;
        #pragma unroll 16
        for (int c = 0; c < 64; c++) s = fmaf(sW2[j * 64 + c], sW2[k * 64 + c], s);
        g_M[p] = s;
    }
    if (tid < 64) {
        float s = 0.f;
        #pragma unroll 16
        for (int c = 0; c < 64; c++) s = fmaf(sW2[tid * 64 + c], sb2[c], s);
        g_v[tid] = s;
    }
    if (tid == 0) {
        float s = 0.f;
        for (int c = 0; c < 64; c++) s = fmaf(sb2[c], sb2[c], s);
        g_c0 = s;
    }
}

// ---------------- K-prew: build gate-interleaved padded GRU weight matrix --------
__global__ void k_prew(const float* __restrict__ Wih, const float* __restrict__ Whh) {
    int stride = gridDim.x * blockDim.x;
    int idx = blockIdx.x * blockDim.x + threadIdx.x;
    for (int p = idx; p < 256 * 512; p += stride) {
        int k = p >> 9, c = p & 511;
        int jb = c >> 5, t = c & 31, q = t >> 3;
        int j = jb * 8 + (t & 7);
        float w;
        if (q == 0)      w = (k < 128) ? Wih[(size_t)j * 128 + k]
                                       : Whh[(size_t)j * 128 + (k - 128)];
        else if (q == 1) w = (k < 128) ? Wih[(size_t)(128 + j) * 128 + k]
                                       : Whh[(size_t)(128 + j) * 128 + (k - 128)];
        else if (q == 2) w = (k < 128) ? Wih[(size_t)(256 + j) * 128 + k] : 0.f;
        else             w = (k < 128) ? 0.f : Whh[(size_t)(256 + j) * 128 + (k - 128)];
        g_Wg[p] = w;
    }
}

// ======================= K1: message MLP, cp.async double-buffered ================
// smem: sU[16896] (H stride 132; A0@0, A1@4608 during GEMM1), sWa/sWb 32x136, sN.
__device__ __forceinline__ void msg_stage(
    int kc, float* abuf, float* wbuf,
    const int* sN, int nE, int e0,
    const float* memory, const float* ef, const float* ts,
    const float* tw, const float* tb, const float* W1, int tid)
{
    if (kc < 8) {
        const int* nodes = (kc < 4) ? sN : sN + 128;
        int q0 = (kc & 3) * 8;
        #pragma unroll
        for (int it = 0; it < 4; it++) {
            int idx = tid + 256 * it;
            int e = idx >> 3, q = idx & 7;
            cpa16(abuf + e * 36 + q * 4,
                  (const float4*)(memory + (size_t)nodes[e] * 128) + q0 + q, e < nE);
        }
    } else if (kc == 8) {
        #pragma unroll
        for (int it = 0; it < 4; it++) {
            int idx = tid + 256 * it;
            int e = idx >> 3, q = idx & 7;
            cpa16(abuf + e * 36 + q * 4,
                  (const float4*)(ef + (size_t)(e0 + e) * 32) + q, e < nE);
        }
    } else {
        for (int it = 0; it < 16; it++) {
            int idx = tid + 256 * it;
            int e = idx >> 5, c = idx & 31;
            float t = 0.f;
            if (e < nE) t = cosf(ts[e0 + e] * __ldg(tw + c) + __ldg(tb + c));
            abuf[e * 36 + c] = t;
        }
    }
    const float4* wsrc = (const float4*)(W1 + (size_t)kc * 32 * 128);
    #pragma unroll
    for (int it = 0; it < 4; it++) {
        int idx = tid + 256 * it;
        int r = idx >> 5, c = idx & 31;
        cpa16(wbuf + r * 136 + c * 4, wsrc + idx, true);
    }
}

__global__ __launch_bounds__(256, 2) void k_msg(
    const int* __restrict__ src, const int* __restrict__ dst,
    const float* __restrict__ ef, const float* __restrict__ ts,
    const float* __restrict__ memory,
    const float* __restrict__ tw, const float* __restrict__ tb,
    const float* __restrict__ W1, const float* __restrict__ b1,
    const float* __restrict__ W2, const float* __restrict__ b2,
    int E)
{
    float* sU  = smem;                 // 16896 (H stride 132)
    float* sA0 = smem;                 // 128*36
    float* sA1 = smem + 4608;          // 128*36
    float* sWa = smem + 16896;         // 32*136
    float* sWb = sWa + 4352;           // 32*136
    int*   sN  = (int*)(sWb + 4352);

    const int tid  = threadIdx.x;
    const int lane = tid & 31;
    const int wid  = tid >> 5;
    const int wm   = wid >> 2;
    const int wn   = wid & 3;
    const int grp  = lane >> 2;
    const int thr  = lane & 3;
    const int e0 = blockIdx.x * 128;
    const int nE = min(128, E - e0);

    if (tid < 128) sN[tid] = (tid < nE) ? src[e0 + tid] : 0;
    else           sN[tid] = (tid - 128 < nE) ? dst[e0 + tid - 128] : 0;
    __syncthreads();

    float4 acc[4][4];
    #pragma unroll
    for (int mt = 0; mt < 4; mt++)
        #pragma unroll
        for (int nt = 0; nt < 4; nt++) acc[mt][nt] = make_float4(0.f, 0.f, 0.f, 0.f);

    // prologue: prefetch chunks 0,1
    msg_stage(0, sA0, sWa, sN, nE, e0, memory, ef, ts, tw, tb, W1, tid);
    CP_COMMIT();
    msg_stage(1, sA1, sWb, sN, nE, e0, memory, ef, ts, tw, tb, W1, tid);
    CP_COMMIT();
    CP_WAIT(1);
    __syncthreads();   // chunk 0 ready, visible

    // -------- GEMM1: K=320, 10 chunks of 32, double-buffered --------
    #pragma unroll 1
    for (int kc = 0; kc < 10; kc++) {
        float* abuf = (kc & 1) ? sA1 : sA0;
        float* wbuf = (kc & 1) ? sWb : sWa;
        #pragma unroll
        for (int ks = 0; ks < 4; ks++) {
            unsigned int a[4][4], b[4][2];
            #pragma unroll
            for (int mt = 0; mt < 4; mt++) {
                int r0 = (wm * 64 + mt * 16 + grp) * 36 + ks * 8 + thr;
                int r1 = r0 + 8 * 36;
                a[mt][0] = __float_as_uint(abuf[r0]);
                a[mt][1] = __float_as_uint(abuf[r1]);
                a[mt][2] = __float_as_uint(abuf[r0 + 4]);
                a[mt][3] = __float_as_uint(abuf[r1 + 4]);
            }
            #pragma unroll
            for (int nt = 0; nt < 4; nt++) {
                int col = wn * 32 + nt * 8 + grp;
                b[nt][0] = __float_as_uint(wbuf[(ks * 8 + thr) * 136 + col]);
                b[nt][1] = __float_as_uint(wbuf[(ks * 8 + thr + 4) * 136 + col]);
            }
            #pragma unroll
            for (int mt = 0; mt < 4; mt++)
                #pragma unroll
                for (int nt = 0; nt < 4; nt++)
                    mma_tf32(acc[mt][nt], a[mt], b[nt]);
        }
        if (kc == 9) break;
        __syncthreads();                    // all warps done with pair (kc&1)
        if (kc + 2 <= 9) {
            msg_stage(kc + 2, abuf, wbuf, sN, nE, e0, memory, ef, ts, tw, tb, W1, tid);
            CP_COMMIT();
            CP_WAIT(1);                     // chunk kc+1 done
        } else {
            CP_WAIT(0);
        }
        __syncthreads();                    // visibility
    }
    __syncthreads();  // all MMAs done before H overwrites sU

    // prefetch W2 chunks 0,1
    {
        const float4* wsrc = (const float4*)W2;
        #pragma unroll
        for (int it = 0; it < 4; it++) {
            int idx = tid + 256 * it;
            int r = idx >> 5, c = idx & 31;
            cpa16(sWa + r * 136 + c * 4, wsrc + idx, true);
        }
        CP_COMMIT();
        wsrc = (const float4*)(W2 + 32 * 128);
        #pragma unroll
        for (int it = 0; it < 4; it++) {
            int idx = tid + 256 * it;
            int r = idx >> 5, c = idx & 31;
            cpa16(sWb + r * 136 + c * 4, wsrc + idx, true);
        }
        CP_COMMIT();
    }

    // bias + relu -> H in sU (stride 132, raw f32)
    {
        float bc0[4], bc1[4];
        #pragma unroll
        for (int nt = 0; nt < 4; nt++) {
            int col = wn * 32 + nt * 8 + 2 * thr;
            bc0[nt] = __ldg(b1 + col);
            bc1[nt] = __ldg(b1 + col + 1);
        }
        #pragma unroll
        for (int mt = 0; mt < 4; mt++) {
            int r0 = wm * 64 + mt * 16 + grp;
            #pragma unroll
            for (int nt = 0; nt < 4; nt++) {
                int col = wn * 32 + nt * 8 + 2 * thr;
                sU[r0 * 132 + col]           = fmaxf(acc[mt][nt].x + bc0[nt], 0.f);
                sU[r0 * 132 + col + 1]       = fmaxf(acc[mt][nt].y + bc1[nt], 0.f);
                sU[(r0 + 8) * 132 + col]     = fmaxf(acc[mt][nt].z + bc0[nt], 0.f);
                sU[(r0 + 8) * 132 + col + 1] = fmaxf(acc[mt][nt].w + bc1[nt], 0.f);
                acc[mt][nt] = make_float4(0.f, 0.f, 0.f, 0.f);
            }
        }
    }
    CP_WAIT(1);
    __syncthreads();   // H + W2 chunk0 ready

    // -------- GEMM2: K=128, 4 chunks, W double-buffered --------
    #pragma unroll 1
    for (int kc = 0; kc < 4; kc++) {
        float* wbuf = (kc & 1) ? sWb : sWa;
        #pragma unroll
        for (int ks = 0; ks < 4; ks++) {
            unsigned int a[4][4], b[4][2];
            int kbase = kc * 32 + ks * 8;
            #pragma unroll
            for (int mt = 0; mt < 4; mt++) {
                int r0 = (wm * 64 + mt * 16 + grp) * 132 + kbase + thr;
                int r1 = r0 + 8 * 132;
                a[mt][0] = __float_as_uint(sU[r0]);
                a[mt][1] = __float_as_uint(sU[r1]);
                a[mt][2] = __float_as_uint(sU[r0 + 4]);
                a[mt][3] = __float_as_uint(sU[r1 + 4]);
            }
            #pragma unroll
            for (int nt = 0; nt < 4; nt++) {
                int col = wn * 32 + nt * 8 + grp;
                b[nt][0] = __float_as_uint(wbuf[(ks * 8 + thr) * 136 + col]);
                b[nt][1] = __float_as_uint(wbuf[(ks * 8 + thr + 4) * 136 + col]);
            }
            #pragma unroll
            for (int mt = 0; mt < 4; mt++)
                #pragma unroll
                for (int nt = 0; nt < 4; nt++)
                    mma_tf32(acc[mt][nt], a[mt], b[nt]);
        }
        if (kc == 3) break;
        __syncthreads();
        if (kc + 2 <= 3) {
            const float4* wsrc = (const float4*)(W2 + (size_t)(kc + 2) * 32 * 128);
            #pragma unroll
            for (int it = 0; it < 4; it++) {
                int idx = tid + 256 * it;
                int r = idx >> 5, c = idx & 31;
                cpa16(wbuf + r * 136 + c * 4, wsrc + idx, true);
            }
            CP_COMMIT();
            CP_WAIT(1);
        } else {
            CP_WAIT(0);
        }
        __syncthreads();
    }
    __syncthreads();

    // -------- msg (+b2) -> sU, then float4 scatter --------
    {
        float bc0[4], bc1[4];
        #pragma unroll
        for (int nt = 0; nt < 4; nt++) {
            int col = wn * 32 + nt * 8 + 2 * thr;
            bc0[nt] = __ldg(b2 + col);
            bc1[nt] = __ldg(b2 + col + 1);
        }
        #pragma unroll
        for (int mt = 0; mt < 4; mt++) {
            int r0 = wm * 64 + mt * 16 + grp;
            #pragma unroll
            for (int nt = 0; nt < 4; nt++) {
                int col = wn * 32 + nt * 8 + 2 * thr;
                sU[r0 * 132 + col]           = acc[mt][nt].x + bc0[nt];
                sU[r0 * 132 + col + 1]       = acc[mt][nt].y + bc1[nt];
                sU[(r0 + 8) * 132 + col]     = acc[mt][nt].z + bc0[nt];
                sU[(r0 + 8) * 132 + col + 1] = acc[mt][nt].w + bc1[nt];
            }
        }
    }
    __syncthreads();

    {
        const int tx = tid & 15, ty = tid >> 4;
        #pragma unroll
        for (int i = 0; i < 8; i++) {
            int e = i * 16 + ty;
            if (e < nE) {
                float4 v0 = ((const float4*)(sU + e * 132))[tx];
                float4 v1 = ((const float4*)(sU + e * 132))[16 + tx];
                int ns = sN[e], nd = sN[128 + e];
                atomicAdd((float4*)(g_aggr + (size_t)ns * 128) + tx, v0);
                atomicAdd((float4*)(g_aggr + (size_t)ns * 128) + 16 + tx, v1);
                atomicAdd((float4*)(g_aggr + (size_t)nd * 128) + tx, v0);
                atomicAdd((float4*)(g_aggr + (size_t)nd * 128) + 16 + tx, v1);
            }
        }
    }
    if (tid < nE) {
        atomicAdd(&g_cnt[sN[tid]], 1.f);
        atomicAdd(&g_cnt[sN[128 + tid]], 1.f);
    }
}

// ======================= K2: GRU via tf32 MMA, gate-interleaved ===================
__global__ __launch_bounds__(256, 2) void k_gru(
    const float* __restrict__ memory,
    const float* __restrict__ bih, const float* __restrict__ bhh)
{
    float* sA   = smem;                 // 64*36
    float* sW   = smem + 64 * 36;       // 32*264
    float* sCnt = sW + 32 * 264;        // 64

    const int tid  = threadIdx.x;
    const int lane = tid & 31;
    const int wid  = tid >> 5;
    const int grp  = lane >> 2;
    const int thr  = lane & 3;
    const int n0 = blockIdx.x * 64;
    const int nN = min(64, N_NODES - n0);

    if (tid < 64) sCnt[tid] = (tid < nN) ? g_cnt[n0 + tid] : 0.f;
    __syncthreads();

    #pragma unroll 1
    for (int sweep = 0; sweep < 2; sweep++) {
        float4 acc[4][4];
        #pragma unroll
        for (int mt = 0; mt < 4; mt++)
            #pragma unroll
            for (int nt = 0; nt < 4; nt++) acc[mt][nt] = make_float4(0.f, 0.f, 0.f, 0.f);

        #pragma unroll 1
        for (int kc = 0; kc < 8; kc++) {
            // stage A (64 x 32): kc<4 mean-msg (compute), kc>=4 memory (cp.async)
            #pragma unroll
            for (int it = 0; it < 2; it++) {
                int idx = tid + 256 * it;
                int e = idx >> 3, q = idx & 7;
                if (kc < 4) {
                    float4 v = make_float4(0.f, 0.f, 0.f, 0.f);
                    if (e < nN) {
                        v = *((const float4*)(g_aggr + (size_t)(n0 + e) * 128) + kc * 8 + q);
                        float cnt = sCnt[e];
                        float inv = (cnt > 0.f) ? (1.f / cnt) : 0.f;
                        v.x *= inv; v.y *= inv; v.z *= inv; v.w *= inv;
                    }
                    ((float4*)sA)[e * 9 + q] = v;
                } else {
                    cpa16(sA + e * 36 + q * 4,
                          (const float4*)(memory + (size_t)(n0 + e) * 128) + (kc - 4) * 8 + q,
                          e < nN);
                }
            }
            // stage W (32 x 256, stride 264) via cp.async
            {
                const float* wsrc = g_Wg + (size_t)kc * 32 * 512 + sweep * 256;
                #pragma unroll
                for (int it = 0; it < 8; it++) {
                    int idx = tid + 256 * it;
                    int r = idx >> 6, c = idx & 63;
                    cpa16(sW + r * 264 + c * 4, (const float4*)(wsrc + (size_t)r * 512) + c, true);
                }
            }
            CP_COMMIT();
            CP_WAIT(0);
            __syncthreads();
            #pragma unroll
            for (int ks = 0; ks < 4; ks++) {
                unsigned int a[4][4], b[4][2];
                #pragma unroll
                for (int mt = 0; mt < 4; mt++) {
                    int r0 = (mt * 16 + grp) * 36 + ks * 8 + thr;
                    int r1 = r0 + 8 * 36;
                    a[mt][0] = __float_as_uint(sA[r0]);
                    a[mt][1] = __float_as_uint(sA[r1]);
                    a[mt][2] = __float_as_uint(sA[r0 + 4]);
                    a[mt][3] = __float_as_uint(sA[r1 + 4]);
                }
                #pragma unroll
                for (int nt = 0; nt < 4; nt++) {
                    int col = wid * 32 + nt * 8 + grp;
                    b[nt][0] = __float_as_uint(sW[(ks * 8 + thr) * 264 + col]);
                    b[nt][1] = __float_as_uint(sW[(ks * 8 + thr + 4) * 264 + col]);
                }
                #pragma unroll
                for (int mt = 0; mt < 4; mt++)
                    #pragma unroll
                    for (int nt = 0; nt < 4; nt++)
                        mma_tf32(acc[mt][nt], a[mt], b[nt]);
            }
            __syncthreads();
        }

        int j0 = sweep * 64 + wid * 8 + 2 * thr;
        float br0 = __ldg(bih + j0) + __ldg(bhh + j0);
        float br1 = __ldg(bih + j0 + 1) + __ldg(bhh + j0 + 1);
        float bz0 = __ldg(bih + 128 + j0) + __ldg(bhh + 128 + j0);
        float bz1 = __ldg(bih + 128 + j0 + 1) + __ldg(bhh + 128 + j0 + 1);
        float bi0 = __ldg(bih + 256 + j0),      bi1 = __ldg(bih + 256 + j0 + 1);
        float bh0 = __ldg(bhh + 256 + j0),      bh1 = __ldg(bhh + 256 + j0 + 1);

        #pragma unroll
        for (int mt = 0; mt < 4; mt++) {
            #pragma unroll
            for (int half = 0; half < 2; half++) {
                int row = mt * 16 + grp + half * 8;
                if (row < nN) {
                    float rp0 = half ? acc[mt][0].z : acc[mt][0].x;
                    float rp1 = half ? acc[mt][0].w : acc[mt][0].y;
                    float zp0 = half ? acc[mt][1].z : acc[mt][1].x;
                    float zp1 = half ? acc[mt][1].w : acc[mt][1].y;
                    float ip0 = half ? acc[mt][2].z : acc[mt][2].x;
                    float ip1 = half ? acc[mt][2].w : acc[mt][2].y;
                    float hp0 = half ? acc[mt][3].z : acc[mt][3].x;
                    float hp1 = half ? acc[mt][3].w : acc[mt][3].y;

                    float2 hv = *(const float2*)(memory + (size_t)(n0 + row) * 128 + j0);
                    float cnt = sCnt[row];

                    float r0g = sigm(rp0 + br0), r1g = sigm(rp1 + br1);
                    float z0g = sigm(zp0 + bz0), z1g = sigm(zp1 + bz1);
                    float n0g = tanhf(ip0 + bi0 + r0g * (hp0 + bh0));
                    float n1g = tanhf(ip1 + bi1 + r1g * (hp1 + bh1));
                    float2 res;
                    res.x = (cnt > 0.f) ? ((1.f - z0g) * n0g + z0g * hv.x) : hv.x;
                    res.y = (cnt > 0.f) ? ((1.f - z1g) * n1g + z1g * hv.y) : hv.y;
                    *(float2*)(g_newmem + (size_t)(n0 + row) * 128 + j0) = res;
                }
            }
        }
    }
}

// ======================= K3: embeddings via tf32 MMA + bilinear dot ===============
__global__ __launch_bounds__(256, 2) void k_emb(
    const int* __restrict__ src, const int* __restrict__ dst,
    const float* __restrict__ sf, const float* __restrict__ df,
    const float* __restrict__ W1, const float* __restrict__ b1,
    float* __restrict__ out, int E)
{
    float* sA  = smem;                  // 128*36
    float* sW  = smem + 128 * 36;       // 32*72
    float* sM  = smem;                  // tail alias
    float* sv  = smem + 64 * 64;        // tail alias
    float* sHs = smem + 6912;           // 128*68
    float* sHd = smem + 6912 + 128 * 68;// 128*68
    int*   sN  = (int*)(smem + 6912 + 2 * 128 * 68);

    const int tid  = threadIdx.x;
    const int lane = tid & 31;
    const int wid  = tid >> 5;
    const int wm   = wid >> 1;
    const int wn   = wid & 1;
    const int grp  = lane >> 2;
    const int thr  = lane & 3;
    const int e0 = blockIdx.x * 128;
    const int nE = min(128, E - e0);

    #pragma unroll 1
    for (int side = 0; side < 2; side++) {
        const int* nodes = side ? dst : src;
        const float* feats = side ? df : sf;
        float* sH = side ? sHd : sHs;

        __syncthreads();
        if (tid < 128) sN[tid] = (tid < nE) ? nodes[e0 + tid] : 0;
        __syncthreads();

        float4 acc[2][4];
        #pragma unroll
        for (int mt = 0; mt < 2; mt++)
            #pragma unroll
            for (int nt = 0; nt < 4; nt++) acc[mt][nt] = make_float4(0.f, 0.f, 0.f, 0.f);

        #pragma unroll 1
        for (int kc = 0; kc < 6; kc++) {
            if (kc < 4) {
                int q0 = kc * 8;
                #pragma unroll
                for (int it = 0; it < 4; it++) {
                    int idx = tid + 256 * it;
                    int e = idx >> 3, q = idx & 7;
                    cpa16(sA + e * 36 + q * 4,
                          (const float4*)(g_newmem + (size_t)sN[e] * 128) + q0 + q, e < nE);
                }
            } else {
                int fc = kc - 4;
                #pragma unroll
                for (int it = 0; it < 4; it++) {
                    int idx = tid + 256 * it;
                    int e = idx >> 3, q = idx & 7;
                    cpa16(sA + e * 36 + q * 4,
                          (const float4*)(feats + (size_t)(e0 + e) * 64) + fc * 8 + q, e < nE);
                }
            }
            {
                const float4* wsrc = (const float4*)(W1 + (size_t)kc * 32 * 64);
                #pragma unroll
                for (int it = 0; it < 2; it++) {
                    int idx = tid + 256 * it;
                    int r = idx >> 4, c = idx & 15;
                    cpa16(sW + r * 72 + c * 4, wsrc + idx, true);
                }
            }
            CP_COMMIT();
            CP_WAIT(0);
            __syncthreads();
            #pragma unroll
            for (int ks = 0; ks < 4; ks++) {
                unsigned int a[2][4], b[4][2];
                #pragma unroll
                for (int mt = 0; mt < 2; mt++) {
                    int r0 = (wm * 32 + mt * 16 + grp) * 36 + ks * 8 + thr;
                    int r1 = r0 + 8 * 36;
                    a[mt][0] = __float_as_uint(sA[r0]);
                    a[mt][1] = __float_as_uint(sA[r1]);
                    a[mt][2] = __float_as_uint(sA[r0 + 4]);
                    a[mt][3] = __float_as_uint(sA[r1 + 4]);
                }
                #pragma unroll
                for (int nt = 0; nt < 4; nt++) {
                    int col = wn * 32 + nt * 8 + grp;
                    b[nt][0] = __float_as_uint(sW[(ks * 8 + thr) * 72 + col]);
                    b[nt][1] = __float_as_uint(sW[(ks * 8 + thr + 4) * 72 + col]);
                }
                #pragma unroll
                for (int mt = 0; mt < 2; mt++)
                    #pragma unroll
                    for (int nt = 0; nt < 4; nt++)
                        mma_tf32(acc[mt][nt], a[mt], b[nt]);
            }
            __syncthreads();
        }

        {
            float bc0[4], bc1[4];
            #pragma unroll
            for (int nt = 0; nt < 4; nt++) {
                int col = wn * 32 + nt * 8 + 2 * thr;
                bc0[nt] = __ldg(b1 + col);
                bc1[nt] = __ldg(b1 + col + 1);
            }
            #pragma unroll
            for (int mt = 0; mt < 2; mt++) {
                int r0 = wm * 32 + mt * 16 + grp;
                #pragma unroll
                for (int nt = 0; nt < 4; nt++) {
                    int col = wn * 32 + nt * 8 + 2 * thr;
                    sH[r0 * 68 + col]           = fmaxf(acc[mt][nt].x + bc0[nt], 0.f);
                    sH[r0 * 68 + col + 1]       = fmaxf(acc[mt][nt].y + bc1[nt], 0.f);
                    sH[(r0 + 8) * 68 + col]     = fmaxf(acc[mt][nt].z + bc0[nt], 0.f);
                    sH[(r0 + 8) * 68 + col + 1] = fmaxf(acc[mt][nt].w + bc1[nt], 0.f);
                }
            }
        }
    }
    __syncthreads();

    #pragma unroll
    for (int it = 0; it < 4; it++)
        ((float4*)sM)[tid + 256 * it] = ((const float4*)g_M)[tid + 256 * it];
    if (tid < 16) ((float4*)sv)[tid] = ((const float4*)g_v)[tid];
    __syncthreads();

    const int tx = tid & 15, ty = tid >> 4;
    float4 t[8];
    #pragma unroll
    for (int i = 0; i < 8; i++) t[i] = make_float4(0.f, 0.f, 0.f, 0.f);
    #pragma unroll 8
    for (int kk = 0; kk < 64; kk++) {
        float4 m = ((const float4*)sM)[kk * 16 + tx];
        #pragma unroll
        for (int i = 0; i < 8; i++) {
            float a = sHd[(i * 16 + ty) * 68 + kk];
            t[i].x = fmaf(a, m.x, t[i].x);
            t[i].y = fmaf(a, m.y, t[i].y);
            t[i].z = fmaf(a, m.z, t[i].z);
            t[i].w = fmaf(a, m.w, t[i].w);
        }
    }

    float c0 = g_c0;
    float4 vv = ((const float4*)sv)[tx];
    float p[8];
    #pragma unroll
    for (int i = 0; i < 8; i++) {
        int row = i * 16 + ty;
        float4 hs = ((const float4*)(sHs + row * 68))[tx];
        float4 hd = ((const float4*)(sHd + row * 68))[tx];
        p[i] = hs.x * t[i].x + hs.y * t[i].y + hs.z * t[i].z + hs.w * t[i].w
             + (hs.x + hd.x) * vv.x + (hs.y + hd.y) * vv.y
             + (hs.z + hd.z) * vv.z + (hs.w + hd.w) * vv.w;
    }
    #pragma unroll
    for (int m = 1; m < 16; m <<= 1)
        #pragma unroll
        for (int i = 0; i < 8; i++)
            p[i] += __shfl_xor_sync(0xffffffffu, p[i], m);
    if (tx == 0) {
        #pragma unroll
        for (int i = 0; i < 8; i++) {
            int e = i * 16 + ty;
            if (e < nE) out[e0 + e] = p[i] + c0;
        }
    }
}

// ---------------- host launch ----------------
extern "C" void kernel_launch(void* const* d_in, const int* in_sizes, int n_in,
                              void* d_out, int out_size)
{
    const int*   src   = (const int*)d_in[0];
    const int*   dst   = (const int*)d_in[1];
    const float* ef    = (const float*)d_in[2];
    const float* ts    = (const float*)d_in[3];
    const float* sf    = (const float*)d_in[4];
    const float* df    = (const float*)d_in[5];
    const float* mem   = (const float*)d_in[6];
    const float* tw    = (const float*)d_in[7];
    const float* tb    = (const float*)d_in[8];
    const float* mw1   = (const float*)d_in[9];
    const float* mb1   = (const float*)d_in[10];
    const float* mw2   = (const float*)d_in[11];
    const float* mb2   = (const float*)d_in[12];
    const float* gwih  = (const float*)d_in[13];
    const float* gwhh  = (const float*)d_in[14];
    const float* gbih  = (const float*)d_in[15];
    const float* gbhh  = (const float*)d_in[16];
    const float* ew1   = (const float*)d_in[17];
    const float* eb1   = (const float*)d_in[18];
    const float* ew2   = (const float*)d_in[19];
    const float* eb2   = (const float*)d_in[20];
    float* out = (float*)d_out;

    const int E = in_sizes[0];

    const int SMEM1 = (16896 + 2 * 4352) * 4 + 256 * 4;          // ~103.4KB
    const int SMEM2 = (64 * 36 + 32 * 264 + 64) * 4;
    const int SMEM3 = (6912 + 2 * 128 * 68) * 4 + 128 * 4;

    cudaFuncSetAttribute(k_msg, cudaFuncAttributeMaxDynamicSharedMemorySize, SMEM1);
    cudaFuncSetAttribute(k_gru, cudaFuncAttributeMaxDynamicSharedMemorySize, SMEM2);
    cudaFuncSetAttribute(k_emb, cudaFuncAttributeMaxDynamicSharedMemorySize, SMEM3);

    k_zero<<<2048, 256>>>();
    k_pre<<<1, 256>>>(ew2, eb2);
    k_prew<<<256, 256>>>(gwih, gwhh);
    k_msg<<<(E + 127) / 128, 256, SMEM1>>>(src, dst, ef, ts, mem, tw, tb,
                                           mw1, mb1, mw2, mb2, E);
    k_gru<<<(N_NODES + 63) / 64, 256, SMEM2>>>(mem, gbih, gbhh);
    k_emb<<<(E + 127) / 128, 256, SMEM3>>>(src, dst, sf, df,
                                           ew1, eb1, out, E);
}